// round 4
// baseline (speedup 1.0000x reference)
#include <cuda_runtime.h>
#include <cuda_bf16.h>
#include <math.h>

// ---------------- problem constants ----------------
#define HH 200
#define WW 200
#define NPIX (HH*WW)            // 40000
#define CIN 512
#define AA 9
#define NBOX (NPIX*AA)          // 360000
#define PRE_NMS 6000
#define POST_NMS 300
#define MIN_SIZE (16.0f/1000.0f)
#define IOU_THR 0.7f

#define CLS_OFF 0
#define LOC_OFF (NBOX*2)        // 720000
#define ROI_OFF (NBOX*2 + NBOX*4)  // 2160000

#define MASK_W 192              // 32-bit words per mask row (>= 6000/32)
#define SORTN 8192
#define TIE_WORDS ((NBOX + 31) / 32)   // 11250
#define NBLK 1407               // ceil(NBOX/256)

// ---------------- scratch (device globals; no allocation allowed) ------------
// NOTE: __device__ symbols are ONLY referenced from device code. Passing them
// as host-side kernel arguments silently yields the host shadow address
// (ATS-accessible on GB300 => no fault, just wrong/persistent memory).
__device__ float g_x[(size_t)CIN * NPIX];          // conv1 output (relu), [ci][p]
__device__ float g_cls[(size_t)NBOX * 2];          // private copy of cls logits
__device__ float g_loc[(size_t)NBOX * 4];          // private copy of loc deltas
__device__ float g_roi[(size_t)NBOX * 4];
__device__ unsigned g_key[NBOX];                   // ascending-sort key (= score desc)
__device__ unsigned g_hist[4 * 256];
__device__ unsigned g_state[2];                    // {threshold T, r = ties needed}
__device__ int g_cnt;                              // count of keys strictly < T
__device__ unsigned g_bcnt[NBLK + 1];
__device__ unsigned g_boff[NBLK + 1];
__device__ unsigned long long g_cand[SORTN];
__device__ unsigned g_tiebm[TIE_WORDS];
__device__ float g_nb[6144 * 4];                   // top-6000 boxes (padded)
__device__ unsigned g_keep_init[MASK_W];
__device__ unsigned g_keep_fin[MASK_W];
__device__ unsigned g_mask[(size_t)PRE_NMS * MASK_W];

// ---------------- init ----------------
__global__ void init_k() {
    int t = blockIdx.x * 256 + threadIdx.x;
    const int STRIDE = 48 * 256;
    for (int i = t; i < 4 * 256; i += STRIDE) g_hist[i] = 0;
    for (int i = t; i < TIE_WORDS; i += STRIDE) g_tiebm[i] = 0;
    for (int i = t; i < SORTN; i += STRIDE) g_cand[i] = 0xFFFFFFFFFFFFFFFFull;
    for (int i = t; i < NBLK + 1; i += STRIDE) { g_bcnt[i] = 0; g_boff[i] = 0; }
    for (int i = t; i < MASK_W; i += STRIDE) { g_keep_init[i] = 0; g_keep_fin[i] = 0; }
    if (t == 0) { g_cnt = 0; g_state[0] = 0u; g_state[1] = PRE_NMS; }
}

// ---------------- conv 3x3 (512->512) + bias + relu ----------------
// block tile: 64 out-channels x (16x4) pixels, 256 threads, thread = 4co x 4px
#define TX 16
#define TY 4
#define COT 64
#define CK 8
__global__ __launch_bounds__(256) void conv3x3_k(
    const float* __restrict__ f, const float* __restrict__ w1,
    const float* __restrict__ b1)
{
    __shared__ float s_in[CK][TY + 2][TX + 2];
    __shared__ float s_w[COT][CK][9];

    const int bx = blockIdx.x * TX;
    const int by = blockIdx.y * TY;
    const int co0 = blockIdx.z * COT;
    const int t = threadIdx.x;
    const int pg = t & 15;           // 16 pixel-groups (4 px each, same row)
    const int cg = t >> 4;           // 16 co-groups (4 co each)
    const int lx = (pg & 3) * 4;
    const int ly = pg >> 2;

    float acc[4][4];
#pragma unroll
    for (int k = 0; k < 4; k++)
#pragma unroll
        for (int j = 0; j < 4; j++) acc[k][j] = 0.f;

    for (int cb = 0; cb < CIN; cb += CK) {
        __syncthreads();
        // stage input tile: CK x 6 x 18 = 864
        for (int i = t; i < CK * 6 * 18; i += 256) {
            int ci = i / 108;
            int rem = i - ci * 108;
            int r = rem / 18;
            int c = rem - r * 18;
            int gy = by + r - 1, gx = bx + c - 1;
            float v = 0.f;
            if (gy >= 0 && gy < HH && gx >= 0 && gx < WW)
                v = f[((size_t)(cb + ci) * HH + gy) * WW + gx];
            s_in[ci][r][c] = v;
        }
        // stage weights: 64 x 8 x 9 = 4608
        for (int i = t; i < COT * CK * 9; i += 256) {
            int co = i / (CK * 9);
            int rem = i - co * (CK * 9);
            int ci = rem / 9;
            int tap = rem - ci * 9;
            s_w[co][ci][tap] = w1[((size_t)(co0 + co) * CIN + (cb + ci)) * 9 + tap];
        }
        __syncthreads();

#pragma unroll 2
        for (int ci = 0; ci < CK; ci++) {
            float in[3][6];
#pragma unroll
            for (int r = 0; r < 3; r++)
#pragma unroll
                for (int c = 0; c < 6; c++)
                    in[r][c] = s_in[ci][ly + r][lx + c];
#pragma unroll
            for (int k = 0; k < 4; k++) {
#pragma unroll
                for (int r = 0; r < 3; r++)
#pragma unroll
                    for (int c2 = 0; c2 < 3; c2++) {
                        float wv = s_w[cg * 4 + k][ci][r * 3 + c2];
#pragma unroll
                        for (int j = 0; j < 4; j++)
                            acc[k][j] = fmaf(wv, in[r][c2 + j], acc[k][j]);
                    }
            }
        }
    }

    const int y = by + ly;
#pragma unroll
    for (int k = 0; k < 4; k++) {
        int co = co0 + cg * 4 + k;
        float bias = b1[co];
#pragma unroll
        for (int j = 0; j < 4; j++) {
            int x = bx + lx + j;
            if (x < WW && y < HH) {
                float v = acc[k][j] + bias;
                g_x[((size_t)co * HH + y) * WW + x] = v > 0.f ? v : 0.f;
            }
        }
    }
}

// ---------------- 1x1 heads (cls 18 + loc 36), NHWC into d_out + private ----
#define PXT 128
#define OC 64
#define CKB 16
__global__ __launch_bounds__(256) void conv1x1_k(
    const float* __restrict__ wc, const float* __restrict__ bc,
    const float* __restrict__ wl, const float* __restrict__ bl,
    float* __restrict__ out)
{
    __shared__ float s_x[CKB][PXT];
    __shared__ float s_w[OC][CKB];
    const int p0 = blockIdx.x * PXT;
    const int t = threadIdx.x;
    const int cg = t >> 4;   // 16 groups x 4 co
    const int pg = t & 15;   // 16 groups x 8 px

    float acc[4][8];
#pragma unroll
    for (int k = 0; k < 4; k++)
#pragma unroll
        for (int j = 0; j < 8; j++) acc[k][j] = 0.f;

    for (int cb = 0; cb < CIN; cb += CKB) {
        __syncthreads();
        for (int i = t; i < CKB * PXT; i += 256) {
            int ci = i >> 7, pp = i & 127;
            int p = p0 + pp;
            s_x[ci][pp] = (p < NPIX) ? g_x[(size_t)(cb + ci) * NPIX + p] : 0.f;
        }
        for (int i = t; i < OC * CKB; i += 256) {
            int co = i >> 4, ci = i & 15;
            float v = 0.f;
            if (co < 18) v = wc[(size_t)co * CIN + cb + ci];
            else if (co < 54) v = wl[(size_t)(co - 18) * CIN + cb + ci];
            s_w[co][ci] = v;
        }
        __syncthreads();
#pragma unroll 4
        for (int ci = 0; ci < CKB; ci++) {
            float xv[8];
#pragma unroll
            for (int j = 0; j < 8; j++) xv[j] = s_x[ci][pg * 8 + j];
#pragma unroll
            for (int k = 0; k < 4; k++) {
                float wv = s_w[cg * 4 + k][ci];
#pragma unroll
                for (int j = 0; j < 8; j++)
                    acc[k][j] = fmaf(wv, xv[j], acc[k][j]);
            }
        }
    }

#pragma unroll
    for (int k = 0; k < 4; k++) {
        int co = cg * 4 + k;
#pragma unroll
        for (int j = 0; j < 8; j++) {
            int p = p0 + pg * 8 + j;
            if (p < NPIX) {
                if (co < 18) {
                    float v = acc[k][j] + bc[co];
                    out[CLS_OFF + (size_t)p * 18 + co] = v;
                    g_cls[(size_t)p * 18 + co] = v;
                } else if (co < 54) {
                    float v = acc[k][j] + bl[co - 18];
                    out[LOC_OFF + (size_t)p * 36 + (co - 18)] = v;
                    g_loc[(size_t)p * 36 + (co - 18)] = v;
                }
            }
        }
    }
}

// ---------------- decode boxes + scores + sort keys ----------------
__global__ void decode_k(const float* __restrict__ anchor)
{
    int n = blockIdx.x * 256 + threadIdx.x;
    if (n >= NBOX) return;
    float a0 = anchor[(size_t)n * 4 + 0], a1 = anchor[(size_t)n * 4 + 1];
    float a2 = anchor[(size_t)n * 4 + 2], a3 = anchor[(size_t)n * 4 + 3];
    float aw = a2 - a0, ah = a3 - a1;
    float acx = (a0 + a2) * 0.5f, acy = (a1 + a3) * 0.5f;
    float l0 = g_loc[(size_t)n * 4 + 0];
    float l1 = g_loc[(size_t)n * 4 + 1];
    float l2 = g_loc[(size_t)n * 4 + 2];
    float l3 = g_loc[(size_t)n * 4 + 3];
    float cx = l0 * aw + acx, cy = l1 * ah + acy;
    float bw = expf(l2) * aw, bh = expf(l3) * ah;
    float x1 = fminf(fmaxf(cx - bw * 0.5f, 0.f), 1.f);
    float y1 = fminf(fmaxf(cy - bh * 0.5f, 0.f), 1.f);
    float x2 = fminf(fmaxf(cx + bw * 0.5f, 0.f), 1.f);
    float y2 = fminf(fmaxf(cy + bh * 0.5f, 0.f), 1.f);
    g_roi[(size_t)n * 4 + 0] = x1;
    g_roi[(size_t)n * 4 + 1] = y1;
    g_roi[(size_t)n * 4 + 2] = x2;
    g_roi[(size_t)n * 4 + 3] = y2;

    float c0 = g_cls[(size_t)n * 2 + 0];
    float c1 = g_cls[(size_t)n * 2 + 1];
    float s = 1.f / (1.f + expf(c0 - c1));     // softmax[:,1]
    bool valid = ((y2 - y1) >= MIN_SIZE) && ((x2 - x1) >= MIN_SIZE);
    float sc = valid ? s : -1.0f;

    unsigned b = __float_as_uint(sc);
    unsigned ord = (b & 0x80000000u) ? ~b : (b | 0x80000000u); // ascending float order
    g_key[n] = ~ord;    // ascending key == descending score
}

// ---------------- 4-pass MSD radix select: exact 32-bit threshold ----------
// pass id selects g_hist slice INSIDE device code (never pass __device__
// symbols as host-side kernel arguments!)
__global__ void hist_k(int pass, unsigned shift, unsigned pmask)
{
    __shared__ unsigned h[256];
    int t = threadIdx.x;
    for (int i = t; i < 256; i += 256) h[i] = 0;
    __syncthreads();
    unsigned prefix = g_state[0];
    for (int n = blockIdx.x * 256 + t; n < NBOX; n += gridDim.x * 256) {
        unsigned K = g_key[n];
        if ((K & pmask) == prefix) atomicAdd(&h[(K >> shift) & 255u], 1u);
    }
    __syncthreads();
    unsigned* hist = &g_hist[pass * 256];
    for (int i = t; i < 256; i += 256)
        if (h[i]) atomicAdd(&hist[i], h[i]);
}

__global__ void scan_k(int pass, unsigned shift)
{
    if (threadIdx.x == 0) {
        const unsigned* hist = &g_hist[pass * 256];
        unsigned k = g_state[1];
        unsigned cum = 0;
        int d = 0;
        for (; d < 256; d++) {
            if (cum + hist[d] >= k) break;
            cum += hist[d];
        }
        if (d > 255) d = 255;
        g_state[0] |= ((unsigned)d) << shift;
        g_state[1] = k - cum;
    }
}

// ---------------- deterministic compaction (no atomic ordering) ------------
// phase 1: per-block counts of keys strictly < T
__global__ __launch_bounds__(256) void count_k()
{
    __shared__ unsigned wsum[8];
    int n = blockIdx.x * 256 + threadIdx.x;
    unsigned T = g_state[0];
    bool pred = (n < NBOX) && (g_key[n] < T);
    unsigned bal = __ballot_sync(0xFFFFFFFFu, pred);
    if ((threadIdx.x & 31) == 0) wsum[threadIdx.x >> 5] = (unsigned)__popc(bal);
    __syncthreads();
    if (threadIdx.x == 0) {
        unsigned s = 0;
#pragma unroll
        for (int w = 0; w < 8; w++) s += wsum[w];
        g_bcnt[blockIdx.x] = s;
    }
}

// phase 2: exclusive scan over block counts (single thread; 1407 iterations)
__global__ void scanb_k()
{
    if (threadIdx.x == 0) {
        unsigned acc = 0;
        for (int i = 0; i < NBLK; i++) { g_boff[i] = acc; acc += g_bcnt[i]; }
        g_cnt = (int)acc;   // = PRE_NMS - r
    }
}

// phase 3: rank-based placement (deterministic order) + tie bitmap
__global__ __launch_bounds__(256) void place_k()
{
    __shared__ unsigned wcnt[8];
    __shared__ unsigned wex[8];
    int t = threadIdx.x;
    int n = blockIdx.x * 256 + t;
    unsigned T = g_state[0];
    unsigned K = (n < NBOX) ? g_key[n] : 0xFFFFFFFFu;
    bool pred = (n < NBOX) && (K < T);
    unsigned bal = __ballot_sync(0xFFFFFFFFu, pred);
    int lane = t & 31, w = t >> 5;
    if (lane == 0) wcnt[w] = (unsigned)__popc(bal);
    __syncthreads();
    if (t == 0) {
        unsigned a = 0;
#pragma unroll
        for (int i = 0; i < 8; i++) { wex[i] = a; a += wcnt[i]; }
    }
    __syncthreads();
    if (pred) {
        unsigned rank = g_boff[blockIdx.x] + wex[w] +
                        (unsigned)__popc(bal & ((1u << lane) - 1u));
        g_cand[rank] = ((unsigned long long)K << 32) | (unsigned)n;
    }
    if ((n < NBOX) && (K == T))
        atomicOr(&g_tiebm[n >> 5], 1u << (n & 31));
}

// pick the r smallest indices among ties (matches top_k stable tie-break)
__global__ void tie_select_k()
{
    const int lane = threadIdx.x;     // 32 threads
    const int base = g_cnt;
    const unsigned r = g_state[1];
    const unsigned T = g_state[0];
    unsigned taken = 0;
    for (int w0 = 0; w0 < TIE_WORDS && taken < r; w0 += 32) {
        int wi = w0 + lane;
        unsigned word = (wi < TIE_WORDS) ? g_tiebm[wi] : 0u;
        int cnt = __popc(word);
        int pre = cnt;
#pragma unroll
        for (int o = 1; o < 32; o <<= 1) {
            int v = __shfl_up_sync(0xFFFFFFFFu, pre, o);
            if (lane >= o) pre += v;
        }
        unsigned rank = taken + (unsigned)(pre - cnt);
        while (word && rank < r) {
            int b = __ffs(word) - 1;
            word &= word - 1;
            unsigned n = (unsigned)wi * 32u + (unsigned)b;
            g_cand[base + rank] = ((unsigned long long)T << 32) | n;
            rank++;
        }
        taken += (unsigned)__shfl_sync(0xFFFFFFFFu, pre, 31);
    }
}

// ---------------- single-block bitonic sort of candidates + gather ----------
extern __shared__ unsigned long long s_sort[];
__global__ void sort_topk_k()
{
    const int t = threadIdx.x;   // 1024 threads
    for (int i = t; i < SORTN; i += 1024)
        s_sort[i] = (i < PRE_NMS) ? g_cand[i] : 0xFFFFFFFFFFFFFFFFull;
    __syncthreads();
    for (int k = 2; k <= SORTN; k <<= 1) {
        for (int j = k >> 1; j > 0; j >>= 1) {
            for (int i = t; i < SORTN; i += 1024) {
                int ixj = i ^ j;
                if (ixj > i) {
                    unsigned long long a = s_sort[i], b = s_sort[ixj];
                    bool up = ((i & k) == 0);
                    if ((a > b) == up) { s_sort[i] = b; s_sort[ixj] = a; }
                }
            }
            __syncthreads();
        }
    }
    // gather boxes + initial keep bitset (valid = score >= 0)
    for (int i = t; i < 6144; i += 1024) {
        bool valid = false;
        if (i < PRE_NMS) {
            unsigned long long v = s_sort[i];
            unsigned K = (unsigned)(v >> 32);
            unsigned n = (unsigned)v;
            float b0 = 0, b1 = 0, b2 = 0, b3 = 0;
            if (n < (unsigned)NBOX) {
                b0 = g_roi[(size_t)n * 4 + 0];
                b1 = g_roi[(size_t)n * 4 + 1];
                b2 = g_roi[(size_t)n * 4 + 2];
                b3 = g_roi[(size_t)n * 4 + 3];
                valid = (K < 0x80000000u);   // score >= 0
            }
            g_nb[(size_t)i * 4 + 0] = b0;
            g_nb[(size_t)i * 4 + 1] = b1;
            g_nb[(size_t)i * 4 + 2] = b2;
            g_nb[(size_t)i * 4 + 3] = b3;
        }
        unsigned bal = __ballot_sync(0xFFFFFFFFu, valid);
        if ((t & 31) == 0) g_keep_init[i >> 5] = bal;
    }
}

// ---------------- NMS suppression bitmask (j > i only) ----------------
__global__ __launch_bounds__(MASK_W) void mask_k()
{
    const int i = blockIdx.x;
    const int w = threadIdx.x;
    float x1 = g_nb[(size_t)i * 4 + 0], y1 = g_nb[(size_t)i * 4 + 1];
    float x2 = g_nb[(size_t)i * 4 + 2], y2 = g_nb[(size_t)i * 4 + 3];
    float ai = (x2 - x1) * (y2 - y1);
    unsigned bits = 0;
    int jbase = w * 32;
#pragma unroll 4
    for (int b = 0; b < 32; b++) {
        int j = jbase + b;
        if (j > i && j < PRE_NMS) {
            float u1 = g_nb[(size_t)j * 4 + 0], v1 = g_nb[(size_t)j * 4 + 1];
            float u2 = g_nb[(size_t)j * 4 + 2], v2 = g_nb[(size_t)j * 4 + 3];
            float xx1 = fmaxf(x1, u1), yy1 = fmaxf(y1, v1);
            float xx2 = fminf(x2, u2), yy2 = fminf(y2, v2);
            float inter = fmaxf(xx2 - xx1, 0.f) * fmaxf(yy2 - yy1, 0.f);
            float aj = (u2 - u1) * (v2 - v1);
            float iou = inter / (ai + aj - inter + 1e-12f);
            if (iou > IOU_THR) bits |= (1u << b);
        }
    }
    g_mask[(size_t)i * MASK_W + w] = bits;
}

// ---------------- sequential greedy scan (single warp) ----------------
__global__ void nms_scan_k()
{
    const int lane = threadIdx.x;   // 32 threads
    unsigned kw[6];
#pragma unroll
    for (int q = 0; q < 6; q++) kw[q] = g_keep_init[q * 32 + lane];

#pragma unroll
    for (int q = 0; q < 6; q++) {
        const int iend = (q == 5) ? (PRE_NMS - 5 * 1024) : 1024;
        for (int ii = 0; ii < iend; ii++) {
            int i = q * 1024 + ii;
            unsigned word = __shfl_sync(0xFFFFFFFFu, kw[q], (i >> 5) & 31);
            if ((word >> (i & 31)) & 1u) {
                const unsigned* row = &g_mask[(size_t)i * MASK_W];
#pragma unroll
                for (int r = 0; r < 6; r++) kw[r] &= ~row[r * 32 + lane];
            }
        }
    }
#pragma unroll
    for (int q = 0; q < 6; q++) g_keep_fin[q * 32 + lane] = kw[q];
}

// ---------------- write rois (first 300 kept, zero-padded) ----------------
__global__ void write_rois_k(float* __restrict__ out)
{
    float* rois = out + ROI_OFF;
    int t = threadIdx.x;
    for (int i = t; i < POST_NMS * 4; i += 256) rois[i] = 0.f;
    __syncthreads();
    if (t == 0) {
        int r = 0;
        for (int i = 0; i < PRE_NMS && r < POST_NMS; i++) {
            if ((g_keep_fin[i >> 5] >> (i & 31)) & 1u) {
                rois[r * 4 + 0] = g_nb[(size_t)i * 4 + 0];
                rois[r * 4 + 1] = g_nb[(size_t)i * 4 + 1];
                rois[r * 4 + 2] = g_nb[(size_t)i * 4 + 2];
                rois[r * 4 + 3] = g_nb[(size_t)i * 4 + 3];
                r++;
            }
        }
    }
}

// ---------------- launcher ----------------
extern "C" void kernel_launch(void* const* d_in, const int* in_sizes, int n_in,
                              void* d_out, int out_size)
{
    const float* features = (const float*)d_in[0];
    const float* anchor   = (const float*)d_in[1];
    const float* w1       = (const float*)d_in[2];
    const float* b1       = (const float*)d_in[3];
    const float* wc       = (const float*)d_in[4];
    const float* bc       = (const float*)d_in[5];
    const float* wl       = (const float*)d_in[6];
    const float* bl       = (const float*)d_in[7];
    float* out = (float*)d_out;

    cudaFuncSetAttribute(sort_topk_k,
                         cudaFuncAttributeMaxDynamicSharedMemorySize,
                         SORTN * sizeof(unsigned long long));

    init_k<<<48, 256>>>();

    dim3 g1((WW + TX - 1) / TX, (HH + TY - 1) / TY, CIN / COT);
    conv3x3_k<<<g1, 256>>>(features, w1, b1);

    conv1x1_k<<<(NPIX + PXT - 1) / PXT, 256>>>(wc, bc, wl, bl, out);

    decode_k<<<(NBOX + 255) / 256, 256>>>(anchor);

    hist_k<<<512, 256>>>(0, 24u, 0x00000000u);
    scan_k<<<1, 32>>>(0, 24u);
    hist_k<<<512, 256>>>(1, 16u, 0xFF000000u);
    scan_k<<<1, 32>>>(1, 16u);
    hist_k<<<512, 256>>>(2,  8u, 0xFFFF0000u);
    scan_k<<<1, 32>>>(2,  8u);
    hist_k<<<512, 256>>>(3,  0u, 0xFFFFFF00u);
    scan_k<<<1, 32>>>(3,  0u);

    count_k<<<NBLK, 256>>>();
    scanb_k<<<1, 32>>>();
    place_k<<<NBLK, 256>>>();
    tie_select_k<<<1, 32>>>();

    sort_topk_k<<<1, 1024, SORTN * sizeof(unsigned long long)>>>();

    mask_k<<<PRE_NMS, MASK_W>>>();

    nms_scan_k<<<1, 32>>>();

    write_rois_k<<<1, 256>>>(out);
}

// round 5
// speedup vs baseline: 1.0450x; 1.0450x over previous
#include <cuda_runtime.h>
#include <cuda_bf16.h>
#include <math.h>

// ---------------- problem constants ----------------
#define HH 200
#define WW 200
#define NPIX (HH*WW)            // 40000
#define CIN 512
#define AA 9
#define NBOX (NPIX*AA)          // 360000
#define PRE_NMS 6000
#define POST_NMS 300
#define MIN_SIZE (16.0f/1000.0f)
#define IOU_THR 0.7f

#define CLS_OFF 0
#define LOC_OFF (NBOX*2)        // 720000
#define ROI_OFF (NBOX*2 + NBOX*4)  // 2160000

#define MASK_W 192              // 32-bit words per mask row (>= 6000/32)
#define SORTN 8192
#define TIE_WORDS ((NBOX + 31) / 32)   // 11250
#define NBLK 1407               // ceil(NBOX/256)

// ---------------- scratch (device globals; no allocation allowed) ------------
// NOTE: __device__ symbols are ONLY referenced from device code. Passing them
// as host-side kernel arguments silently yields the host shadow address.
__device__ float g_x[(size_t)CIN * NPIX];          // conv1 output (relu), [ci][p]
__device__ float g_cls[(size_t)NBOX * 2];          // private copy of cls logits
__device__ float g_loc[(size_t)NBOX * 4];          // private copy of loc deltas
__device__ __align__(16) float g_roi[(size_t)NBOX * 4];
__device__ unsigned g_key[NBOX];                   // ascending-sort key (= score desc)
__device__ unsigned g_hist[4 * 256];
__device__ unsigned g_state[2];                    // {threshold T, r = ties needed}
__device__ int g_cnt;                              // count of keys strictly < T
__device__ unsigned g_bcnt[NBLK + 1];
__device__ unsigned g_boff[NBLK + 1];
__device__ unsigned long long g_cand[SORTN];
__device__ unsigned g_tiebm[TIE_WORDS];
__device__ __align__(16) float g_nb[6144 * 4];     // top-6000 boxes (padded)
__device__ unsigned g_keep_init[MASK_W];
__device__ unsigned g_keep_fin[MASK_W];
__device__ unsigned g_mask[(size_t)PRE_NMS * MASK_W];

// ---------------- packed f32x2 helpers (sm_103a) ----------------
__device__ __forceinline__ unsigned long long fma2(
    unsigned long long a, unsigned long long b, unsigned long long c)
{
    unsigned long long d;
    asm("fma.rn.f32x2 %0, %1, %2, %3;" : "=l"(d) : "l"(a), "l"(b), "l"(c));
    return d;
}
__device__ __forceinline__ unsigned long long pack2(unsigned lo, unsigned hi)
{
    unsigned long long r;
    asm("mov.b64 %0, {%1, %2};" : "=l"(r) : "r"(lo), "r"(hi));
    return r;
}
__device__ __forceinline__ void unpack2(unsigned long long v, unsigned& lo, unsigned& hi)
{
    asm("mov.b64 {%0, %1}, %2;" : "=r"(lo), "=r"(hi) : "l"(v));
}

// ---------------- init ----------------
__global__ void init_k() {
    int t = blockIdx.x * 256 + threadIdx.x;
    const int STRIDE = 48 * 256;
    for (int i = t; i < 4 * 256; i += STRIDE) g_hist[i] = 0;
    for (int i = t; i < TIE_WORDS; i += STRIDE) g_tiebm[i] = 0;
    for (int i = t; i < SORTN; i += STRIDE) g_cand[i] = 0xFFFFFFFFFFFFFFFFull;
    for (int i = t; i < NBLK + 1; i += STRIDE) { g_bcnt[i] = 0; g_boff[i] = 0; }
    for (int i = t; i < MASK_W; i += STRIDE) { g_keep_init[i] = 0; g_keep_fin[i] = 0; }
    if (t == 0) { g_cnt = 0; g_state[0] = 0u; g_state[1] = PRE_NMS; }
}

// ---------------- conv 3x3 (512->512) + bias + relu, packed f32x2 ----------
// block tile: 64 co x (16w x 8h) px, 256 threads
// thread: 4 co x 2 rows x 4 px (accumulated as f32x2 pairs)
#define TX 16
#define TY 8
#define COT 64
#define CK 8
__global__ __launch_bounds__(256) void conv3x3_k(
    const float* __restrict__ f, const float* __restrict__ w1,
    const float* __restrict__ b1)
{
    __shared__ __align__(16) float s_in[CK][TY + 2][TX + 2];  // 8x10x18
    __shared__ float2 s_w2[COT][CK][9];                        // weights duplicated

    const int bx = blockIdx.x * TX;
    const int by = blockIdx.y * TY;
    const int co0 = blockIdx.z * COT;
    const int t = threadIdx.x;
    const int pg = t & 15;            // 16 pixel-groups
    const int cg = t >> 4;            // 16 co-groups (4 co each)
    const int lx = (pg & 3) * 4;      // 0,4,8,12
    const int ly2 = (pg >> 2) * 2;    // 0,2,4,6  (two output rows each)

    unsigned long long acc2[4][2][2];
#pragma unroll
    for (int k = 0; k < 4; k++)
#pragma unroll
        for (int o = 0; o < 2; o++)
#pragma unroll
            for (int p = 0; p < 2; p++) acc2[k][o][p] = 0ull;

    for (int cb = 0; cb < CIN; cb += CK) {
        __syncthreads();
        // stage input tile: CK x 10 x 18 = 1440
        for (int i = t; i < CK * 10 * 18; i += 256) {
            int ci = i / 180;
            int rem = i - ci * 180;
            int r = rem / 18;
            int c = rem - r * 18;
            int gy = by + r - 1, gx = bx + c - 1;
            float v = 0.f;
            if (gy >= 0 && gy < HH && gx >= 0 && gx < WW)
                v = f[((size_t)(cb + ci) * HH + gy) * WW + gx];
            s_in[ci][r][c] = v;
        }
        // stage weights duplicated: 64 x 8 x 9
        for (int i = t; i < COT * CK * 9; i += 256) {
            int co = i / (CK * 9);
            int rem = i - co * (CK * 9);
            int ci = rem / 9;
            int tap = rem - ci * 9;
            float v = w1[((size_t)(co0 + co) * CIN + (cb + ci)) * 9 + tap];
            s_w2[co][ci][tap] = make_float2(v, v);
        }
        __syncthreads();

#pragma unroll
        for (int ci = 0; ci < CK; ci++) {
            // load 4 input rows x 6 cols as aligned pairs, build odd pairs
            unsigned long long E[4][3], O[4][2];
#pragma unroll
            for (int r = 0; r < 4; r++) {
                const float* row = &s_in[ci][ly2 + r][lx];
#pragma unroll
                for (int e = 0; e < 3; e++)
                    E[r][e] = *reinterpret_cast<const unsigned long long*>(row + 2 * e);
                unsigned a0, a1, a2, a3, a4, a5;
                unpack2(E[r][0], a0, a1);
                unpack2(E[r][1], a2, a3);
                unpack2(E[r][2], a4, a5);
                O[r][0] = pack2(a1, a2);
                O[r][1] = pack2(a3, a4);
            }
#pragma unroll
            for (int k = 0; k < 4; k++) {
                const float2* wrow = &s_w2[cg * 4 + k][ci][0];
#pragma unroll
                for (int rt = 0; rt < 3; rt++) {
#pragma unroll
                    for (int c2 = 0; c2 < 3; c2++) {
                        unsigned long long w =
                            *reinterpret_cast<const unsigned long long*>(wrow + rt * 3 + c2);
#pragma unroll
                        for (int o = 0; o < 2; o++) {
                            int r = o + rt;
                            unsigned long long p0, p1;
                            if (c2 == 0)      { p0 = E[r][0]; p1 = E[r][1]; }
                            else if (c2 == 1) { p0 = O[r][0]; p1 = O[r][1]; }
                            else              { p0 = E[r][1]; p1 = E[r][2]; }
                            acc2[k][o][0] = fma2(w, p0, acc2[k][o][0]);
                            acc2[k][o][1] = fma2(w, p1, acc2[k][o][1]);
                        }
                    }
                }
            }
        }
    }

#pragma unroll
    for (int k = 0; k < 4; k++) {
        int co = co0 + cg * 4 + k;
        float bias = b1[co];
#pragma unroll
        for (int o = 0; o < 2; o++) {
            int y = by + ly2 + o;
#pragma unroll
            for (int p = 0; p < 2; p++) {
                unsigned ulo, uhi;
                unpack2(acc2[k][o][p], ulo, uhi);
                float v0 = __uint_as_float(ulo) + bias;
                float v1 = __uint_as_float(uhi) + bias;
                int x0 = bx + lx + 2 * p;
                if (x0 < WW)
                    g_x[((size_t)co * HH + y) * WW + x0] = v0 > 0.f ? v0 : 0.f;
                if (x0 + 1 < WW)
                    g_x[((size_t)co * HH + y) * WW + x0 + 1] = v1 > 0.f ? v1 : 0.f;
            }
        }
    }
}

// ---------------- 1x1 heads (cls 18 + loc 36), NHWC into d_out + private ----
#define PXT 128
#define OC 64
#define CKB 16
__global__ __launch_bounds__(256) void conv1x1_k(
    const float* __restrict__ wc, const float* __restrict__ bc,
    const float* __restrict__ wl, const float* __restrict__ bl,
    float* __restrict__ out)
{
    __shared__ float s_x[CKB][PXT];
    __shared__ float s_w[OC][CKB];
    const int p0 = blockIdx.x * PXT;
    const int t = threadIdx.x;
    const int cg = t >> 4;   // 16 groups x 4 co
    const int pg = t & 15;   // 16 groups x 8 px

    float acc[4][8];
#pragma unroll
    for (int k = 0; k < 4; k++)
#pragma unroll
        for (int j = 0; j < 8; j++) acc[k][j] = 0.f;

    for (int cb = 0; cb < CIN; cb += CKB) {
        __syncthreads();
        for (int i = t; i < CKB * PXT; i += 256) {
            int ci = i >> 7, pp = i & 127;
            int p = p0 + pp;
            s_x[ci][pp] = (p < NPIX) ? g_x[(size_t)(cb + ci) * NPIX + p] : 0.f;
        }
        for (int i = t; i < OC * CKB; i += 256) {
            int co = i >> 4, ci = i & 15;
            float v = 0.f;
            if (co < 18) v = wc[(size_t)co * CIN + cb + ci];
            else if (co < 54) v = wl[(size_t)(co - 18) * CIN + cb + ci];
            s_w[co][ci] = v;
        }
        __syncthreads();
#pragma unroll 4
        for (int ci = 0; ci < CKB; ci++) {
            float xv[8];
#pragma unroll
            for (int j = 0; j < 8; j++) xv[j] = s_x[ci][pg * 8 + j];
#pragma unroll
            for (int k = 0; k < 4; k++) {
                float wv = s_w[cg * 4 + k][ci];
#pragma unroll
                for (int j = 0; j < 8; j++)
                    acc[k][j] = fmaf(wv, xv[j], acc[k][j]);
            }
        }
    }

#pragma unroll
    for (int k = 0; k < 4; k++) {
        int co = cg * 4 + k;
#pragma unroll
        for (int j = 0; j < 8; j++) {
            int p = p0 + pg * 8 + j;
            if (p < NPIX) {
                if (co < 18) {
                    float v = acc[k][j] + bc[co];
                    out[CLS_OFF + (size_t)p * 18 + co] = v;
                    g_cls[(size_t)p * 18 + co] = v;
                } else if (co < 54) {
                    float v = acc[k][j] + bl[co - 18];
                    out[LOC_OFF + (size_t)p * 36 + (co - 18)] = v;
                    g_loc[(size_t)p * 36 + (co - 18)] = v;
                }
            }
        }
    }
}

// ---------------- decode boxes + scores + sort keys ----------------
__global__ void decode_k(const float* __restrict__ anchor)
{
    int n = blockIdx.x * 256 + threadIdx.x;
    if (n >= NBOX) return;
    float a0 = anchor[(size_t)n * 4 + 0], a1 = anchor[(size_t)n * 4 + 1];
    float a2 = anchor[(size_t)n * 4 + 2], a3 = anchor[(size_t)n * 4 + 3];
    float aw = a2 - a0, ah = a3 - a1;
    float acx = (a0 + a2) * 0.5f, acy = (a1 + a3) * 0.5f;
    float l0 = g_loc[(size_t)n * 4 + 0];
    float l1 = g_loc[(size_t)n * 4 + 1];
    float l2 = g_loc[(size_t)n * 4 + 2];
    float l3 = g_loc[(size_t)n * 4 + 3];
    float cx = l0 * aw + acx, cy = l1 * ah + acy;
    float bw = expf(l2) * aw, bh = expf(l3) * ah;
    float x1 = fminf(fmaxf(cx - bw * 0.5f, 0.f), 1.f);
    float y1 = fminf(fmaxf(cy - bh * 0.5f, 0.f), 1.f);
    float x2 = fminf(fmaxf(cx + bw * 0.5f, 0.f), 1.f);
    float y2 = fminf(fmaxf(cy + bh * 0.5f, 0.f), 1.f);
    g_roi[(size_t)n * 4 + 0] = x1;
    g_roi[(size_t)n * 4 + 1] = y1;
    g_roi[(size_t)n * 4 + 2] = x2;
    g_roi[(size_t)n * 4 + 3] = y2;

    float c0 = g_cls[(size_t)n * 2 + 0];
    float c1 = g_cls[(size_t)n * 2 + 1];
    float s = 1.f / (1.f + expf(c0 - c1));     // softmax[:,1]
    bool valid = ((y2 - y1) >= MIN_SIZE) && ((x2 - x1) >= MIN_SIZE);
    float sc = valid ? s : -1.0f;

    unsigned b = __float_as_uint(sc);
    unsigned ord = (b & 0x80000000u) ? ~b : (b | 0x80000000u); // ascending float order
    g_key[n] = ~ord;    // ascending key == descending score
}

// ---------------- 4-pass MSD radix select: exact 32-bit threshold ----------
__global__ void hist_k(int pass, unsigned shift, unsigned pmask)
{
    __shared__ unsigned h[256];
    int t = threadIdx.x;
    for (int i = t; i < 256; i += 256) h[i] = 0;
    __syncthreads();
    unsigned prefix = g_state[0];
    for (int n = blockIdx.x * 256 + t; n < NBOX; n += gridDim.x * 256) {
        unsigned K = g_key[n];
        if ((K & pmask) == prefix) atomicAdd(&h[(K >> shift) & 255u], 1u);
    }
    __syncthreads();
    unsigned* hist = &g_hist[pass * 256];
    for (int i = t; i < 256; i += 256)
        if (h[i]) atomicAdd(&hist[i], h[i]);
}

__global__ void scan_k(int pass, unsigned shift)
{
    if (threadIdx.x == 0) {
        const unsigned* hist = &g_hist[pass * 256];
        unsigned k = g_state[1];
        unsigned cum = 0;
        int d = 0;
        for (; d < 256; d++) {
            if (cum + hist[d] >= k) break;
            cum += hist[d];
        }
        if (d > 255) d = 255;
        g_state[0] |= ((unsigned)d) << shift;
        g_state[1] = k - cum;
    }
}

// ---------------- deterministic compaction (no atomic ordering) ------------
__global__ __launch_bounds__(256) void count_k()
{
    __shared__ unsigned wsum[8];
    int n = blockIdx.x * 256 + threadIdx.x;
    unsigned T = g_state[0];
    bool pred = (n < NBOX) && (g_key[n] < T);
    unsigned bal = __ballot_sync(0xFFFFFFFFu, pred);
    if ((threadIdx.x & 31) == 0) wsum[threadIdx.x >> 5] = (unsigned)__popc(bal);
    __syncthreads();
    if (threadIdx.x == 0) {
        unsigned s = 0;
#pragma unroll
        for (int w = 0; w < 8; w++) s += wsum[w];
        g_bcnt[blockIdx.x] = s;
    }
}

// exclusive scan over 1407 block counts (parallel chunked)
#define SCCH 6
__global__ __launch_bounds__(256) void scanb_k()
{
    __shared__ unsigned ssum[256];
    int t = threadIdx.x;
    unsigned loc[SCCH];
    unsigned s = 0;
#pragma unroll
    for (int e = 0; e < SCCH; e++) {
        int idx = t * SCCH + e;
        loc[e] = (idx < NBLK) ? g_bcnt[idx] : 0u;
        s += loc[e];
    }
    ssum[t] = s;
    __syncthreads();
    if (t == 0) {
        unsigned acc = 0;
        for (int i = 0; i < 256; i++) { unsigned tmp = ssum[i]; ssum[i] = acc; acc += tmp; }
        g_cnt = (int)acc;
    }
    __syncthreads();
    unsigned run = ssum[t];
#pragma unroll
    for (int e = 0; e < SCCH; e++) {
        int idx = t * SCCH + e;
        if (idx < NBLK) g_boff[idx] = run;
        run += loc[e];
    }
}

// phase 3: rank-based placement (deterministic order) + tie bitmap
__global__ __launch_bounds__(256) void place_k()
{
    __shared__ unsigned wcnt[8];
    __shared__ unsigned wex[8];
    int t = threadIdx.x;
    int n = blockIdx.x * 256 + t;
    unsigned T = g_state[0];
    unsigned K = (n < NBOX) ? g_key[n] : 0xFFFFFFFFu;
    bool pred = (n < NBOX) && (K < T);
    unsigned bal = __ballot_sync(0xFFFFFFFFu, pred);
    int lane = t & 31, w = t >> 5;
    if (lane == 0) wcnt[w] = (unsigned)__popc(bal);
    __syncthreads();
    if (t == 0) {
        unsigned a = 0;
#pragma unroll
        for (int i = 0; i < 8; i++) { wex[i] = a; a += wcnt[i]; }
    }
    __syncthreads();
    if (pred) {
        unsigned rank = g_boff[blockIdx.x] + wex[w] +
                        (unsigned)__popc(bal & ((1u << lane) - 1u));
        g_cand[rank] = ((unsigned long long)K << 32) | (unsigned)n;
    }
    if ((n < NBOX) && (K == T))
        atomicOr(&g_tiebm[n >> 5], 1u << (n & 31));
}

// pick the r smallest indices among ties (matches top_k stable tie-break)
__global__ void tie_select_k()
{
    const int lane = threadIdx.x;     // 32 threads
    const int base = g_cnt;
    const unsigned r = g_state[1];
    const unsigned T = g_state[0];
    unsigned taken = 0;
    for (int w0 = 0; w0 < TIE_WORDS && taken < r; w0 += 32) {
        int wi = w0 + lane;
        unsigned word = (wi < TIE_WORDS) ? g_tiebm[wi] : 0u;
        int cnt = __popc(word);
        int pre = cnt;
#pragma unroll
        for (int o = 1; o < 32; o <<= 1) {
            int v = __shfl_up_sync(0xFFFFFFFFu, pre, o);
            if (lane >= o) pre += v;
        }
        unsigned rank = taken + (unsigned)(pre - cnt);
        while (word && rank < r) {
            int b = __ffs(word) - 1;
            word &= word - 1;
            unsigned n = (unsigned)wi * 32u + (unsigned)b;
            g_cand[base + rank] = ((unsigned long long)T << 32) | n;
            rank++;
        }
        taken += (unsigned)__shfl_sync(0xFFFFFFFFu, pre, 31);
    }
}

// ---------------- single-block bitonic sort of candidates + gather ----------
extern __shared__ unsigned long long s_sort[];
__global__ void sort_topk_k()
{
    const int t = threadIdx.x;   // 1024 threads
    for (int i = t; i < SORTN; i += 1024)
        s_sort[i] = (i < PRE_NMS) ? g_cand[i] : 0xFFFFFFFFFFFFFFFFull;
    __syncthreads();
    for (int k = 2; k <= SORTN; k <<= 1) {
        for (int j = k >> 1; j > 0; j >>= 1) {
            for (int i = t; i < SORTN; i += 1024) {
                int ixj = i ^ j;
                if (ixj > i) {
                    unsigned long long a = s_sort[i], b = s_sort[ixj];
                    bool up = ((i & k) == 0);
                    if ((a > b) == up) { s_sort[i] = b; s_sort[ixj] = a; }
                }
            }
            __syncthreads();
        }
    }
    // gather boxes + initial keep bitset (valid = score >= 0)
    for (int i = t; i < 6144; i += 1024) {
        bool valid = false;
        if (i < PRE_NMS) {
            unsigned long long v = s_sort[i];
            unsigned K = (unsigned)(v >> 32);
            unsigned n = (unsigned)v;
            float b0 = 0, b1 = 0, b2 = 0, b3 = 0;
            if (n < (unsigned)NBOX) {
                const float4 bb = *reinterpret_cast<const float4*>(&g_roi[(size_t)n * 4]);
                b0 = bb.x; b1 = bb.y; b2 = bb.z; b3 = bb.w;
                valid = (K < 0x80000000u);   // score >= 0
            }
            g_nb[(size_t)i * 4 + 0] = b0;
            g_nb[(size_t)i * 4 + 1] = b1;
            g_nb[(size_t)i * 4 + 2] = b2;
            g_nb[(size_t)i * 4 + 3] = b3;
        }
        unsigned bal = __ballot_sync(0xFFFFFFFFu, valid);
        if ((t & 31) == 0) g_keep_init[i >> 5] = bal;
    }
}

// ---------------- NMS suppression bitmask (j > i only) ----------------
__global__ __launch_bounds__(MASK_W) void mask_k()
{
    const int i = blockIdx.x;
    const int w = threadIdx.x;
    const float4* nb4 = reinterpret_cast<const float4*>(g_nb);
    float4 bi = nb4[i];
    float ai = (bi.z - bi.x) * (bi.w - bi.y);
    unsigned bits = 0;
    int jbase = w * 32;
#pragma unroll 4
    for (int b = 0; b < 32; b++) {
        int j = jbase + b;
        if (j > i && j < PRE_NMS) {
            float4 bj = nb4[j];
            float xx1 = fmaxf(bi.x, bj.x), yy1 = fmaxf(bi.y, bj.y);
            float xx2 = fminf(bi.z, bj.z), yy2 = fminf(bi.w, bj.w);
            float inter = fmaxf(xx2 - xx1, 0.f) * fmaxf(yy2 - yy1, 0.f);
            float aj = (bj.z - bj.x) * (bj.w - bj.y);
            float iou = inter / (ai + aj - inter + 1e-12f);
            if (iou > IOU_THR) bits |= (1u << b);
        }
    }
    g_mask[(size_t)i * MASK_W + w] = bits;
}

// ---------------- sequential greedy scan (single warp) ----------------
__global__ void nms_scan_k()
{
    const int lane = threadIdx.x;   // 32 threads
    unsigned kw[6];
#pragma unroll
    for (int q = 0; q < 6; q++) kw[q] = g_keep_init[q * 32 + lane];

#pragma unroll
    for (int q = 0; q < 6; q++) {
        const int iend = (q == 5) ? (PRE_NMS - 5 * 1024) : 1024;
        for (int ii = 0; ii < iend; ii++) {
            int i = q * 1024 + ii;
            unsigned word = __shfl_sync(0xFFFFFFFFu, kw[q], (i >> 5) & 31);
            if ((word >> (i & 31)) & 1u) {
                const unsigned* row = &g_mask[(size_t)i * MASK_W];
#pragma unroll
                for (int r = 0; r < 6; r++) kw[r] &= ~row[r * 32 + lane];
            }
        }
    }
#pragma unroll
    for (int q = 0; q < 6; q++) g_keep_fin[q * 32 + lane] = kw[q];
}

// ---------------- write rois (first 300 kept, zero-padded, parallel) -------
__global__ __launch_bounds__(256) void write_rois_k(float* __restrict__ out)
{
    float* rois = out + ROI_OFF;
    __shared__ unsigned woff[MASK_W];
    int t = threadIdx.x;
    for (int i = t; i < POST_NMS * 4; i += 256) rois[i] = 0.f;
    if (t < MASK_W) woff[t] = (unsigned)__popc(g_keep_fin[t]);
    __syncthreads();
    if (t == 0) {
        unsigned acc = 0;
        for (int i = 0; i < MASK_W; i++) { unsigned tmp = woff[i]; woff[i] = acc; acc += tmp; }
    }
    __syncthreads();
    if (t < MASK_W) {
        unsigned word = g_keep_fin[t];
        unsigned rank = woff[t];
        while (word) {
            int b = __ffs(word) - 1;
            word &= word - 1;
            if (rank < POST_NMS) {
                int i = t * 32 + b;
                rois[rank * 4 + 0] = g_nb[(size_t)i * 4 + 0];
                rois[rank * 4 + 1] = g_nb[(size_t)i * 4 + 1];
                rois[rank * 4 + 2] = g_nb[(size_t)i * 4 + 2];
                rois[rank * 4 + 3] = g_nb[(size_t)i * 4 + 3];
            }
            rank++;
        }
    }
}

// ---------------- launcher ----------------
extern "C" void kernel_launch(void* const* d_in, const int* in_sizes, int n_in,
                              void* d_out, int out_size)
{
    const float* features = (const float*)d_in[0];
    const float* anchor   = (const float*)d_in[1];
    const float* w1       = (const float*)d_in[2];
    const float* b1       = (const float*)d_in[3];
    const float* wc       = (const float*)d_in[4];
    const float* bc       = (const float*)d_in[5];
    const float* wl       = (const float*)d_in[6];
    const float* bl       = (const float*)d_in[7];
    float* out = (float*)d_out;

    cudaFuncSetAttribute(sort_topk_k,
                         cudaFuncAttributeMaxDynamicSharedMemorySize,
                         SORTN * sizeof(unsigned long long));

    init_k<<<48, 256>>>();

    dim3 g1((WW + TX - 1) / TX, (HH + TY - 1) / TY, CIN / COT);
    conv3x3_k<<<g1, 256>>>(features, w1, b1);

    conv1x1_k<<<(NPIX + PXT - 1) / PXT, 256>>>(wc, bc, wl, bl, out);

    decode_k<<<(NBOX + 255) / 256, 256>>>(anchor);

    hist_k<<<512, 256>>>(0, 24u, 0x00000000u);
    scan_k<<<1, 32>>>(0, 24u);
    hist_k<<<512, 256>>>(1, 16u, 0xFF000000u);
    scan_k<<<1, 32>>>(1, 16u);
    hist_k<<<512, 256>>>(2,  8u, 0xFFFF0000u);
    scan_k<<<1, 32>>>(2,  8u);
    hist_k<<<512, 256>>>(3,  0u, 0xFFFFFF00u);
    scan_k<<<1, 32>>>(3,  0u);

    count_k<<<NBLK, 256>>>();
    scanb_k<<<1, 256>>>();
    place_k<<<NBLK, 256>>>();
    tie_select_k<<<1, 32>>>();

    sort_topk_k<<<1, 1024, SORTN * sizeof(unsigned long long)>>>();

    mask_k<<<PRE_NMS, MASK_W>>>();

    nms_scan_k<<<1, 32>>>();

    write_rois_k<<<1, 256>>>(out);
}

// round 8
// speedup vs baseline: 1.3349x; 1.2775x over previous
#include <cuda_runtime.h>
#include <cuda_bf16.h>
#include <math.h>
#include <cstdint>

// ---------------- problem constants ----------------
#define HH 200
#define WW 200
#define NPIX (HH*WW)            // 40000
#define CIN 512
#define AA 9
#define NBOX (NPIX*AA)          // 360000
#define PRE_NMS 6000
#define POST_NMS 300
#define MIN_SIZE (16.0f/1000.0f)
#define IOU_THR 0.7f

#define CLS_OFF 0
#define LOC_OFF (NBOX*2)        // 720000
#define ROI_OFF (NBOX*2 + NBOX*4)  // 2160000

#define MASK_W 192
#define SORTN 8192
#define TIE_WORDS ((NBOX + 31) / 32)   // 11250
#define NBLK 1407               // ceil(NBOX/256)

// ---- implicit GEMM geometry (warp-level mma.sync, sm_80+ path) ----
#define KTOT (CIN*9)            // 4608
#define KC 32
#define NCHUNK (KTOT/KC)        // 144
#define DRAIN 2                 // drain accumulators every 2 chunks (RZ-bias fix)
#define MTILE 128
#define NTILE 128
#define NPXT ((NPIX + NTILE - 1)/NTILE)   // 313
#define PITCH 40                // bf16 elems per smem row (80 B) - conflict-free
#define SPLIT_B (128*PITCH*2)   // 10240 bytes per split tile
#define BS_OFF  (3*SPLIT_B)     // B tiles start after 3 A tiles
#define CONV_SMEM (6*SPLIT_B)   // 61440 bytes

// ---------------- scratch (device globals) ------------
__device__ float g_x[(size_t)CIN * NPIX];
__device__ __align__(16) __nv_bfloat16 g_ws[3][(size_t)CIN * KTOT];   // split weights [co][k]
__device__ __align__(16) __nv_bfloat16 g_xs[3][(size_t)CIN * NPIX];   // split features [ci][p]
__device__ float g_cls[(size_t)NBOX * 2];
__device__ float g_loc[(size_t)NBOX * 4];
__device__ __align__(16) float g_roi[(size_t)NBOX * 4];
__device__ unsigned g_key[NBOX];
__device__ unsigned g_hist[4 * 256];
__device__ unsigned g_state[2];
__device__ int g_cnt;
__device__ unsigned g_bcnt[NBLK + 1];
__device__ unsigned g_boff[NBLK + 1];
__device__ unsigned long long g_cand[SORTN];
__device__ unsigned g_tiebm[TIE_WORDS];
__device__ __align__(16) float g_nb[6144 * 4];
__device__ unsigned g_keep_init[MASK_W];
__device__ unsigned g_keep_fin[MASK_W];
__device__ unsigned g_mask[(size_t)PRE_NMS * MASK_W];

// ---------------- PTX helpers ----------------
__device__ __forceinline__ uint32_t smem_u32(const void* p) {
    uint32_t a;
    asm("{ .reg .u64 t; cvta.to.shared.u64 t, %1; cvt.u32.u64 %0, t; }" : "=r"(a) : "l"(p));
    return a;
}
__device__ __forceinline__ void ldsm_x4(unsigned* r, uint32_t addr) {
    asm volatile("ldmatrix.sync.aligned.m8n8.x4.shared.b16 {%0,%1,%2,%3}, [%4];"
        : "=r"(r[0]), "=r"(r[1]), "=r"(r[2]), "=r"(r[3]) : "r"(addr));
}
__device__ __forceinline__ void ldsm_x2(unsigned* r, uint32_t addr) {
    asm volatile("ldmatrix.sync.aligned.m8n8.x2.shared.b16 {%0,%1}, [%2];"
        : "=r"(r[0]), "=r"(r[1]) : "r"(addr));
}
__device__ __forceinline__ void mma16816(float* d, const unsigned* a, const unsigned* b) {
    asm volatile(
        "mma.sync.aligned.m16n8k16.row.col.f32.bf16.bf16.f32 "
        "{%0,%1,%2,%3}, {%4,%5,%6,%7}, {%8,%9}, {%0,%1,%2,%3};"
        : "+f"(d[0]), "+f"(d[1]), "+f"(d[2]), "+f"(d[3])
        : "r"(a[0]), "r"(a[1]), "r"(a[2]), "r"(a[3]), "r"(b[0]), "r"(b[1]));
}

// ---------------- init ----------------
__global__ void init_k() {
    int t = blockIdx.x * 256 + threadIdx.x;
    const int STRIDE = 48 * 256;
    for (int i = t; i < 4 * 256; i += STRIDE) g_hist[i] = 0;
    for (int i = t; i < TIE_WORDS; i += STRIDE) g_tiebm[i] = 0;
    for (int i = t; i < SORTN; i += STRIDE) g_cand[i] = 0xFFFFFFFFFFFFFFFFull;
}
__global__ void initb_k() {
    int t = blockIdx.x * 256 + threadIdx.x;
    const int STRIDE = 48 * 256;
    for (int i = t; i < NBLK + 1; i += STRIDE) { g_bcnt[i] = 0; g_boff[i] = 0; }
    for (int i = t; i < MASK_W; i += STRIDE) { g_keep_init[i] = 0; g_keep_fin[i] = 0; }
    if (t == 0) { g_cnt = 0; g_state[0] = 0u; g_state[1] = PRE_NMS; }
}

// ---------------- fp32 -> 3x bf16 splits ----------------
__device__ __forceinline__ void split3(float v, __nv_bfloat16& b0,
                                       __nv_bfloat16& b1, __nv_bfloat16& b2) {
    b0 = __float2bfloat16(v);
    float r = v - __bfloat162float(b0);
    b1 = __float2bfloat16(r);
    float r2 = r - __bfloat162float(b1);
    b2 = __float2bfloat16(r2);
}

__global__ __launch_bounds__(256) void xsplit_k(const float* __restrict__ f, int phase)
{
    const size_t HALF = (size_t)CIN * NPIX / 2;
    size_t n = (size_t)phase * HALF + blockIdx.x * 256 + threadIdx.x;
    if (n >= (size_t)(phase + 1) * HALF) return;
    __nv_bfloat16 a, b, c;
    split3(f[n], a, b, c);
    g_xs[0][n] = a; g_xs[1][n] = b; g_xs[2][n] = c;
}

__global__ __launch_bounds__(256) void wsplit_k(const float* __restrict__ w1)
{
    size_t n = (size_t)blockIdx.x * 256 + threadIdx.x;
    if (n >= (size_t)CIN * KTOT) return;
    __nv_bfloat16 a, b, c;
    split3(w1[n], a, b, c);
    g_ws[0][n] = a; g_ws[1][n] = b; g_ws[2][n] = c;
}

// ---------------- conv3x3 via mma.sync bf16x3 implicit GEMM ----------------
// CTA: 128co x 128px, 8 warps (warp tile 64x32), K chunks of 32.
// Accumulator chains drained every DRAIN chunks into fp32 masters to kill
// HMMA's RZ-biased accumulate (measured 3.1e-5 at chain length 1728).
__global__ __launch_bounds__(256) void conv_mma_k(const float* __restrict__ b1)
{
    extern __shared__ __align__(16) char smem[];
    const uint32_t sb = smem_u32(smem);
    const int t = threadIdx.x;
    const int w = t >> 5, lane = t & 31;
    const int p0 = blockIdx.x * NTILE;
    const int co0 = blockIdx.y * MTILE;
    const int mw = (w & 1) * 64;      // warp co offset
    const int nw = (w >> 1) * 32;     // warp px offset

    float acc[4][4][4];    // mma working accumulators
    float accm[4][4][4];   // fp32 masters
#pragma unroll
    for (int mt = 0; mt < 4; mt++)
#pragma unroll
        for (int nt = 0; nt < 4; nt++)
#pragma unroll
            for (int e = 0; e < 4; e++) { acc[mt][nt][e] = 0.f; accm[mt][nt][e] = 0.f; }

    // staging roles
    const int arow = t >> 1, ahalf = t & 1;          // A: 2 thr/row, 16 bf16 each
    const int bpx = t & 127, bseg = (t >> 7) * 16;   // B: px, k-segment base (2x16)
    const int bp = p0 + bpx;
    const int by = bp / 200, bx2 = bp - by * 200;

    // per-lane ldmatrix byte offsets
    const uint32_t a_lb = (uint32_t)(((lane & 7) + ((lane >> 3) & 1) * 8) * (PITCH * 2)
                                     + (lane >> 4) * 16);
    const uint32_t b_lb = (uint32_t)((lane & 7) * (PITCH * 2) + ((lane >> 3) & 1) * 16);

    for (int c = 0; c < NCHUNK; c++) {
        const int k0g = c * KC;
        if (c) __syncthreads();   // previous chunk's readers done

        // ---- stage A: 3 splits x 128 x 32 bf16
#pragma unroll
        for (int s = 0; s < 3; s++) {
            const uint4* src = (const uint4*)&g_ws[s][(size_t)(co0 + arow) * KTOT
                                                     + k0g + ahalf * 16];
            uint4 v0 = src[0], v1 = src[1];
            uint4* dst = (uint4*)(smem + s * SPLIT_B + arow * (PITCH * 2) + ahalf * 32);
            dst[0] = v0; dst[1] = v1;
        }
        // ---- stage B (im2col gather): 3 splits x 128px x 32k
#pragma unroll
        for (int seg = 0; seg < 2; seg++) {
            const int klb = bseg + seg * 8;
#pragma unroll
            for (int s = 0; s < 3; s++) {
                unsigned rr[4];
#pragma unroll
                for (int jj = 0; jj < 4; jj++) {
                    unsigned pk = 0;
#pragma unroll
                    for (int h = 0; h < 2; h++) {
                        int k = k0g + klb + jj * 2 + h;
                        int ci = k / 9;
                        int tap = k - 9 * ci;
                        int dy = tap / 3 - 1, dx = tap - (tap / 3) * 3 - 1;
                        int yy = by + dy, xx = bx2 + dx;
                        unsigned v = 0;
                        if (bp < NPIX && (unsigned)yy < (unsigned)HH &&
                            (unsigned)xx < (unsigned)WW) {
                            v = *(const unsigned short*)
                                (&g_xs[s][(size_t)ci * NPIX + yy * WW + xx]);
                        }
                        pk |= v << (16 * h);
                    }
                    rr[jj] = pk;
                }
                *(uint4*)(smem + BS_OFF + s * SPLIT_B + bpx * (PITCH * 2) + klb * 2)
                    = make_uint4(rr[0], rr[1], rr[2], rr[3]);
            }
        }
        __syncthreads();

        // ---- compute: 2 k16 steps x 6 split-products
#pragma unroll
        for (int ks = 0; ks < 2; ks++) {
            const uint32_t koff = (uint32_t)(ks * 32);   // k16*2 bytes
#pragma unroll
            for (int s = 0; s < 3; s++) {
                unsigned af[4][4];
#pragma unroll
                for (int mt = 0; mt < 4; mt++)
                    ldsm_x4(af[mt], sb + s * SPLIT_B
                            + (uint32_t)((mw + mt * 16) * (PITCH * 2)) + a_lb + koff);
#pragma unroll
                for (int tt = 0; tt < 3; tt++) {
                    if (s + tt > 2) break;
                    unsigned bf[4][2];
#pragma unroll
                    for (int nt = 0; nt < 4; nt++)
                        ldsm_x2(bf[nt], sb + BS_OFF + tt * SPLIT_B
                                + (uint32_t)((nw + nt * 8) * (PITCH * 2)) + b_lb + koff);
#pragma unroll
                    for (int mt = 0; mt < 4; mt++)
#pragma unroll
                        for (int nt = 0; nt < 4; nt++)
                            mma16816(acc[mt][nt], af[mt], bf[nt]);
                }
            }
        }

        // ---- drain working accumulators into fp32 masters (RN adds)
        if ((c % DRAIN) == (DRAIN - 1)) {
#pragma unroll
            for (int mt = 0; mt < 4; mt++)
#pragma unroll
                for (int nt = 0; nt < 4; nt++)
#pragma unroll
                    for (int e = 0; e < 4; e++) {
                        accm[mt][nt][e] += acc[mt][nt][e];
                        acc[mt][nt][e] = 0.f;
                    }
        }
    }

    // ---- epilogue: bias + relu -> g_x (masters hold full sums; NCHUNK%DRAIN==0)
#pragma unroll
    for (int mt = 0; mt < 4; mt++) {
        int r0 = co0 + mw + mt * 16 + (lane >> 2);
        float bias0 = b1[r0], bias1 = b1[r0 + 8];
#pragma unroll
        for (int nt = 0; nt < 4; nt++) {
            int col = p0 + nw + nt * 8 + (lane & 3) * 2;
            if (col < NPIX) {
                float v0 = accm[mt][nt][0] + bias0;
                float v2 = accm[mt][nt][2] + bias1;
                g_x[(size_t)r0 * NPIX + col] = v0 > 0.f ? v0 : 0.f;
                g_x[(size_t)(r0 + 8) * NPIX + col] = v2 > 0.f ? v2 : 0.f;
            }
            if (col + 1 < NPIX) {
                float v1 = accm[mt][nt][1] + bias0;
                float v3 = accm[mt][nt][3] + bias1;
                g_x[(size_t)r0 * NPIX + col + 1] = v1 > 0.f ? v1 : 0.f;
                g_x[(size_t)(r0 + 8) * NPIX + col + 1] = v3 > 0.f ? v3 : 0.f;
            }
        }
    }
}

// ---------------- 1x1 heads (cls 18 + loc 36) ----------------
#define PXT 128
#define OC 64
#define CKB 16
__global__ __launch_bounds__(256) void conv1x1_k(
    const float* __restrict__ wc, const float* __restrict__ bc,
    const float* __restrict__ wl, const float* __restrict__ bl,
    float* __restrict__ out)
{
    __shared__ float s_x[CKB][PXT];
    __shared__ float s_w[OC][CKB];
    const int p0 = blockIdx.x * PXT;
    const int t = threadIdx.x;
    const int cg = t >> 4;
    const int pg = t & 15;

    float acc[4][8];
#pragma unroll
    for (int k = 0; k < 4; k++)
#pragma unroll
        for (int j = 0; j < 8; j++) acc[k][j] = 0.f;

    for (int cb = 0; cb < CIN; cb += CKB) {
        __syncthreads();
        for (int i = t; i < CKB * PXT; i += 256) {
            int ci = i >> 7, pp = i & 127;
            int p = p0 + pp;
            s_x[ci][pp] = (p < NPIX) ? g_x[(size_t)(cb + ci) * NPIX + p] : 0.f;
        }
        for (int i = t; i < OC * CKB; i += 256) {
            int co = i >> 4, ci = i & 15;
            float v = 0.f;
            if (co < 18) v = wc[(size_t)co * CIN + cb + ci];
            else if (co < 54) v = wl[(size_t)(co - 18) * CIN + cb + ci];
            s_w[co][ci] = v;
        }
        __syncthreads();
#pragma unroll 4
        for (int ci = 0; ci < CKB; ci++) {
            float xv[8];
#pragma unroll
            for (int j = 0; j < 8; j++) xv[j] = s_x[ci][pg * 8 + j];
#pragma unroll
            for (int k = 0; k < 4; k++) {
                float wv = s_w[cg * 4 + k][ci];
#pragma unroll
                for (int j = 0; j < 8; j++)
                    acc[k][j] = fmaf(wv, xv[j], acc[k][j]);
            }
        }
    }

#pragma unroll
    for (int k = 0; k < 4; k++) {
        int co = cg * 4 + k;
#pragma unroll
        for (int j = 0; j < 8; j++) {
            int p = p0 + pg * 8 + j;
            if (p < NPIX) {
                if (co < 18) {
                    float v = acc[k][j] + bc[co];
                    out[CLS_OFF + (size_t)p * 18 + co] = v;
                    g_cls[(size_t)p * 18 + co] = v;
                } else if (co < 54) {
                    float v = acc[k][j] + bl[co - 18];
                    out[LOC_OFF + (size_t)p * 36 + (co - 18)] = v;
                    g_loc[(size_t)p * 36 + (co - 18)] = v;
                }
            }
        }
    }
}

// ---------------- decode boxes + scores + sort keys ----------------
__global__ void decode_k(const float* __restrict__ anchor)
{
    int n = blockIdx.x * 256 + threadIdx.x;
    if (n >= NBOX) return;
    float a0 = anchor[(size_t)n * 4 + 0], a1 = anchor[(size_t)n * 4 + 1];
    float a2 = anchor[(size_t)n * 4 + 2], a3 = anchor[(size_t)n * 4 + 3];
    float aw = a2 - a0, ah = a3 - a1;
    float acx = (a0 + a2) * 0.5f, acy = (a1 + a3) * 0.5f;
    float l0 = g_loc[(size_t)n * 4 + 0];
    float l1 = g_loc[(size_t)n * 4 + 1];
    float l2 = g_loc[(size_t)n * 4 + 2];
    float l3 = g_loc[(size_t)n * 4 + 3];
    float cx = l0 * aw + acx, cy = l1 * ah + acy;
    float bw = expf(l2) * aw, bh = expf(l3) * ah;
    float x1 = fminf(fmaxf(cx - bw * 0.5f, 0.f), 1.f);
    float y1 = fminf(fmaxf(cy - bh * 0.5f, 0.f), 1.f);
    float x2 = fminf(fmaxf(cx + bw * 0.5f, 0.f), 1.f);
    float y2 = fminf(fmaxf(cy + bh * 0.5f, 0.f), 1.f);
    g_roi[(size_t)n * 4 + 0] = x1;
    g_roi[(size_t)n * 4 + 1] = y1;
    g_roi[(size_t)n * 4 + 2] = x2;
    g_roi[(size_t)n * 4 + 3] = y2;

    float c0 = g_cls[(size_t)n * 2 + 0];
    float c1 = g_cls[(size_t)n * 2 + 1];
    float s = 1.f / (1.f + expf(c0 - c1));
    bool valid = ((y2 - y1) >= MIN_SIZE) && ((x2 - x1) >= MIN_SIZE);
    float sc = valid ? s : -1.0f;

    unsigned b = __float_as_uint(sc);
    unsigned ord = (b & 0x80000000u) ? ~b : (b | 0x80000000u);
    g_key[n] = ~ord;
}

// ---------------- 4-pass MSD radix select ----------------
__global__ void hist_k(int pass, unsigned shift, unsigned pmask)
{
    __shared__ unsigned h[256];
    int t = threadIdx.x;
    for (int i = t; i < 256; i += 256) h[i] = 0;
    __syncthreads();
    unsigned prefix = g_state[0];
    for (int n = blockIdx.x * 256 + t; n < NBOX; n += gridDim.x * 256) {
        unsigned K = g_key[n];
        if ((K & pmask) == prefix) atomicAdd(&h[(K >> shift) & 255u], 1u);
    }
    __syncthreads();
    unsigned* hist = &g_hist[pass * 256];
    for (int i = t; i < 256; i += 256)
        if (h[i]) atomicAdd(&hist[i], h[i]);
}

__global__ void scan_k(int pass, unsigned shift)
{
    if (threadIdx.x == 0) {
        const unsigned* hist = &g_hist[pass * 256];
        unsigned k = g_state[1];
        unsigned cum = 0;
        int d = 0;
        for (; d < 256; d++) {
            if (cum + hist[d] >= k) break;
            cum += hist[d];
        }
        if (d > 255) d = 255;
        g_state[0] |= ((unsigned)d) << shift;
        g_state[1] = k - cum;
    }
}

// ---------------- deterministic compaction ------------
__global__ __launch_bounds__(256) void count_k()
{
    __shared__ unsigned wsum[8];
    int n = blockIdx.x * 256 + threadIdx.x;
    unsigned T = g_state[0];
    bool pred = (n < NBOX) && (g_key[n] < T);
    unsigned bal = __ballot_sync(0xFFFFFFFFu, pred);
    if ((threadIdx.x & 31) == 0) wsum[threadIdx.x >> 5] = (unsigned)__popc(bal);
    __syncthreads();
    if (threadIdx.x == 0) {
        unsigned s = 0;
#pragma unroll
        for (int w = 0; w < 8; w++) s += wsum[w];
        g_bcnt[blockIdx.x] = s;
    }
}

#define SCCH 6
__global__ __launch_bounds__(256) void scanb_k()
{
    __shared__ unsigned ssum[256];
    int t = threadIdx.x;
    unsigned loc[SCCH];
    unsigned s = 0;
#pragma unroll
    for (int e = 0; e < SCCH; e++) {
        int idx = t * SCCH + e;
        loc[e] = (idx < NBLK) ? g_bcnt[idx] : 0u;
        s += loc[e];
    }
    ssum[t] = s;
    __syncthreads();
    if (t == 0) {
        unsigned acc = 0;
        for (int i = 0; i < 256; i++) { unsigned tmp = ssum[i]; ssum[i] = acc; acc += tmp; }
        g_cnt = (int)acc;
    }
    __syncthreads();
    unsigned run = ssum[t];
#pragma unroll
    for (int e = 0; e < SCCH; e++) {
        int idx = t * SCCH + e;
        if (idx < NBLK) g_boff[idx] = run;
        run += loc[e];
    }
}

__global__ __launch_bounds__(256) void place_k()
{
    __shared__ unsigned wcnt[8];
    __shared__ unsigned wex[8];
    int t = threadIdx.x;
    int n = blockIdx.x * 256 + t;
    unsigned T = g_state[0];
    unsigned K = (n < NBOX) ? g_key[n] : 0xFFFFFFFFu;
    bool pred = (n < NBOX) && (K < T);
    unsigned bal = __ballot_sync(0xFFFFFFFFu, pred);
    int lane = t & 31, w = t >> 5;
    if (lane == 0) wcnt[w] = (unsigned)__popc(bal);
    __syncthreads();
    if (t == 0) {
        unsigned a = 0;
#pragma unroll
        for (int i = 0; i < 8; i++) { wex[i] = a; a += wcnt[i]; }
    }
    __syncthreads();
    if (pred) {
        unsigned rank = g_boff[blockIdx.x] + wex[w] +
                        (unsigned)__popc(bal & ((1u << lane) - 1u));
        g_cand[rank] = ((unsigned long long)K << 32) | (unsigned)n;
    }
    if ((n < NBOX) && (K == T))
        atomicOr(&g_tiebm[n >> 5], 1u << (n & 31));
}

__global__ void tie_select_k()
{
    const int lane = threadIdx.x;
    const int base = g_cnt;
    const unsigned r = g_state[1];
    const unsigned T = g_state[0];
    unsigned taken = 0;
    for (int w0 = 0; w0 < TIE_WORDS && taken < r; w0 += 32) {
        int wi = w0 + lane;
        unsigned word = (wi < TIE_WORDS) ? g_tiebm[wi] : 0u;
        int cnt = __popc(word);
        int pre = cnt;
#pragma unroll
        for (int o = 1; o < 32; o <<= 1) {
            int v = __shfl_up_sync(0xFFFFFFFFu, pre, o);
            if (lane >= o) pre += v;
        }
        unsigned rank = taken + (unsigned)(pre - cnt);
        while (word && rank < r) {
            int b = __ffs(word) - 1;
            word &= word - 1;
            unsigned n = (unsigned)wi * 32u + (unsigned)b;
            g_cand[base + rank] = ((unsigned long long)T << 32) | n;
            rank++;
        }
        taken += (unsigned)__shfl_sync(0xFFFFFFFFu, pre, 31);
    }
}

// ---------------- single-block bitonic sort + gather ----------
extern __shared__ unsigned long long s_sort[];
__global__ void sort_topk_k()
{
    const int t = threadIdx.x;
    for (int i = t; i < SORTN; i += 1024)
        s_sort[i] = (i < PRE_NMS) ? g_cand[i] : 0xFFFFFFFFFFFFFFFFull;
    __syncthreads();
    for (int k = 2; k <= SORTN; k <<= 1) {
        for (int j = k >> 1; j > 0; j >>= 1) {
            for (int i = t; i < SORTN; i += 1024) {
                int ixj = i ^ j;
                if (ixj > i) {
                    unsigned long long a = s_sort[i], b = s_sort[ixj];
                    bool up = ((i & k) == 0);
                    if ((a > b) == up) { s_sort[i] = b; s_sort[ixj] = a; }
                }
            }
            __syncthreads();
        }
    }
    for (int i = t; i < 6144; i += 1024) {
        bool valid = false;
        if (i < PRE_NMS) {
            unsigned long long v = s_sort[i];
            unsigned K = (unsigned)(v >> 32);
            unsigned n = (unsigned)v;
            float b0 = 0, b1 = 0, b2 = 0, b3 = 0;
            if (n < (unsigned)NBOX) {
                const float4 bb = *reinterpret_cast<const float4*>(&g_roi[(size_t)n * 4]);
                b0 = bb.x; b1 = bb.y; b2 = bb.z; b3 = bb.w;
                valid = (K < 0x80000000u);
            }
            g_nb[(size_t)i * 4 + 0] = b0;
            g_nb[(size_t)i * 4 + 1] = b1;
            g_nb[(size_t)i * 4 + 2] = b2;
            g_nb[(size_t)i * 4 + 3] = b3;
        }
        unsigned bal = __ballot_sync(0xFFFFFFFFu, valid);
        if ((t & 31) == 0) g_keep_init[i >> 5] = bal;
    }
}

// ---------------- NMS suppression bitmask ----------------
__global__ __launch_bounds__(MASK_W) void mask_k()
{
    const int i = blockIdx.x;
    const int w = threadIdx.x;
    const float4* nb4 = reinterpret_cast<const float4*>(g_nb);
    float4 bi = nb4[i];
    float ai = (bi.z - bi.x) * (bi.w - bi.y);
    unsigned bits = 0;
    int jbase = w * 32;
#pragma unroll 4
    for (int b = 0; b < 32; b++) {
        int j = jbase + b;
        if (j > i && j < PRE_NMS) {
            float4 bj = nb4[j];
            float xx1 = fmaxf(bi.x, bj.x), yy1 = fmaxf(bi.y, bj.y);
            float xx2 = fminf(bi.z, bj.z), yy2 = fminf(bi.w, bj.w);
            float inter = fmaxf(xx2 - xx1, 0.f) * fmaxf(yy2 - yy1, 0.f);
            float aj = (bj.z - bj.x) * (bj.w - bj.y);
            float iou = inter / (ai + aj - inter + 1e-12f);
            if (iou > IOU_THR) bits |= (1u << b);
        }
    }
    g_mask[(size_t)i * MASK_W + w] = bits;
}

// ---------------- sequential greedy scan (single warp) ----------------
__global__ void nms_scan_k()
{
    const int lane = threadIdx.x;
    unsigned kw[6];
#pragma unroll
    for (int q = 0; q < 6; q++) kw[q] = g_keep_init[q * 32 + lane];

#pragma unroll
    for (int q = 0; q < 6; q++) {
        const int iend = (q == 5) ? (PRE_NMS - 5 * 1024) : 1024;
        for (int ii = 0; ii < iend; ii++) {
            int i = q * 1024 + ii;
            unsigned word = __shfl_sync(0xFFFFFFFFu, kw[q], (i >> 5) & 31);
            if ((word >> (i & 31)) & 1u) {
                const unsigned* row = &g_mask[(size_t)i * MASK_W];
#pragma unroll
                for (int r = 0; r < 6; r++) kw[r] &= ~row[r * 32 + lane];
            }
        }
    }
#pragma unroll
    for (int q = 0; q < 6; q++) g_keep_fin[q * 32 + lane] = kw[q];
}

// ---------------- write rois ----------------
__global__ __launch_bounds__(256) void write_rois_k(float* __restrict__ out)
{
    float* rois = out + ROI_OFF;
    __shared__ unsigned woff[MASK_W];
    int t = threadIdx.x;
    for (int i = t; i < POST_NMS * 4; i += 256) rois[i] = 0.f;
    if (t < MASK_W) woff[t] = (unsigned)__popc(g_keep_fin[t]);
    __syncthreads();
    if (t == 0) {
        unsigned acc = 0;
        for (int i = 0; i < MASK_W; i++) { unsigned tmp = woff[i]; woff[i] = acc; acc += tmp; }
    }
    __syncthreads();
    if (t < MASK_W) {
        unsigned word = g_keep_fin[t];
        unsigned rank = woff[t];
        while (word) {
            int b = __ffs(word) - 1;
            word &= word - 1;
            if (rank < POST_NMS) {
                int i = t * 32 + b;
                rois[rank * 4 + 0] = g_nb[(size_t)i * 4 + 0];
                rois[rank * 4 + 1] = g_nb[(size_t)i * 4 + 1];
                rois[rank * 4 + 2] = g_nb[(size_t)i * 4 + 2];
                rois[rank * 4 + 3] = g_nb[(size_t)i * 4 + 3];
            }
            rank++;
        }
    }
}

// ---------------- launcher ----------------
extern "C" void kernel_launch(void* const* d_in, const int* in_sizes, int n_in,
                              void* d_out, int out_size)
{
    const float* features = (const float*)d_in[0];
    const float* anchor   = (const float*)d_in[1];
    const float* w1       = (const float*)d_in[2];
    const float* b1       = (const float*)d_in[3];
    const float* wc       = (const float*)d_in[4];
    const float* bc       = (const float*)d_in[5];
    const float* wl       = (const float*)d_in[6];
    const float* bl       = (const float*)d_in[7];
    float* out = (float*)d_out;

    cudaFuncSetAttribute(sort_topk_k,
                         cudaFuncAttributeMaxDynamicSharedMemorySize,
                         SORTN * sizeof(unsigned long long));
    cudaFuncSetAttribute(conv_mma_k,
                         cudaFuncAttributeMaxDynamicSharedMemorySize,
                         CONV_SMEM);

    // launches 0..4 precede conv_mma (ncu -s 5 -c 1 captures conv_mma)
    init_k<<<48, 256>>>();
    initb_k<<<48, 256>>>();
    const int XHALF_BLKS = (int)(((size_t)CIN * NPIX / 2 + 255) / 256);
    xsplit_k<<<XHALF_BLKS, 256>>>(features, 0);
    xsplit_k<<<XHALF_BLKS, 256>>>(features, 1);
    wsplit_k<<<(int)(((size_t)CIN * KTOT + 255) / 256), 256>>>(w1);

    dim3 gmma(NPXT, CIN / MTILE);   // 313 x 4
    conv_mma_k<<<gmma, 256, CONV_SMEM>>>(b1);

    conv1x1_k<<<(NPIX + PXT - 1) / PXT, 256>>>(wc, bc, wl, bl, out);

    decode_k<<<(NBOX + 255) / 256, 256>>>(anchor);

    hist_k<<<512, 256>>>(0, 24u, 0x00000000u);
    scan_k<<<1, 32>>>(0, 24u);
    hist_k<<<512, 256>>>(1, 16u, 0xFF000000u);
    scan_k<<<1, 32>>>(1, 16u);
    hist_k<<<512, 256>>>(2,  8u, 0xFFFF0000u);
    scan_k<<<1, 32>>>(2,  8u);
    hist_k<<<512, 256>>>(3,  0u, 0xFFFFFF00u);
    scan_k<<<1, 32>>>(3,  0u);

    count_k<<<NBLK, 256>>>();
    scanb_k<<<1, 256>>>();
    place_k<<<NBLK, 256>>>();
    tie_select_k<<<1, 32>>>();

    sort_topk_k<<<1, 1024, SORTN * sizeof(unsigned long long)>>>();

    mask_k<<<PRE_NMS, MASK_W>>>();

    nms_scan_k<<<1, 32>>>();

    write_rois_k<<<1, 256>>>(out);
}

// round 9
// speedup vs baseline: 1.4351x; 1.0751x over previous
#include <cuda_runtime.h>
#include <cuda_bf16.h>
#include <math.h>
#include <cstdint>

// ---------------- problem constants ----------------
#define HH 200
#define WW 200
#define NPIX (HH*WW)            // 40000
#define CIN 512
#define AA 9
#define NBOX (NPIX*AA)          // 360000
#define PRE_NMS 6000
#define POST_NMS 300
#define MIN_SIZE (16.0f/1000.0f)
#define IOU_THR 0.7f

#define CLS_OFF 0
#define LOC_OFF (NBOX*2)        // 720000
#define ROI_OFF (NBOX*2 + NBOX*4)  // 2160000

#define MASK_W 192
#define SORTN 8192
#define TIE_WORDS ((NBOX + 31) / 32)   // 11250
#define NBLK 1407               // ceil(NBOX/256)

// ---- implicit GEMM geometry (warp-level mma.sync, sm_80+ path) ----
#define KTOT (CIN*9)            // 4608
#define KC 32
#define NCHUNK (KTOT/KC)        // 144
#define DRAIN 2                 // drain accumulators every 2 chunks (RZ-bias fix)
#define MTILE 128
#define NTILE 128
#define NPXT ((NPIX + NTILE - 1)/NTILE)   // 313
#define PITCH 40                // bf16 elems per smem row (80 B) - conflict-free
#define SPLIT_B (128*PITCH*2)   // 10240 bytes per split tile
#define BS_OFF  (3*SPLIT_B)     // B tiles start after 3 A tiles
#define CONV_SMEM (6*SPLIT_B)   // 61440 bytes

// ---------------- scratch (device globals) ------------
__device__ float g_x[(size_t)CIN * NPIX];
__device__ __align__(16) __nv_bfloat16 g_ws[3][(size_t)CIN * KTOT];   // split weights [co][k]
__device__ __align__(16) __nv_bfloat16 g_xs[3][(size_t)CIN * NPIX];   // split features [ci][p]
__device__ float g_cls[(size_t)NBOX * 2];
__device__ float g_loc[(size_t)NBOX * 4];
__device__ __align__(16) float g_roi[(size_t)NBOX * 4];
__device__ unsigned g_key[NBOX];
__device__ unsigned g_hist[4 * 256];
__device__ unsigned g_state[2];
__device__ int g_cnt;
__device__ unsigned g_bcnt[NBLK + 1];
__device__ unsigned g_boff[NBLK + 1];
__device__ unsigned long long g_cand[SORTN];
__device__ unsigned g_tiebm[TIE_WORDS];
__device__ __align__(16) float g_nb[6144 * 4];
__device__ unsigned g_keep_init[MASK_W];
__device__ unsigned g_keep_fin[MASK_W];
__device__ unsigned g_mask[(size_t)PRE_NMS * MASK_W];

// ---------------- PTX helpers ----------------
__device__ __forceinline__ uint32_t smem_u32(const void* p) {
    uint32_t a;
    asm("{ .reg .u64 t; cvta.to.shared.u64 t, %1; cvt.u32.u64 %0, t; }" : "=r"(a) : "l"(p));
    return a;
}
__device__ __forceinline__ void ldsm_x4(unsigned* r, uint32_t addr) {
    asm volatile("ldmatrix.sync.aligned.m8n8.x4.shared.b16 {%0,%1,%2,%3}, [%4];"
        : "=r"(r[0]), "=r"(r[1]), "=r"(r[2]), "=r"(r[3]) : "r"(addr));
}
__device__ __forceinline__ void ldsm_x2(unsigned* r, uint32_t addr) {
    asm volatile("ldmatrix.sync.aligned.m8n8.x2.shared.b16 {%0,%1}, [%2];"
        : "=r"(r[0]), "=r"(r[1]) : "r"(addr));
}
__device__ __forceinline__ void mma16816(float* d, const unsigned* a, const unsigned* b) {
    asm volatile(
        "mma.sync.aligned.m16n8k16.row.col.f32.bf16.bf16.f32 "
        "{%0,%1,%2,%3}, {%4,%5,%6,%7}, {%8,%9}, {%0,%1,%2,%3};"
        : "+f"(d[0]), "+f"(d[1]), "+f"(d[2]), "+f"(d[3])
        : "r"(a[0]), "r"(a[1]), "r"(a[2]), "r"(a[3]), "r"(b[0]), "r"(b[1]));
}

// ---------------- init ----------------
__global__ void init_k() {
    int t = blockIdx.x * 256 + threadIdx.x;
    const int STRIDE = 48 * 256;
    for (int i = t; i < 4 * 256; i += STRIDE) g_hist[i] = 0;
    for (int i = t; i < TIE_WORDS; i += STRIDE) g_tiebm[i] = 0;
    for (int i = t; i < SORTN; i += STRIDE) g_cand[i] = 0xFFFFFFFFFFFFFFFFull;
}
__global__ void initb_k() {
    int t = blockIdx.x * 256 + threadIdx.x;
    const int STRIDE = 48 * 256;
    for (int i = t; i < NBLK + 1; i += STRIDE) { g_bcnt[i] = 0; g_boff[i] = 0; }
    for (int i = t; i < MASK_W; i += STRIDE) { g_keep_init[i] = 0; g_keep_fin[i] = 0; }
    if (t == 0) { g_cnt = 0; g_state[0] = 0u; g_state[1] = PRE_NMS; }
}

// ---------------- fp32 -> 3x bf16 splits ----------------
__device__ __forceinline__ void split3(float v, __nv_bfloat16& b0,
                                       __nv_bfloat16& b1, __nv_bfloat16& b2) {
    b0 = __float2bfloat16(v);
    float r = v - __bfloat162float(b0);
    b1 = __float2bfloat16(r);
    float r2 = r - __bfloat162float(b1);
    b2 = __float2bfloat16(r2);
}

__global__ __launch_bounds__(256) void xsplit_k(const float* __restrict__ f, int phase)
{
    const size_t HALF = (size_t)CIN * NPIX / 2;
    size_t n = (size_t)phase * HALF + blockIdx.x * 256 + threadIdx.x;
    if (n >= (size_t)(phase + 1) * HALF) return;
    __nv_bfloat16 a, b, c;
    split3(f[n], a, b, c);
    g_xs[0][n] = a; g_xs[1][n] = b; g_xs[2][n] = c;
}

__global__ __launch_bounds__(256) void wsplit_k(const float* __restrict__ w1)
{
    size_t n = (size_t)blockIdx.x * 256 + threadIdx.x;
    if (n >= (size_t)CIN * KTOT) return;
    __nv_bfloat16 a, b, c;
    split3(w1[n], a, b, c);
    g_ws[0][n] = a; g_ws[1][n] = b; g_ws[2][n] = c;
}

// ---------------- conv3x3 via mma.sync bf16x3 implicit GEMM ----------------
// CTA: 128co x 128px, 8 warps (warp tile 64x32), K chunks of 32.
// Register-pipelined staging: chunk c+1 global loads issued before chunk c's
// compute; im2col address math computed once per k and reused for 3 splits.
// Accumulator chains drained every DRAIN chunks into fp32 masters (RZ fix).
__global__ __launch_bounds__(256) void conv_mma_k(const float* __restrict__ b1)
{
    extern __shared__ __align__(16) char smem[];
    const uint32_t sb = smem_u32(smem);
    const int t = threadIdx.x;
    const int w = t >> 5, lane = t & 31;
    const int p0 = blockIdx.x * NTILE;
    const int co0 = blockIdx.y * MTILE;
    const int mw = (w & 1) * 64;      // warp co offset
    const int nw = (w >> 1) * 32;     // warp px offset

    float acc[4][4][4];    // mma working accumulators
    float accm[4][4][4];   // fp32 masters
#pragma unroll
    for (int mt = 0; mt < 4; mt++)
#pragma unroll
        for (int nt = 0; nt < 4; nt++)
#pragma unroll
            for (int e = 0; e < 4; e++) { acc[mt][nt][e] = 0.f; accm[mt][nt][e] = 0.f; }

    // staging roles
    const int arow = t >> 1, ahalf = t & 1;      // A: 2 thr/row, 16 bf16 each
    const int bpx = t & 127;                     // B: pixel owned
    const int bk0 = (t >> 7) * 16;               // B: first of 16 k-offsets
    const int bp = p0 + bpx;
    const int by = bp / 200, bx2 = bp - by * 200;
    const bool bok = bp < NPIX;

    // per-lane ldmatrix byte offsets
    const uint32_t a_lb = (uint32_t)(((lane & 7) + ((lane >> 3) & 1) * 8) * (PITCH * 2)
                                     + (lane >> 4) * 16);
    const uint32_t b_lb = (uint32_t)((lane & 7) * (PITCH * 2) + ((lane >> 3) & 1) * 16);

    // prefetch registers: A = 3 splits x 2 uint4; B = 3 splits x 8 packed u32
    uint4 aR[3][2];
    unsigned bR[3][8];

    auto prefetch = [&](int c) {
        const int k0g = c * KC;
#pragma unroll
        for (int s = 0; s < 3; s++) {
            const uint4* src = (const uint4*)&g_ws[s][(size_t)(co0 + arow) * KTOT
                                                     + k0g + ahalf * 16];
            aR[s][0] = src[0];
            aR[s][1] = src[1];
        }
#pragma unroll
        for (int e2 = 0; e2 < 8; e2++) {
            unsigned v[3][2];
#pragma unroll
            for (int h = 0; h < 2; h++) {
                int k = k0g + bk0 + e2 * 2 + h;
                int ci = (int)(((unsigned)k * 7282u) >> 16);    // k/9, k<4608
                int tap = k - 9 * ci;
                int t3 = (tap * 11) >> 5;                        // tap/3, tap<9
                int dy = t3 - 1, dx = tap - 3 * t3 - 1;
                int yy = by + dy, xx = bx2 + dx;
                bool ok = bok && ((unsigned)yy < (unsigned)HH) &&
                          ((unsigned)xx < (unsigned)WW);
                size_t off = (size_t)ci * NPIX + yy * WW + xx;   // shared by splits
#pragma unroll
                for (int s = 0; s < 3; s++)
                    v[s][h] = ok ? (unsigned)*(const unsigned short*)&g_xs[s][off] : 0u;
            }
#pragma unroll
            for (int s = 0; s < 3; s++)
                bR[s][e2] = v[s][0] | (v[s][1] << 16);
        }
    };

    auto store_stage = [&]() {
#pragma unroll
        for (int s = 0; s < 3; s++) {
            uint4* dst = (uint4*)(smem + s * SPLIT_B + arow * (PITCH * 2) + ahalf * 32);
            dst[0] = aR[s][0];
            dst[1] = aR[s][1];
        }
#pragma unroll
        for (int s = 0; s < 3; s++) {
            uint4* dst = (uint4*)(smem + BS_OFF + s * SPLIT_B
                                  + bpx * (PITCH * 2) + bk0 * 2);
            dst[0] = make_uint4(bR[s][0], bR[s][1], bR[s][2], bR[s][3]);
            dst[1] = make_uint4(bR[s][4], bR[s][5], bR[s][6], bR[s][7]);
        }
    };

    prefetch(0);

    for (int c = 0; c < NCHUNK; c++) {
        __syncthreads();    // previous compute done reading smem
        store_stage();
        __syncthreads();    // tile visible to all warps
        if (c + 1 < NCHUNK) prefetch(c + 1);   // LDGs hide under compute below

        // ---- compute: 2 k16 steps x 6 split-products
#pragma unroll
        for (int ks = 0; ks < 2; ks++) {
            const uint32_t koff = (uint32_t)(ks * 32);   // k16*2 bytes
#pragma unroll
            for (int s = 0; s < 3; s++) {
                unsigned af[4][4];
#pragma unroll
                for (int mt = 0; mt < 4; mt++)
                    ldsm_x4(af[mt], sb + s * SPLIT_B
                            + (uint32_t)((mw + mt * 16) * (PITCH * 2)) + a_lb + koff);
#pragma unroll
                for (int tt = 0; tt < 3; tt++) {
                    if (s + tt > 2) break;
                    unsigned bf[4][2];
#pragma unroll
                    for (int nt = 0; nt < 4; nt++)
                        ldsm_x2(bf[nt], sb + BS_OFF + tt * SPLIT_B
                                + (uint32_t)((nw + nt * 8) * (PITCH * 2)) + b_lb + koff);
#pragma unroll
                    for (int mt = 0; mt < 4; mt++)
#pragma unroll
                        for (int nt = 0; nt < 4; nt++)
                            mma16816(acc[mt][nt], af[mt], bf[nt]);
                }
            }
        }

        // ---- drain working accumulators into fp32 masters (RN adds)
        if ((c % DRAIN) == (DRAIN - 1)) {
#pragma unroll
            for (int mt = 0; mt < 4; mt++)
#pragma unroll
                for (int nt = 0; nt < 4; nt++)
#pragma unroll
                    for (int e = 0; e < 4; e++) {
                        accm[mt][nt][e] += acc[mt][nt][e];
                        acc[mt][nt][e] = 0.f;
                    }
        }
    }

    // ---- epilogue: bias + relu -> g_x (masters hold full sums; NCHUNK%DRAIN==0)
#pragma unroll
    for (int mt = 0; mt < 4; mt++) {
        int r0 = co0 + mw + mt * 16 + (lane >> 2);
        float bias0 = b1[r0], bias1 = b1[r0 + 8];
#pragma unroll
        for (int nt = 0; nt < 4; nt++) {
            int col = p0 + nw + nt * 8 + (lane & 3) * 2;
            if (col < NPIX) {
                float v0 = accm[mt][nt][0] + bias0;
                float v2 = accm[mt][nt][2] + bias1;
                g_x[(size_t)r0 * NPIX + col] = v0 > 0.f ? v0 : 0.f;
                g_x[(size_t)(r0 + 8) * NPIX + col] = v2 > 0.f ? v2 : 0.f;
            }
            if (col + 1 < NPIX) {
                float v1 = accm[mt][nt][1] + bias0;
                float v3 = accm[mt][nt][3] + bias1;
                g_x[(size_t)r0 * NPIX + col + 1] = v1 > 0.f ? v1 : 0.f;
                g_x[(size_t)(r0 + 8) * NPIX + col + 1] = v3 > 0.f ? v3 : 0.f;
            }
        }
    }
}

// ---------------- 1x1 heads (cls 18 + loc 36) ----------------
#define PXT 128
#define OC 64
#define CKB 16
__global__ __launch_bounds__(256) void conv1x1_k(
    const float* __restrict__ wc, const float* __restrict__ bc,
    const float* __restrict__ wl, const float* __restrict__ bl,
    float* __restrict__ out)
{
    __shared__ float s_x[CKB][PXT];
    __shared__ float s_w[OC][CKB];
    const int p0 = blockIdx.x * PXT;
    const int t = threadIdx.x;
    const int cg = t >> 4;
    const int pg = t & 15;

    float acc[4][8];
#pragma unroll
    for (int k = 0; k < 4; k++)
#pragma unroll
        for (int j = 0; j < 8; j++) acc[k][j] = 0.f;

    for (int cb = 0; cb < CIN; cb += CKB) {
        __syncthreads();
        for (int i = t; i < CKB * PXT; i += 256) {
            int ci = i >> 7, pp = i & 127;
            int p = p0 + pp;
            s_x[ci][pp] = (p < NPIX) ? g_x[(size_t)(cb + ci) * NPIX + p] : 0.f;
        }
        for (int i = t; i < OC * CKB; i += 256) {
            int co = i >> 4, ci = i & 15;
            float v = 0.f;
            if (co < 18) v = wc[(size_t)co * CIN + cb + ci];
            else if (co < 54) v = wl[(size_t)(co - 18) * CIN + cb + ci];
            s_w[co][ci] = v;
        }
        __syncthreads();
#pragma unroll 4
        for (int ci = 0; ci < CKB; ci++) {
            float xv[8];
#pragma unroll
            for (int j = 0; j < 8; j++) xv[j] = s_x[ci][pg * 8 + j];
#pragma unroll
            for (int k = 0; k < 4; k++) {
                float wv = s_w[cg * 4 + k][ci];
#pragma unroll
                for (int j = 0; j < 8; j++)
                    acc[k][j] = fmaf(wv, xv[j], acc[k][j]);
            }
        }
    }

#pragma unroll
    for (int k = 0; k < 4; k++) {
        int co = cg * 4 + k;
#pragma unroll
        for (int j = 0; j < 8; j++) {
            int p = p0 + pg * 8 + j;
            if (p < NPIX) {
                if (co < 18) {
                    float v = acc[k][j] + bc[co];
                    out[CLS_OFF + (size_t)p * 18 + co] = v;
                    g_cls[(size_t)p * 18 + co] = v;
                } else if (co < 54) {
                    float v = acc[k][j] + bl[co - 18];
                    out[LOC_OFF + (size_t)p * 36 + (co - 18)] = v;
                    g_loc[(size_t)p * 36 + (co - 18)] = v;
                }
            }
        }
    }
}

// ---------------- decode boxes + scores + sort keys ----------------
__global__ void decode_k(const float* __restrict__ anchor)
{
    int n = blockIdx.x * 256 + threadIdx.x;
    if (n >= NBOX) return;
    float a0 = anchor[(size_t)n * 4 + 0], a1 = anchor[(size_t)n * 4 + 1];
    float a2 = anchor[(size_t)n * 4 + 2], a3 = anchor[(size_t)n * 4 + 3];
    float aw = a2 - a0, ah = a3 - a1;
    float acx = (a0 + a2) * 0.5f, acy = (a1 + a3) * 0.5f;
    float l0 = g_loc[(size_t)n * 4 + 0];
    float l1 = g_loc[(size_t)n * 4 + 1];
    float l2 = g_loc[(size_t)n * 4 + 2];
    float l3 = g_loc[(size_t)n * 4 + 3];
    float cx = l0 * aw + acx, cy = l1 * ah + acy;
    float bw = expf(l2) * aw, bh = expf(l3) * ah;
    float x1 = fminf(fmaxf(cx - bw * 0.5f, 0.f), 1.f);
    float y1 = fminf(fmaxf(cy - bh * 0.5f, 0.f), 1.f);
    float x2 = fminf(fmaxf(cx + bw * 0.5f, 0.f), 1.f);
    float y2 = fminf(fmaxf(cy + bh * 0.5f, 0.f), 1.f);
    g_roi[(size_t)n * 4 + 0] = x1;
    g_roi[(size_t)n * 4 + 1] = y1;
    g_roi[(size_t)n * 4 + 2] = x2;
    g_roi[(size_t)n * 4 + 3] = y2;

    float c0 = g_cls[(size_t)n * 2 + 0];
    float c1 = g_cls[(size_t)n * 2 + 1];
    float s = 1.f / (1.f + expf(c0 - c1));
    bool valid = ((y2 - y1) >= MIN_SIZE) && ((x2 - x1) >= MIN_SIZE);
    float sc = valid ? s : -1.0f;

    unsigned b = __float_as_uint(sc);
    unsigned ord = (b & 0x80000000u) ? ~b : (b | 0x80000000u);
    g_key[n] = ~ord;
}

// ---------------- 4-pass MSD radix select ----------------
__global__ void hist_k(int pass, unsigned shift, unsigned pmask)
{
    __shared__ unsigned h[256];
    int t = threadIdx.x;
    for (int i = t; i < 256; i += 256) h[i] = 0;
    __syncthreads();
    unsigned prefix = g_state[0];
    for (int n = blockIdx.x * 256 + t; n < NBOX; n += gridDim.x * 256) {
        unsigned K = g_key[n];
        if ((K & pmask) == prefix) atomicAdd(&h[(K >> shift) & 255u], 1u);
    }
    __syncthreads();
    unsigned* hist = &g_hist[pass * 256];
    for (int i = t; i < 256; i += 256)
        if (h[i]) atomicAdd(&hist[i], h[i]);
}

__global__ void scan_k(int pass, unsigned shift)
{
    if (threadIdx.x == 0) {
        const unsigned* hist = &g_hist[pass * 256];
        unsigned k = g_state[1];
        unsigned cum = 0;
        int d = 0;
        for (; d < 256; d++) {
            if (cum + hist[d] >= k) break;
            cum += hist[d];
        }
        if (d > 255) d = 255;
        g_state[0] |= ((unsigned)d) << shift;
        g_state[1] = k - cum;
    }
}

// ---------------- deterministic compaction ------------
__global__ __launch_bounds__(256) void count_k()
{
    __shared__ unsigned wsum[8];
    int n = blockIdx.x * 256 + threadIdx.x;
    unsigned T = g_state[0];
    bool pred = (n < NBOX) && (g_key[n] < T);
    unsigned bal = __ballot_sync(0xFFFFFFFFu, pred);
    if ((threadIdx.x & 31) == 0) wsum[threadIdx.x >> 5] = (unsigned)__popc(bal);
    __syncthreads();
    if (threadIdx.x == 0) {
        unsigned s = 0;
#pragma unroll
        for (int w = 0; w < 8; w++) s += wsum[w];
        g_bcnt[blockIdx.x] = s;
    }
}

#define SCCH 6
__global__ __launch_bounds__(256) void scanb_k()
{
    __shared__ unsigned ssum[256];
    int t = threadIdx.x;
    unsigned loc[SCCH];
    unsigned s = 0;
#pragma unroll
    for (int e = 0; e < SCCH; e++) {
        int idx = t * SCCH + e;
        loc[e] = (idx < NBLK) ? g_bcnt[idx] : 0u;
        s += loc[e];
    }
    ssum[t] = s;
    __syncthreads();
    if (t == 0) {
        unsigned acc = 0;
        for (int i = 0; i < 256; i++) { unsigned tmp = ssum[i]; ssum[i] = acc; acc += tmp; }
        g_cnt = (int)acc;
    }
    __syncthreads();
    unsigned run = ssum[t];
#pragma unroll
    for (int e = 0; e < SCCH; e++) {
        int idx = t * SCCH + e;
        if (idx < NBLK) g_boff[idx] = run;
        run += loc[e];
    }
}

__global__ __launch_bounds__(256) void place_k()
{
    __shared__ unsigned wcnt[8];
    __shared__ unsigned wex[8];
    int t = threadIdx.x;
    int n = blockIdx.x * 256 + t;
    unsigned T = g_state[0];
    unsigned K = (n < NBOX) ? g_key[n] : 0xFFFFFFFFu;
    bool pred = (n < NBOX) && (K < T);
    unsigned bal = __ballot_sync(0xFFFFFFFFu, pred);
    int lane = t & 31, w = t >> 5;
    if (lane == 0) wcnt[w] = (unsigned)__popc(bal);
    __syncthreads();
    if (t == 0) {
        unsigned a = 0;
#pragma unroll
        for (int i = 0; i < 8; i++) { wex[i] = a; a += wcnt[i]; }
    }
    __syncthreads();
    if (pred) {
        unsigned rank = g_boff[blockIdx.x] + wex[w] +
                        (unsigned)__popc(bal & ((1u << lane) - 1u));
        g_cand[rank] = ((unsigned long long)K << 32) | (unsigned)n;
    }
    if ((n < NBOX) && (K == T))
        atomicOr(&g_tiebm[n >> 5], 1u << (n & 31));
}

__global__ void tie_select_k()
{
    const int lane = threadIdx.x;
    const int base = g_cnt;
    const unsigned r = g_state[1];
    const unsigned T = g_state[0];
    unsigned taken = 0;
    for (int w0 = 0; w0 < TIE_WORDS && taken < r; w0 += 32) {
        int wi = w0 + lane;
        unsigned word = (wi < TIE_WORDS) ? g_tiebm[wi] : 0u;
        int cnt = __popc(word);
        int pre = cnt;
#pragma unroll
        for (int o = 1; o < 32; o <<= 1) {
            int v = __shfl_up_sync(0xFFFFFFFFu, pre, o);
            if (lane >= o) pre += v;
        }
        unsigned rank = taken + (unsigned)(pre - cnt);
        while (word && rank < r) {
            int b = __ffs(word) - 1;
            word &= word - 1;
            unsigned n = (unsigned)wi * 32u + (unsigned)b;
            g_cand[base + rank] = ((unsigned long long)T << 32) | n;
            rank++;
        }
        taken += (unsigned)__shfl_sync(0xFFFFFFFFu, pre, 31);
    }
}

// ---------------- single-block bitonic sort + gather ----------
extern __shared__ unsigned long long s_sort[];
__global__ void sort_topk_k()
{
    const int t = threadIdx.x;
    for (int i = t; i < SORTN; i += 1024)
        s_sort[i] = (i < PRE_NMS) ? g_cand[i] : 0xFFFFFFFFFFFFFFFFull;
    __syncthreads();
    for (int k = 2; k <= SORTN; k <<= 1) {
        for (int j = k >> 1; j > 0; j >>= 1) {
            for (int i = t; i < SORTN; i += 1024) {
                int ixj = i ^ j;
                if (ixj > i) {
                    unsigned long long a = s_sort[i], b = s_sort[ixj];
                    bool up = ((i & k) == 0);
                    if ((a > b) == up) { s_sort[i] = b; s_sort[ixj] = a; }
                }
            }
            __syncthreads();
        }
    }
    for (int i = t; i < 6144; i += 1024) {
        bool valid = false;
        if (i < PRE_NMS) {
            unsigned long long v = s_sort[i];
            unsigned K = (unsigned)(v >> 32);
            unsigned n = (unsigned)v;
            float b0 = 0, b1 = 0, b2 = 0, b3 = 0;
            if (n < (unsigned)NBOX) {
                const float4 bb = *reinterpret_cast<const float4*>(&g_roi[(size_t)n * 4]);
                b0 = bb.x; b1 = bb.y; b2 = bb.z; b3 = bb.w;
                valid = (K < 0x80000000u);
            }
            g_nb[(size_t)i * 4 + 0] = b0;
            g_nb[(size_t)i * 4 + 1] = b1;
            g_nb[(size_t)i * 4 + 2] = b2;
            g_nb[(size_t)i * 4 + 3] = b3;
        }
        unsigned bal = __ballot_sync(0xFFFFFFFFu, valid);
        if ((t & 31) == 0) g_keep_init[i >> 5] = bal;
    }
}

// ---------------- NMS suppression bitmask ----------------
__global__ __launch_bounds__(MASK_W) void mask_k()
{
    const int i = blockIdx.x;
    const int w = threadIdx.x;
    const float4* nb4 = reinterpret_cast<const float4*>(g_nb);
    float4 bi = nb4[i];
    float ai = (bi.z - bi.x) * (bi.w - bi.y);
    unsigned bits = 0;
    int jbase = w * 32;
#pragma unroll 4
    for (int b = 0; b < 32; b++) {
        int j = jbase + b;
        if (j > i && j < PRE_NMS) {
            float4 bj = nb4[j];
            float xx1 = fmaxf(bi.x, bj.x), yy1 = fmaxf(bi.y, bj.y);
            float xx2 = fminf(bi.z, bj.z), yy2 = fminf(bi.w, bj.w);
            float inter = fmaxf(xx2 - xx1, 0.f) * fmaxf(yy2 - yy1, 0.f);
            float aj = (bj.z - bj.x) * (bj.w - bj.y);
            float iou = inter / (ai + aj - inter + 1e-12f);
            if (iou > IOU_THR) bits |= (1u << b);
        }
    }
    g_mask[(size_t)i * MASK_W + w] = bits;
}

// ---------------- sequential greedy scan (single warp) ----------------
__global__ void nms_scan_k()
{
    const int lane = threadIdx.x;
    unsigned kw[6];
#pragma unroll
    for (int q = 0; q < 6; q++) kw[q] = g_keep_init[q * 32 + lane];

#pragma unroll
    for (int q = 0; q < 6; q++) {
        const int iend = (q == 5) ? (PRE_NMS - 5 * 1024) : 1024;
        for (int ii = 0; ii < iend; ii++) {
            int i = q * 1024 + ii;
            unsigned word = __shfl_sync(0xFFFFFFFFu, kw[q], (i >> 5) & 31);
            if ((word >> (i & 31)) & 1u) {
                const unsigned* row = &g_mask[(size_t)i * MASK_W];
#pragma unroll
                for (int r = 0; r < 6; r++) kw[r] &= ~row[r * 32 + lane];
            }
        }
    }
#pragma unroll
    for (int q = 0; q < 6; q++) g_keep_fin[q * 32 + lane] = kw[q];
}

// ---------------- write rois ----------------
__global__ __launch_bounds__(256) void write_rois_k(float* __restrict__ out)
{
    float* rois = out + ROI_OFF;
    __shared__ unsigned woff[MASK_W];
    int t = threadIdx.x;
    for (int i = t; i < POST_NMS * 4; i += 256) rois[i] = 0.f;
    if (t < MASK_W) woff[t] = (unsigned)__popc(g_keep_fin[t]);
    __syncthreads();
    if (t == 0) {
        unsigned acc = 0;
        for (int i = 0; i < MASK_W; i++) { unsigned tmp = woff[i]; woff[i] = acc; acc += tmp; }
    }
    __syncthreads();
    if (t < MASK_W) {
        unsigned word = g_keep_fin[t];
        unsigned rank = woff[t];
        while (word) {
            int b = __ffs(word) - 1;
            word &= word - 1;
            if (rank < POST_NMS) {
                int i = t * 32 + b;
                rois[rank * 4 + 0] = g_nb[(size_t)i * 4 + 0];
                rois[rank * 4 + 1] = g_nb[(size_t)i * 4 + 1];
                rois[rank * 4 + 2] = g_nb[(size_t)i * 4 + 2];
                rois[rank * 4 + 3] = g_nb[(size_t)i * 4 + 3];
            }
            rank++;
        }
    }
}

// ---------------- launcher ----------------
extern "C" void kernel_launch(void* const* d_in, const int* in_sizes, int n_in,
                              void* d_out, int out_size)
{
    const float* features = (const float*)d_in[0];
    const float* anchor   = (const float*)d_in[1];
    const float* w1       = (const float*)d_in[2];
    const float* b1       = (const float*)d_in[3];
    const float* wc       = (const float*)d_in[4];
    const float* bc       = (const float*)d_in[5];
    const float* wl       = (const float*)d_in[6];
    const float* bl       = (const float*)d_in[7];
    float* out = (float*)d_out;

    cudaFuncSetAttribute(sort_topk_k,
                         cudaFuncAttributeMaxDynamicSharedMemorySize,
                         SORTN * sizeof(unsigned long long));
    cudaFuncSetAttribute(conv_mma_k,
                         cudaFuncAttributeMaxDynamicSharedMemorySize,
                         CONV_SMEM);

    // launches 0..4 precede conv_mma (ncu -s 5 -c 1 captures conv_mma)
    init_k<<<48, 256>>>();
    initb_k<<<48, 256>>>();
    const int XHALF_BLKS = (int)(((size_t)CIN * NPIX / 2 + 255) / 256);
    xsplit_k<<<XHALF_BLKS, 256>>>(features, 0);
    xsplit_k<<<XHALF_BLKS, 256>>>(features, 1);
    wsplit_k<<<(int)(((size_t)CIN * KTOT + 255) / 256), 256>>>(w1);

    dim3 gmma(NPXT, CIN / MTILE);   // 313 x 4
    conv_mma_k<<<gmma, 256, CONV_SMEM>>>(b1);

    conv1x1_k<<<(NPIX + PXT - 1) / PXT, 256>>>(wc, bc, wl, bl, out);

    decode_k<<<(NBOX + 255) / 256, 256>>>(anchor);

    hist_k<<<512, 256>>>(0, 24u, 0x00000000u);
    scan_k<<<1, 32>>>(0, 24u);
    hist_k<<<512, 256>>>(1, 16u, 0xFF000000u);
    scan_k<<<1, 32>>>(1, 16u);
    hist_k<<<512, 256>>>(2,  8u, 0xFFFF0000u);
    scan_k<<<1, 32>>>(2,  8u);
    hist_k<<<512, 256>>>(3,  0u, 0xFFFFFF00u);
    scan_k<<<1, 32>>>(3,  0u);

    count_k<<<NBLK, 256>>>();
    scanb_k<<<1, 256>>>();
    place_k<<<NBLK, 256>>>();
    tie_select_k<<<1, 32>>>();

    sort_topk_k<<<1, 1024, SORTN * sizeof(unsigned long long)>>>();

    mask_k<<<PRE_NMS, MASK_W>>>();

    nms_scan_k<<<1, 32>>>();

    write_rois_k<<<1, 256>>>(out);
}

// round 10
// speedup vs baseline: 1.5772x; 1.0990x over previous
#include <cuda_runtime.h>
#include <cuda_bf16.h>
#include <cuda_fp16.h>
#include <math.h>
#include <cstdint>

// ---------------- problem constants ----------------
#define HH 200
#define WW 200
#define NPIX (HH*WW)            // 40000
#define CIN 512
#define AA 9
#define NBOX (NPIX*AA)          // 360000
#define PRE_NMS 6000
#define POST_NMS 300
#define MIN_SIZE (16.0f/1000.0f)
#define IOU_THR 0.7f

#define CLS_OFF 0
#define LOC_OFF (NBOX*2)        // 720000
#define ROI_OFF (NBOX*2 + NBOX*4)  // 2160000

#define MASK_W 192
#define SORTN 8192
#define TIE_WORDS ((NBOX + 31) / 32)   // 11250
#define NBLK 1407               // ceil(NBOX/256)

// ---- implicit GEMM geometry (warp-level mma.sync, sm_80+ path) ----
#define KTOT (CIN*9)            // 4608
#define KC 32
#define NCHUNK (KTOT/KC)        // 144
#define DRAIN 2                 // drain accumulators every 2 chunks (RZ-bias fix)
#define MTILE 128
#define NTILE 128
#define NPXT ((NPIX + NTILE - 1)/NTILE)   // 313
#define PITCH 40                // fp16 elems per smem row (80 B) - conflict-free
#define SPLIT_B (128*PITCH*2)   // 10240 bytes per split tile
#define BS_OFF  (2*SPLIT_B)     // B tiles start after 2 A tiles
#define CONV_SMEM (4*SPLIT_B)   // 40960 bytes

// fp16 2-split scaling (exact powers of two; epilogue rescales by 2^-24)
#define XSCALE 1024.0f          // 2^10
#define WSCALE 16384.0f         // 2^14
#define OSCALE (1.0f/16777216.0f)  // 2^-24

// ---------------- scratch (device globals) ------------
__device__ float g_x[(size_t)CIN * NPIX];
__device__ __align__(16) __half g_ws[2][(size_t)CIN * KTOT];   // split weights [co][k]
__device__ __align__(16) __half g_xs[2][(size_t)CIN * NPIX];   // split features [ci][p]
__device__ float g_cls[(size_t)NBOX * 2];
__device__ float g_loc[(size_t)NBOX * 4];
__device__ __align__(16) float g_roi[(size_t)NBOX * 4];
__device__ unsigned g_key[NBOX];
__device__ unsigned g_hist[4 * 256];
__device__ unsigned g_state[2];
__device__ int g_cnt;
__device__ unsigned g_bcnt[NBLK + 1];
__device__ unsigned g_boff[NBLK + 1];
__device__ unsigned long long g_cand[SORTN];
__device__ unsigned g_tiebm[TIE_WORDS];
__device__ __align__(16) float g_nb[6144 * 4];
__device__ unsigned g_keep_init[MASK_W];
__device__ unsigned g_keep_fin[MASK_W];
__device__ unsigned g_mask[(size_t)PRE_NMS * MASK_W];

// ---------------- PTX helpers ----------------
__device__ __forceinline__ uint32_t smem_u32(const void* p) {
    uint32_t a;
    asm("{ .reg .u64 t; cvta.to.shared.u64 t, %1; cvt.u32.u64 %0, t; }" : "=r"(a) : "l"(p));
    return a;
}
__device__ __forceinline__ void ldsm_x4(unsigned* r, uint32_t addr) {
    asm volatile("ldmatrix.sync.aligned.m8n8.x4.shared.b16 {%0,%1,%2,%3}, [%4];"
        : "=r"(r[0]), "=r"(r[1]), "=r"(r[2]), "=r"(r[3]) : "r"(addr));
}
__device__ __forceinline__ void ldsm_x2(unsigned* r, uint32_t addr) {
    asm volatile("ldmatrix.sync.aligned.m8n8.x2.shared.b16 {%0,%1}, [%2];"
        : "=r"(r[0]), "=r"(r[1]) : "r"(addr));
}
__device__ __forceinline__ void mma16816h(float* d, const unsigned* a, const unsigned* b) {
    asm volatile(
        "mma.sync.aligned.m16n8k16.row.col.f32.f16.f16.f32 "
        "{%0,%1,%2,%3}, {%4,%5,%6,%7}, {%8,%9}, {%0,%1,%2,%3};"
        : "+f"(d[0]), "+f"(d[1]), "+f"(d[2]), "+f"(d[3])
        : "r"(a[0]), "r"(a[1]), "r"(a[2]), "r"(a[3]), "r"(b[0]), "r"(b[1]));
}

// ---------------- init ----------------
__global__ void init_k() {
    int t = blockIdx.x * 256 + threadIdx.x;
    const int STRIDE = 48 * 256;
    for (int i = t; i < 4 * 256; i += STRIDE) g_hist[i] = 0;
    for (int i = t; i < TIE_WORDS; i += STRIDE) g_tiebm[i] = 0;
    for (int i = t; i < SORTN; i += STRIDE) g_cand[i] = 0xFFFFFFFFFFFFFFFFull;
}
__global__ void initb_k() {
    int t = blockIdx.x * 256 + threadIdx.x;
    const int STRIDE = 48 * 256;
    for (int i = t; i < NBLK + 1; i += STRIDE) { g_bcnt[i] = 0; g_boff[i] = 0; }
    for (int i = t; i < MASK_W; i += STRIDE) { g_keep_init[i] = 0; g_keep_fin[i] = 0; }
    if (t == 0) { g_cnt = 0; g_state[0] = 0u; g_state[1] = PRE_NMS; }
}

// ---------------- fp32 -> 2x fp16 splits (pre-scaled, exact pow2) -----------
__device__ __forceinline__ void split2h(float v, float scale, __half& h0, __half& h1) {
    float vs = v * scale;                  // exact (power of 2)
    h0 = __float2half_rn(vs);
    h1 = __float2half_rn(vs - __half2float(h0));
}

__global__ __launch_bounds__(256) void xsplit_k(const float* __restrict__ f, int phase)
{
    const size_t HALF = (size_t)CIN * NPIX / 2;
    size_t n = (size_t)phase * HALF + blockIdx.x * 256 + threadIdx.x;
    if (n >= (size_t)(phase + 1) * HALF) return;
    __half a, b;
    split2h(f[n], XSCALE, a, b);
    g_xs[0][n] = a; g_xs[1][n] = b;
}

__global__ __launch_bounds__(256) void wsplit_k(const float* __restrict__ w1)
{
    size_t n = (size_t)blockIdx.x * 256 + threadIdx.x;
    if (n >= (size_t)CIN * KTOT) return;
    __half a, b;
    split2h(w1[n], WSCALE, a, b);
    g_ws[0][n] = a; g_ws[1][n] = b;
}

// ---------------- conv3x3 via mma.sync fp16x2 implicit GEMM ----------------
// CTA: 128co x 128px, 8 warps (warp tile 64x32), K chunks of 32.
// fp16 2-split, 3 products (w0x0 + w0x1 + w1x0); operands pre-scaled by
// 2^10/2^14, epilogue rescales by 2^-24 (exact). Register-pipelined staging.
// Accumulators drained every DRAIN chunks into fp32 masters (RZ-bias fix).
__global__ __launch_bounds__(256) void conv_mma_k(const float* __restrict__ b1)
{
    extern __shared__ __align__(16) char smem[];
    const uint32_t sb = smem_u32(smem);
    const int t = threadIdx.x;
    const int w = t >> 5, lane = t & 31;
    const int p0 = blockIdx.x * NTILE;
    const int co0 = blockIdx.y * MTILE;
    const int mw = (w & 1) * 64;      // warp co offset
    const int nw = (w >> 1) * 32;     // warp px offset

    float acc[4][4][4];    // mma working accumulators
    float accm[4][4][4];   // fp32 masters
#pragma unroll
    for (int mt = 0; mt < 4; mt++)
#pragma unroll
        for (int nt = 0; nt < 4; nt++)
#pragma unroll
            for (int e = 0; e < 4; e++) { acc[mt][nt][e] = 0.f; accm[mt][nt][e] = 0.f; }

    // staging roles
    const int arow = t >> 1, ahalf = t & 1;      // A: 2 thr/row, 16 fp16 each
    const int bpx = t & 127;                     // B: pixel owned
    const int bk0 = (t >> 7) * 16;               // B: first of 16 k-offsets
    const int bp = p0 + bpx;
    const int by = bp / 200, bx2 = bp - by * 200;
    const bool bok = bp < NPIX;

    // per-lane ldmatrix byte offsets
    const uint32_t a_lb = (uint32_t)(((lane & 7) + ((lane >> 3) & 1) * 8) * (PITCH * 2)
                                     + (lane >> 4) * 16);
    const uint32_t b_lb = (uint32_t)((lane & 7) * (PITCH * 2) + ((lane >> 3) & 1) * 16);

    // prefetch registers: A = 2 splits x 2 uint4; B = 2 splits x 8 packed u32
    uint4 aR[2][2];
    unsigned bR[2][8];

    auto prefetch = [&](int c) {
        const int k0g = c * KC;
#pragma unroll
        for (int s = 0; s < 2; s++) {
            const uint4* src = (const uint4*)&g_ws[s][(size_t)(co0 + arow) * KTOT
                                                     + k0g + ahalf * 16];
            aR[s][0] = src[0];
            aR[s][1] = src[1];
        }
#pragma unroll
        for (int e2 = 0; e2 < 8; e2++) {
            unsigned v[2][2];
#pragma unroll
            for (int h = 0; h < 2; h++) {
                int k = k0g + bk0 + e2 * 2 + h;
                int ci = (int)(((unsigned)k * 7282u) >> 16);    // k/9, k<4608
                int tap = k - 9 * ci;
                int t3 = (tap * 11) >> 5;                        // tap/3, tap<9
                int dy = t3 - 1, dx = tap - 3 * t3 - 1;
                int yy = by + dy, xx = bx2 + dx;
                bool ok = bok && ((unsigned)yy < (unsigned)HH) &&
                          ((unsigned)xx < (unsigned)WW);
                size_t off = (size_t)ci * NPIX + yy * WW + xx;   // shared by splits
#pragma unroll
                for (int s = 0; s < 2; s++)
                    v[s][h] = ok ? (unsigned)*(const unsigned short*)&g_xs[s][off] : 0u;
            }
#pragma unroll
            for (int s = 0; s < 2; s++)
                bR[s][e2] = v[s][0] | (v[s][1] << 16);
        }
    };

    auto store_stage = [&]() {
#pragma unroll
        for (int s = 0; s < 2; s++) {
            uint4* dst = (uint4*)(smem + s * SPLIT_B + arow * (PITCH * 2) + ahalf * 32);
            dst[0] = aR[s][0];
            dst[1] = aR[s][1];
        }
#pragma unroll
        for (int s = 0; s < 2; s++) {
            uint4* dst = (uint4*)(smem + BS_OFF + s * SPLIT_B
                                  + bpx * (PITCH * 2) + bk0 * 2);
            dst[0] = make_uint4(bR[s][0], bR[s][1], bR[s][2], bR[s][3]);
            dst[1] = make_uint4(bR[s][4], bR[s][5], bR[s][6], bR[s][7]);
        }
    };

    prefetch(0);

    for (int c = 0; c < NCHUNK; c++) {
        __syncthreads();    // previous compute done reading smem
        store_stage();
        __syncthreads();    // tile visible to all warps
        if (c + 1 < NCHUNK) prefetch(c + 1);   // LDGs hide under compute below

        // ---- compute: 2 k16 steps x 3 split-products
#pragma unroll
        for (int ks = 0; ks < 2; ks++) {
            const uint32_t koff = (uint32_t)(ks * 32);   // k16*2 bytes
            // A fragments for both splits (w0, w1)
            unsigned af0[4][4], af1[4][4];
#pragma unroll
            for (int mt = 0; mt < 4; mt++) {
                uint32_t abase = sb + (uint32_t)((mw + mt * 16) * (PITCH * 2)) + a_lb + koff;
                ldsm_x4(af0[mt], abase);
                ldsm_x4(af1[mt], abase + SPLIT_B);
            }
            // tt = 0 (x0): products w0*x0 and w1*x0
            {
                unsigned bf[4][2];
#pragma unroll
                for (int nt = 0; nt < 4; nt++)
                    ldsm_x2(bf[nt], sb + BS_OFF
                            + (uint32_t)((nw + nt * 8) * (PITCH * 2)) + b_lb + koff);
#pragma unroll
                for (int mt = 0; mt < 4; mt++)
#pragma unroll
                    for (int nt = 0; nt < 4; nt++) {
                        mma16816h(acc[mt][nt], af0[mt], bf[nt]);
                        mma16816h(acc[mt][nt], af1[mt], bf[nt]);
                    }
            }
            // tt = 1 (x1): product w0*x1
            {
                unsigned bf[4][2];
#pragma unroll
                for (int nt = 0; nt < 4; nt++)
                    ldsm_x2(bf[nt], sb + BS_OFF + SPLIT_B
                            + (uint32_t)((nw + nt * 8) * (PITCH * 2)) + b_lb + koff);
#pragma unroll
                for (int mt = 0; mt < 4; mt++)
#pragma unroll
                    for (int nt = 0; nt < 4; nt++)
                        mma16816h(acc[mt][nt], af0[mt], bf[nt]);
            }
        }

        // ---- drain working accumulators into fp32 masters (RN adds)
        if ((c % DRAIN) == (DRAIN - 1)) {
#pragma unroll
            for (int mt = 0; mt < 4; mt++)
#pragma unroll
                for (int nt = 0; nt < 4; nt++)
#pragma unroll
                    for (int e = 0; e < 4; e++) {
                        accm[mt][nt][e] += acc[mt][nt][e];
                        acc[mt][nt][e] = 0.f;
                    }
        }
    }

    // ---- epilogue: rescale (exact pow2) + bias + relu -> g_x
#pragma unroll
    for (int mt = 0; mt < 4; mt++) {
        int r0 = co0 + mw + mt * 16 + (lane >> 2);
        float bias0 = b1[r0], bias1 = b1[r0 + 8];
#pragma unroll
        for (int nt = 0; nt < 4; nt++) {
            int col = p0 + nw + nt * 8 + (lane & 3) * 2;
            if (col < NPIX) {
                float v0 = accm[mt][nt][0] * OSCALE + bias0;
                float v2 = accm[mt][nt][2] * OSCALE + bias1;
                g_x[(size_t)r0 * NPIX + col] = v0 > 0.f ? v0 : 0.f;
                g_x[(size_t)(r0 + 8) * NPIX + col] = v2 > 0.f ? v2 : 0.f;
            }
            if (col + 1 < NPIX) {
                float v1 = accm[mt][nt][1] * OSCALE + bias0;
                float v3 = accm[mt][nt][3] * OSCALE + bias1;
                g_x[(size_t)r0 * NPIX + col + 1] = v1 > 0.f ? v1 : 0.f;
                g_x[(size_t)(r0 + 8) * NPIX + col + 1] = v3 > 0.f ? v3 : 0.f;
            }
        }
    }
}

// ---------------- 1x1 heads (cls 18 + loc 36) ----------------
#define PXT 128
#define OC 64
#define CKB 16
__global__ __launch_bounds__(256) void conv1x1_k(
    const float* __restrict__ wc, const float* __restrict__ bc,
    const float* __restrict__ wl, const float* __restrict__ bl,
    float* __restrict__ out)
{
    __shared__ float s_x[CKB][PXT];
    __shared__ float s_w[OC][CKB];
    const int p0 = blockIdx.x * PXT;
    const int t = threadIdx.x;
    const int cg = t >> 4;
    const int pg = t & 15;

    float acc[4][8];
#pragma unroll
    for (int k = 0; k < 4; k++)
#pragma unroll
        for (int j = 0; j < 8; j++) acc[k][j] = 0.f;

    for (int cb = 0; cb < CIN; cb += CKB) {
        __syncthreads();
        for (int i = t; i < CKB * PXT; i += 256) {
            int ci = i >> 7, pp = i & 127;
            int p = p0 + pp;
            s_x[ci][pp] = (p < NPIX) ? g_x[(size_t)(cb + ci) * NPIX + p] : 0.f;
        }
        for (int i = t; i < OC * CKB; i += 256) {
            int co = i >> 4, ci = i & 15;
            float v = 0.f;
            if (co < 18) v = wc[(size_t)co * CIN + cb + ci];
            else if (co < 54) v = wl[(size_t)(co - 18) * CIN + cb + ci];
            s_w[co][ci] = v;
        }
        __syncthreads();
#pragma unroll 4
        for (int ci = 0; ci < CKB; ci++) {
            float xv[8];
#pragma unroll
            for (int j = 0; j < 8; j++) xv[j] = s_x[ci][pg * 8 + j];
#pragma unroll
            for (int k = 0; k < 4; k++) {
                float wv = s_w[cg * 4 + k][ci];
#pragma unroll
                for (int j = 0; j < 8; j++)
                    acc[k][j] = fmaf(wv, xv[j], acc[k][j]);
            }
        }
    }

#pragma unroll
    for (int k = 0; k < 4; k++) {
        int co = cg * 4 + k;
#pragma unroll
        for (int j = 0; j < 8; j++) {
            int p = p0 + pg * 8 + j;
            if (p < NPIX) {
                if (co < 18) {
                    float v = acc[k][j] + bc[co];
                    out[CLS_OFF + (size_t)p * 18 + co] = v;
                    g_cls[(size_t)p * 18 + co] = v;
                } else if (co < 54) {
                    float v = acc[k][j] + bl[co - 18];
                    out[LOC_OFF + (size_t)p * 36 + (co - 18)] = v;
                    g_loc[(size_t)p * 36 + (co - 18)] = v;
                }
            }
        }
    }
}

// ---------------- decode boxes + scores + sort keys ----------------
__global__ void decode_k(const float* __restrict__ anchor)
{
    int n = blockIdx.x * 256 + threadIdx.x;
    if (n >= NBOX) return;
    float a0 = anchor[(size_t)n * 4 + 0], a1 = anchor[(size_t)n * 4 + 1];
    float a2 = anchor[(size_t)n * 4 + 2], a3 = anchor[(size_t)n * 4 + 3];
    float aw = a2 - a0, ah = a3 - a1;
    float acx = (a0 + a2) * 0.5f, acy = (a1 + a3) * 0.5f;
    float l0 = g_loc[(size_t)n * 4 + 0];
    float l1 = g_loc[(size_t)n * 4 + 1];
    float l2 = g_loc[(size_t)n * 4 + 2];
    float l3 = g_loc[(size_t)n * 4 + 3];
    float cx = l0 * aw + acx, cy = l1 * ah + acy;
    float bw = expf(l2) * aw, bh = expf(l3) * ah;
    float x1 = fminf(fmaxf(cx - bw * 0.5f, 0.f), 1.f);
    float y1 = fminf(fmaxf(cy - bh * 0.5f, 0.f), 1.f);
    float x2 = fminf(fmaxf(cx + bw * 0.5f, 0.f), 1.f);
    float y2 = fminf(fmaxf(cy + bh * 0.5f, 0.f), 1.f);
    g_roi[(size_t)n * 4 + 0] = x1;
    g_roi[(size_t)n * 4 + 1] = y1;
    g_roi[(size_t)n * 4 + 2] = x2;
    g_roi[(size_t)n * 4 + 3] = y2;

    float c0 = g_cls[(size_t)n * 2 + 0];
    float c1 = g_cls[(size_t)n * 2 + 1];
    float s = 1.f / (1.f + expf(c0 - c1));
    bool valid = ((y2 - y1) >= MIN_SIZE) && ((x2 - x1) >= MIN_SIZE);
    float sc = valid ? s : -1.0f;

    unsigned b = __float_as_uint(sc);
    unsigned ord = (b & 0x80000000u) ? ~b : (b | 0x80000000u);
    g_key[n] = ~ord;
}

// ---------------- 4-pass MSD radix select ----------------
__global__ void hist_k(int pass, unsigned shift, unsigned pmask)
{
    __shared__ unsigned h[256];
    int t = threadIdx.x;
    for (int i = t; i < 256; i += 256) h[i] = 0;
    __syncthreads();
    unsigned prefix = g_state[0];
    for (int n = blockIdx.x * 256 + t; n < NBOX; n += gridDim.x * 256) {
        unsigned K = g_key[n];
        if ((K & pmask) == prefix) atomicAdd(&h[(K >> shift) & 255u], 1u);
    }
    __syncthreads();
    unsigned* hist = &g_hist[pass * 256];
    for (int i = t; i < 256; i += 256)
        if (h[i]) atomicAdd(&hist[i], h[i]);
}

__global__ void scan_k(int pass, unsigned shift)
{
    if (threadIdx.x == 0) {
        const unsigned* hist = &g_hist[pass * 256];
        unsigned k = g_state[1];
        unsigned cum = 0;
        int d = 0;
        for (; d < 256; d++) {
            if (cum + hist[d] >= k) break;
            cum += hist[d];
        }
        if (d > 255) d = 255;
        g_state[0] |= ((unsigned)d) << shift;
        g_state[1] = k - cum;
    }
}

// ---------------- deterministic compaction ------------
__global__ __launch_bounds__(256) void count_k()
{
    __shared__ unsigned wsum[8];
    int n = blockIdx.x * 256 + threadIdx.x;
    unsigned T = g_state[0];
    bool pred = (n < NBOX) && (g_key[n] < T);
    unsigned bal = __ballot_sync(0xFFFFFFFFu, pred);
    if ((threadIdx.x & 31) == 0) wsum[threadIdx.x >> 5] = (unsigned)__popc(bal);
    __syncthreads();
    if (threadIdx.x == 0) {
        unsigned s = 0;
#pragma unroll
        for (int w = 0; w < 8; w++) s += wsum[w];
        g_bcnt[blockIdx.x] = s;
    }
}

#define SCCH 6
__global__ __launch_bounds__(256) void scanb_k()
{
    __shared__ unsigned ssum[256];
    int t = threadIdx.x;
    unsigned loc[SCCH];
    unsigned s = 0;
#pragma unroll
    for (int e = 0; e < SCCH; e++) {
        int idx = t * SCCH + e;
        loc[e] = (idx < NBLK) ? g_bcnt[idx] : 0u;
        s += loc[e];
    }
    ssum[t] = s;
    __syncthreads();
    if (t == 0) {
        unsigned acc = 0;
        for (int i = 0; i < 256; i++) { unsigned tmp = ssum[i]; ssum[i] = acc; acc += tmp; }
        g_cnt = (int)acc;
    }
    __syncthreads();
    unsigned run = ssum[t];
#pragma unroll
    for (int e = 0; e < SCCH; e++) {
        int idx = t * SCCH + e;
        if (idx < NBLK) g_boff[idx] = run;
        run += loc[e];
    }
}

__global__ __launch_bounds__(256) void place_k()
{
    __shared__ unsigned wcnt[8];
    __shared__ unsigned wex[8];
    int t = threadIdx.x;
    int n = blockIdx.x * 256 + t;
    unsigned T = g_state[0];
    unsigned K = (n < NBOX) ? g_key[n] : 0xFFFFFFFFu;
    bool pred = (n < NBOX) && (K < T);
    unsigned bal = __ballot_sync(0xFFFFFFFFu, pred);
    int lane = t & 31, w = t >> 5;
    if (lane == 0) wcnt[w] = (unsigned)__popc(bal);
    __syncthreads();
    if (t == 0) {
        unsigned a = 0;
#pragma unroll
        for (int i = 0; i < 8; i++) { wex[i] = a; a += wcnt[i]; }
    }
    __syncthreads();
    if (pred) {
        unsigned rank = g_boff[blockIdx.x] + wex[w] +
                        (unsigned)__popc(bal & ((1u << lane) - 1u));
        g_cand[rank] = ((unsigned long long)K << 32) | (unsigned)n;
    }
    if ((n < NBOX) && (K == T))
        atomicOr(&g_tiebm[n >> 5], 1u << (n & 31));
}

__global__ void tie_select_k()
{
    const int lane = threadIdx.x;
    const int base = g_cnt;
    const unsigned r = g_state[1];
    const unsigned T = g_state[0];
    unsigned taken = 0;
    for (int w0 = 0; w0 < TIE_WORDS && taken < r; w0 += 32) {
        int wi = w0 + lane;
        unsigned word = (wi < TIE_WORDS) ? g_tiebm[wi] : 0u;
        int cnt = __popc(word);
        int pre = cnt;
#pragma unroll
        for (int o = 1; o < 32; o <<= 1) {
            int v = __shfl_up_sync(0xFFFFFFFFu, pre, o);
            if (lane >= o) pre += v;
        }
        unsigned rank = taken + (unsigned)(pre - cnt);
        while (word && rank < r) {
            int b = __ffs(word) - 1;
            word &= word - 1;
            unsigned n = (unsigned)wi * 32u + (unsigned)b;
            g_cand[base + rank] = ((unsigned long long)T << 32) | n;
            rank++;
        }
        taken += (unsigned)__shfl_sync(0xFFFFFFFFu, pre, 31);
    }
}

// ---------------- single-block bitonic sort + gather ----------
extern __shared__ unsigned long long s_sort[];
__global__ void sort_topk_k()
{
    const int t = threadIdx.x;
    for (int i = t; i < SORTN; i += 1024)
        s_sort[i] = (i < PRE_NMS) ? g_cand[i] : 0xFFFFFFFFFFFFFFFFull;
    __syncthreads();
    for (int k = 2; k <= SORTN; k <<= 1) {
        for (int j = k >> 1; j > 0; j >>= 1) {
            for (int i = t; i < SORTN; i += 1024) {
                int ixj = i ^ j;
                if (ixj > i) {
                    unsigned long long a = s_sort[i], b = s_sort[ixj];
                    bool up = ((i & k) == 0);
                    if ((a > b) == up) { s_sort[i] = b; s_sort[ixj] = a; }
                }
            }
            __syncthreads();
        }
    }
    for (int i = t; i < 6144; i += 1024) {
        bool valid = false;
        if (i < PRE_NMS) {
            unsigned long long v = s_sort[i];
            unsigned K = (unsigned)(v >> 32);
            unsigned n = (unsigned)v;
            float b0 = 0, b1 = 0, b2 = 0, b3 = 0;
            if (n < (unsigned)NBOX) {
                const float4 bb = *reinterpret_cast<const float4*>(&g_roi[(size_t)n * 4]);
                b0 = bb.x; b1 = bb.y; b2 = bb.z; b3 = bb.w;
                valid = (K < 0x80000000u);
            }
            g_nb[(size_t)i * 4 + 0] = b0;
            g_nb[(size_t)i * 4 + 1] = b1;
            g_nb[(size_t)i * 4 + 2] = b2;
            g_nb[(size_t)i * 4 + 3] = b3;
        }
        unsigned bal = __ballot_sync(0xFFFFFFFFu, valid);
        if ((t & 31) == 0) g_keep_init[i >> 5] = bal;
    }
}

// ---------------- NMS suppression bitmask ----------------
__global__ __launch_bounds__(MASK_W) void mask_k()
{
    const int i = blockIdx.x;
    const int w = threadIdx.x;
    const float4* nb4 = reinterpret_cast<const float4*>(g_nb);
    float4 bi = nb4[i];
    float ai = (bi.z - bi.x) * (bi.w - bi.y);
    unsigned bits = 0;
    int jbase = w * 32;
#pragma unroll 4
    for (int b = 0; b < 32; b++) {
        int j = jbase + b;
        if (j > i && j < PRE_NMS) {
            float4 bj = nb4[j];
            float xx1 = fmaxf(bi.x, bj.x), yy1 = fmaxf(bi.y, bj.y);
            float xx2 = fminf(bi.z, bj.z), yy2 = fminf(bi.w, bj.w);
            float inter = fmaxf(xx2 - xx1, 0.f) * fmaxf(yy2 - yy1, 0.f);
            float aj = (bj.z - bj.x) * (bj.w - bj.y);
            float iou = inter / (ai + aj - inter + 1e-12f);
            if (iou > IOU_THR) bits |= (1u << b);
        }
    }
    g_mask[(size_t)i * MASK_W + w] = bits;
}

// ---------------- sequential greedy scan (single warp) ----------------
__global__ void nms_scan_k()
{
    const int lane = threadIdx.x;
    unsigned kw[6];
#pragma unroll
    for (int q = 0; q < 6; q++) kw[q] = g_keep_init[q * 32 + lane];

#pragma unroll
    for (int q = 0; q < 6; q++) {
        const int iend = (q == 5) ? (PRE_NMS - 5 * 1024) : 1024;
        for (int ii = 0; ii < iend; ii++) {
            int i = q * 1024 + ii;
            unsigned word = __shfl_sync(0xFFFFFFFFu, kw[q], (i >> 5) & 31);
            if ((word >> (i & 31)) & 1u) {
                const unsigned* row = &g_mask[(size_t)i * MASK_W];
#pragma unroll
                for (int r = 0; r < 6; r++) kw[r] &= ~row[r * 32 + lane];
            }
        }
    }
#pragma unroll
    for (int q = 0; q < 6; q++) g_keep_fin[q * 32 + lane] = kw[q];
}

// ---------------- write rois ----------------
__global__ __launch_bounds__(256) void write_rois_k(float* __restrict__ out)
{
    float* rois = out + ROI_OFF;
    __shared__ unsigned woff[MASK_W];
    int t = threadIdx.x;
    for (int i = t; i < POST_NMS * 4; i += 256) rois[i] = 0.f;
    if (t < MASK_W) woff[t] = (unsigned)__popc(g_keep_fin[t]);
    __syncthreads();
    if (t == 0) {
        unsigned acc = 0;
        for (int i = 0; i < MASK_W; i++) { unsigned tmp = woff[i]; woff[i] = acc; acc += tmp; }
    }
    __syncthreads();
    if (t < MASK_W) {
        unsigned word = g_keep_fin[t];
        unsigned rank = woff[t];
        while (word) {
            int b = __ffs(word) - 1;
            word &= word - 1;
            if (rank < POST_NMS) {
                int i = t * 32 + b;
                rois[rank * 4 + 0] = g_nb[(size_t)i * 4 + 0];
                rois[rank * 4 + 1] = g_nb[(size_t)i * 4 + 1];
                rois[rank * 4 + 2] = g_nb[(size_t)i * 4 + 2];
                rois[rank * 4 + 3] = g_nb[(size_t)i * 4 + 3];
            }
            rank++;
        }
    }
}

// ---------------- launcher ----------------
extern "C" void kernel_launch(void* const* d_in, const int* in_sizes, int n_in,
                              void* d_out, int out_size)
{
    const float* features = (const float*)d_in[0];
    const float* anchor   = (const float*)d_in[1];
    const float* w1       = (const float*)d_in[2];
    const float* b1       = (const float*)d_in[3];
    const float* wc       = (const float*)d_in[4];
    const float* bc       = (const float*)d_in[5];
    const float* wl       = (const float*)d_in[6];
    const float* bl       = (const float*)d_in[7];
    float* out = (float*)d_out;

    cudaFuncSetAttribute(sort_topk_k,
                         cudaFuncAttributeMaxDynamicSharedMemorySize,
                         SORTN * sizeof(unsigned long long));
    cudaFuncSetAttribute(conv_mma_k,
                         cudaFuncAttributeMaxDynamicSharedMemorySize,
                         CONV_SMEM);

    init_k<<<48, 256>>>();
    initb_k<<<48, 256>>>();
    const int XHALF_BLKS = (int)(((size_t)CIN * NPIX / 2 + 255) / 256);
    xsplit_k<<<XHALF_BLKS, 256>>>(features, 0);
    xsplit_k<<<XHALF_BLKS, 256>>>(features, 1);
    wsplit_k<<<(int)(((size_t)CIN * KTOT + 255) / 256), 256>>>(w1);

    dim3 gmma(NPXT, CIN / MTILE);   // 313 x 4
    conv_mma_k<<<gmma, 256, CONV_SMEM>>>(b1);

    conv1x1_k<<<(NPIX + PXT - 1) / PXT, 256>>>(wc, bc, wl, bl, out);

    decode_k<<<(NBOX + 255) / 256, 256>>>(anchor);

    hist_k<<<512, 256>>>(0, 24u, 0x00000000u);
    scan_k<<<1, 32>>>(0, 24u);
    hist_k<<<512, 256>>>(1, 16u, 0xFF000000u);
    scan_k<<<1, 32>>>(1, 16u);
    hist_k<<<512, 256>>>(2,  8u, 0xFFFF0000u);
    scan_k<<<1, 32>>>(2,  8u);
    hist_k<<<512, 256>>>(3,  0u, 0xFFFFFF00u);
    scan_k<<<1, 32>>>(3,  0u);

    count_k<<<NBLK, 256>>>();
    scanb_k<<<1, 256>>>();
    place_k<<<NBLK, 256>>>();
    tie_select_k<<<1, 32>>>();

    sort_topk_k<<<1, 1024, SORTN * sizeof(unsigned long long)>>>();

    mask_k<<<PRE_NMS, MASK_W>>>();

    nms_scan_k<<<1, 32>>>();

    write_rois_k<<<1, 256>>>(out);
}

// round 11
// speedup vs baseline: 1.9320x; 1.2250x over previous
#include <cuda_runtime.h>
#include <cuda_bf16.h>
#include <cuda_fp16.h>
#include <math.h>
#include <cstdint>

// ---------------- problem constants ----------------
#define HH 200
#define WW 200
#define NPIX (HH*WW)            // 40000
#define CIN 512
#define AA 9
#define NBOX (NPIX*AA)          // 360000
#define PRE_NMS 6000
#define POST_NMS 300
#define MIN_SIZE (16.0f/1000.0f)
#define IOU_THR 0.7f

#define CLS_OFF 0
#define LOC_OFF (NBOX*2)        // 720000
#define ROI_OFF (NBOX*2 + NBOX*4)  // 2160000

#define MASK_W 192
#define SORTN 8192
#define TIE_WORDS ((NBOX + 31) / 32)   // 11250
#define NBLK 1407               // ceil(NBOX/256)

// ---- implicit GEMM geometry (warp-level mma.sync, sm_80+ path) ----
#define KTOT (CIN*9)            // 4608
#define KC 32
#define NCHUNK (KTOT/KC)        // 144
#define DRAIN 2                 // drain accumulators every 2 chunks (RZ-bias fix)
#define MTILE 128
#define NTILE 128
#define NPXT ((NPIX + NTILE - 1)/NTILE)   // 313
#define PITCH 40                // fp16 elems per smem row (80 B) - conflict-free
#define SPLIT_B (128*PITCH*2)   // 10240 bytes per split tile
#define BS_OFF  (2*SPLIT_B)     // B tiles start after 2 A tiles
#define CONV_SMEM (4*SPLIT_B)   // 40960 bytes

// fp16 2-split scaling (exact powers of two; epilogue rescales by 2^-24)
#define XSCALE 1024.0f          // 2^10
#define WSCALE 16384.0f         // 2^14
#define OSCALE (1.0f/16777216.0f)  // 2^-24

// ---------------- scratch (device globals) ------------
__device__ float g_x[(size_t)CIN * NPIX];
__device__ __align__(16) __half g_ws[2][(size_t)CIN * KTOT];   // split weights [co][k]
__device__ __align__(16) __half g_xs[2][(size_t)CIN * NPIX];   // split features [ci][p]
__device__ float g_cls[(size_t)NBOX * 2];
__device__ float g_loc[(size_t)NBOX * 4];
__device__ __align__(16) float g_roi[(size_t)NBOX * 4];
__device__ unsigned g_key[NBOX];
__device__ unsigned g_hist[4 * 256];
__device__ unsigned g_state[2];
__device__ int g_cnt;
__device__ unsigned g_bcnt[NBLK + 1];
__device__ unsigned g_boff[NBLK + 1];
__device__ unsigned long long g_cand[SORTN];
__device__ unsigned g_tiebm[TIE_WORDS];
__device__ __align__(16) float g_nb[6144 * 4];
__device__ unsigned g_keep_init[MASK_W];
__device__ unsigned g_keep_fin[MASK_W];
__device__ unsigned g_mask[(size_t)PRE_NMS * MASK_W];

// ---------------- PTX helpers ----------------
__device__ __forceinline__ uint32_t smem_u32(const void* p) {
    uint32_t a;
    asm("{ .reg .u64 t; cvta.to.shared.u64 t, %1; cvt.u32.u64 %0, t; }" : "=r"(a) : "l"(p));
    return a;
}
__device__ __forceinline__ void ldsm_x4(unsigned* r, uint32_t addr) {
    asm volatile("ldmatrix.sync.aligned.m8n8.x4.shared.b16 {%0,%1,%2,%3}, [%4];"
        : "=r"(r[0]), "=r"(r[1]), "=r"(r[2]), "=r"(r[3]) : "r"(addr));
}
__device__ __forceinline__ void ldsm_x2(unsigned* r, uint32_t addr) {
    asm volatile("ldmatrix.sync.aligned.m8n8.x2.shared.b16 {%0,%1}, [%2];"
        : "=r"(r[0]), "=r"(r[1]) : "r"(addr));
}
__device__ __forceinline__ void mma16816h(float* d, const unsigned* a, const unsigned* b) {
    asm volatile(
        "mma.sync.aligned.m16n8k16.row.col.f32.f16.f16.f32 "
        "{%0,%1,%2,%3}, {%4,%5,%6,%7}, {%8,%9}, {%0,%1,%2,%3};"
        : "+f"(d[0]), "+f"(d[1]), "+f"(d[2]), "+f"(d[3])
        : "r"(a[0]), "r"(a[1]), "r"(a[2]), "r"(a[3]), "r"(b[0]), "r"(b[1]));
}

// ---------------- init ----------------
__global__ void init_k() {
    int t = blockIdx.x * 256 + threadIdx.x;
    const int STRIDE = 48 * 256;
    for (int i = t; i < 4 * 256; i += STRIDE) g_hist[i] = 0;
    for (int i = t; i < TIE_WORDS; i += STRIDE) g_tiebm[i] = 0;
    for (int i = t; i < SORTN; i += STRIDE) g_cand[i] = 0xFFFFFFFFFFFFFFFFull;
}
__global__ void initb_k() {
    int t = blockIdx.x * 256 + threadIdx.x;
    const int STRIDE = 48 * 256;
    for (int i = t; i < NBLK + 1; i += STRIDE) { g_bcnt[i] = 0; g_boff[i] = 0; }
    for (int i = t; i < MASK_W; i += STRIDE) { g_keep_init[i] = 0; g_keep_fin[i] = 0; }
    if (t == 0) { g_cnt = 0; g_state[0] = 0u; g_state[1] = PRE_NMS; }
}

// ---------------- fp32 -> 2x fp16 splits (pre-scaled, exact pow2) -----------
__device__ __forceinline__ void split2h(float v, float scale, __half& h0, __half& h1) {
    float vs = v * scale;                  // exact (power of 2)
    h0 = __float2half_rn(vs);
    h1 = __float2half_rn(vs - __half2float(h0));
}

__global__ __launch_bounds__(256) void xsplit_k(const float* __restrict__ f, int phase)
{
    const size_t HALF = (size_t)CIN * NPIX / 2;
    size_t n = (size_t)phase * HALF + blockIdx.x * 256 + threadIdx.x;
    if (n >= (size_t)(phase + 1) * HALF) return;
    __half a, b;
    split2h(f[n], XSCALE, a, b);
    g_xs[0][n] = a; g_xs[1][n] = b;
}

__global__ __launch_bounds__(256) void wsplit_k(const float* __restrict__ w1)
{
    size_t n = (size_t)blockIdx.x * 256 + threadIdx.x;
    if (n >= (size_t)CIN * KTOT) return;
    __half a, b;
    split2h(w1[n], WSCALE, a, b);
    g_ws[0][n] = a; g_ws[1][n] = b;
}

// ---------------- conv3x3 via mma.sync fp16x2 implicit GEMM ----------------
// CTA: 128co x 128px, 8 warps (warp tile 64x32), K chunks of 32.
// fp16 2-split, 3 products (w0x0 + w0x1 + w1x0); operands pre-scaled by
// 2^10/2^14, epilogue rescales by 2^-24 (exact). Register-pipelined staging.
// Accumulators drained every DRAIN chunks into fp32 masters (RZ-bias fix).
__global__ __launch_bounds__(256) void conv_mma_k(const float* __restrict__ b1)
{
    extern __shared__ __align__(16) char smem[];
    const uint32_t sb = smem_u32(smem);
    const int t = threadIdx.x;
    const int w = t >> 5, lane = t & 31;
    const int p0 = blockIdx.x * NTILE;
    const int co0 = blockIdx.y * MTILE;
    const int mw = (w & 1) * 64;      // warp co offset
    const int nw = (w >> 1) * 32;     // warp px offset

    float acc[4][4][4];    // mma working accumulators
    float accm[4][4][4];   // fp32 masters
#pragma unroll
    for (int mt = 0; mt < 4; mt++)
#pragma unroll
        for (int nt = 0; nt < 4; nt++)
#pragma unroll
            for (int e = 0; e < 4; e++) { acc[mt][nt][e] = 0.f; accm[mt][nt][e] = 0.f; }

    // staging roles
    const int arow = t >> 1, ahalf = t & 1;      // A: 2 thr/row, 16 fp16 each
    const int bpx = t & 127;                     // B: pixel owned
    const int bk0 = (t >> 7) * 16;               // B: first of 16 k-offsets
    const int bp = p0 + bpx;
    const int by = bp / 200, bx2 = bp - by * 200;
    const bool bok = bp < NPIX;

    // per-lane ldmatrix byte offsets
    const uint32_t a_lb = (uint32_t)(((lane & 7) + ((lane >> 3) & 1) * 8) * (PITCH * 2)
                                     + (lane >> 4) * 16);
    const uint32_t b_lb = (uint32_t)((lane & 7) * (PITCH * 2) + ((lane >> 3) & 1) * 16);

    // prefetch registers: A = 2 splits x 2 uint4; B = 2 splits x 8 packed u32
    uint4 aR[2][2];
    unsigned bR[2][8];

    auto prefetch = [&](int c) {
        const int k0g = c * KC;
#pragma unroll
        for (int s = 0; s < 2; s++) {
            const uint4* src = (const uint4*)&g_ws[s][(size_t)(co0 + arow) * KTOT
                                                     + k0g + ahalf * 16];
            aR[s][0] = src[0];
            aR[s][1] = src[1];
        }
#pragma unroll
        for (int e2 = 0; e2 < 8; e2++) {
            unsigned v[2][2];
#pragma unroll
            for (int h = 0; h < 2; h++) {
                int k = k0g + bk0 + e2 * 2 + h;
                int ci = (int)(((unsigned)k * 7282u) >> 16);    // k/9, k<4608
                int tap = k - 9 * ci;
                int t3 = (tap * 11) >> 5;                        // tap/3, tap<9
                int dy = t3 - 1, dx = tap - 3 * t3 - 1;
                int yy = by + dy, xx = bx2 + dx;
                bool ok = bok && ((unsigned)yy < (unsigned)HH) &&
                          ((unsigned)xx < (unsigned)WW);
                size_t off = (size_t)ci * NPIX + yy * WW + xx;   // shared by splits
#pragma unroll
                for (int s = 0; s < 2; s++)
                    v[s][h] = ok ? (unsigned)*(const unsigned short*)&g_xs[s][off] : 0u;
            }
#pragma unroll
            for (int s = 0; s < 2; s++)
                bR[s][e2] = v[s][0] | (v[s][1] << 16);
        }
    };

    auto store_stage = [&]() {
#pragma unroll
        for (int s = 0; s < 2; s++) {
            uint4* dst = (uint4*)(smem + s * SPLIT_B + arow * (PITCH * 2) + ahalf * 32);
            dst[0] = aR[s][0];
            dst[1] = aR[s][1];
        }
#pragma unroll
        for (int s = 0; s < 2; s++) {
            uint4* dst = (uint4*)(smem + BS_OFF + s * SPLIT_B
                                  + bpx * (PITCH * 2) + bk0 * 2);
            dst[0] = make_uint4(bR[s][0], bR[s][1], bR[s][2], bR[s][3]);
            dst[1] = make_uint4(bR[s][4], bR[s][5], bR[s][6], bR[s][7]);
        }
    };

    prefetch(0);

    for (int c = 0; c < NCHUNK; c++) {
        __syncthreads();    // previous compute done reading smem
        store_stage();
        __syncthreads();    // tile visible to all warps
        if (c + 1 < NCHUNK) prefetch(c + 1);   // LDGs hide under compute below

        // ---- compute: 2 k16 steps x 3 split-products
#pragma unroll
        for (int ks = 0; ks < 2; ks++) {
            const uint32_t koff = (uint32_t)(ks * 32);   // k16*2 bytes
            // A fragments for both splits (w0, w1)
            unsigned af0[4][4], af1[4][4];
#pragma unroll
            for (int mt = 0; mt < 4; mt++) {
                uint32_t abase = sb + (uint32_t)((mw + mt * 16) * (PITCH * 2)) + a_lb + koff;
                ldsm_x4(af0[mt], abase);
                ldsm_x4(af1[mt], abase + SPLIT_B);
            }
            // tt = 0 (x0): products w0*x0 and w1*x0
            {
                unsigned bf[4][2];
#pragma unroll
                for (int nt = 0; nt < 4; nt++)
                    ldsm_x2(bf[nt], sb + BS_OFF
                            + (uint32_t)((nw + nt * 8) * (PITCH * 2)) + b_lb + koff);
#pragma unroll
                for (int mt = 0; mt < 4; mt++)
#pragma unroll
                    for (int nt = 0; nt < 4; nt++) {
                        mma16816h(acc[mt][nt], af0[mt], bf[nt]);
                        mma16816h(acc[mt][nt], af1[mt], bf[nt]);
                    }
            }
            // tt = 1 (x1): product w0*x1
            {
                unsigned bf[4][2];
#pragma unroll
                for (int nt = 0; nt < 4; nt++)
                    ldsm_x2(bf[nt], sb + BS_OFF + SPLIT_B
                            + (uint32_t)((nw + nt * 8) * (PITCH * 2)) + b_lb + koff);
#pragma unroll
                for (int mt = 0; mt < 4; mt++)
#pragma unroll
                    for (int nt = 0; nt < 4; nt++)
                        mma16816h(acc[mt][nt], af0[mt], bf[nt]);
            }
        }

        // ---- drain working accumulators into fp32 masters (RN adds)
        if ((c % DRAIN) == (DRAIN - 1)) {
#pragma unroll
            for (int mt = 0; mt < 4; mt++)
#pragma unroll
                for (int nt = 0; nt < 4; nt++)
#pragma unroll
                    for (int e = 0; e < 4; e++) {
                        accm[mt][nt][e] += acc[mt][nt][e];
                        acc[mt][nt][e] = 0.f;
                    }
        }
    }

    // ---- epilogue: rescale (exact pow2) + bias + relu -> g_x
#pragma unroll
    for (int mt = 0; mt < 4; mt++) {
        int r0 = co0 + mw + mt * 16 + (lane >> 2);
        float bias0 = b1[r0], bias1 = b1[r0 + 8];
#pragma unroll
        for (int nt = 0; nt < 4; nt++) {
            int col = p0 + nw + nt * 8 + (lane & 3) * 2;
            if (col < NPIX) {
                float v0 = accm[mt][nt][0] * OSCALE + bias0;
                float v2 = accm[mt][nt][2] * OSCALE + bias1;
                g_x[(size_t)r0 * NPIX + col] = v0 > 0.f ? v0 : 0.f;
                g_x[(size_t)(r0 + 8) * NPIX + col] = v2 > 0.f ? v2 : 0.f;
            }
            if (col + 1 < NPIX) {
                float v1 = accm[mt][nt][1] * OSCALE + bias0;
                float v3 = accm[mt][nt][3] * OSCALE + bias1;
                g_x[(size_t)r0 * NPIX + col + 1] = v1 > 0.f ? v1 : 0.f;
                g_x[(size_t)(r0 + 8) * NPIX + col + 1] = v3 > 0.f ? v3 : 0.f;
            }
        }
    }
}

// ---------------- 1x1 heads (cls 18 + loc 36) ----------------
#define PXT 128
#define OC 64
#define CKB 16
__global__ __launch_bounds__(256) void conv1x1_k(
    const float* __restrict__ wc, const float* __restrict__ bc,
    const float* __restrict__ wl, const float* __restrict__ bl,
    float* __restrict__ out)
{
    __shared__ float s_x[CKB][PXT];
    __shared__ float s_w[OC][CKB];
    const int p0 = blockIdx.x * PXT;
    const int t = threadIdx.x;
    const int cg = t >> 4;
    const int pg = t & 15;

    float acc[4][8];
#pragma unroll
    for (int k = 0; k < 4; k++)
#pragma unroll
        for (int j = 0; j < 8; j++) acc[k][j] = 0.f;

    for (int cb = 0; cb < CIN; cb += CKB) {
        __syncthreads();
        for (int i = t; i < CKB * PXT; i += 256) {
            int ci = i >> 7, pp = i & 127;
            int p = p0 + pp;
            s_x[ci][pp] = (p < NPIX) ? g_x[(size_t)(cb + ci) * NPIX + p] : 0.f;
        }
        for (int i = t; i < OC * CKB; i += 256) {
            int co = i >> 4, ci = i & 15;
            float v = 0.f;
            if (co < 18) v = wc[(size_t)co * CIN + cb + ci];
            else if (co < 54) v = wl[(size_t)(co - 18) * CIN + cb + ci];
            s_w[co][ci] = v;
        }
        __syncthreads();
#pragma unroll 4
        for (int ci = 0; ci < CKB; ci++) {
            float xv[8];
#pragma unroll
            for (int j = 0; j < 8; j++) xv[j] = s_x[ci][pg * 8 + j];
#pragma unroll
            for (int k = 0; k < 4; k++) {
                float wv = s_w[cg * 4 + k][ci];
#pragma unroll
                for (int j = 0; j < 8; j++)
                    acc[k][j] = fmaf(wv, xv[j], acc[k][j]);
            }
        }
    }

#pragma unroll
    for (int k = 0; k < 4; k++) {
        int co = cg * 4 + k;
#pragma unroll
        for (int j = 0; j < 8; j++) {
            int p = p0 + pg * 8 + j;
            if (p < NPIX) {
                if (co < 18) {
                    float v = acc[k][j] + bc[co];
                    out[CLS_OFF + (size_t)p * 18 + co] = v;
                    g_cls[(size_t)p * 18 + co] = v;
                } else if (co < 54) {
                    float v = acc[k][j] + bl[co - 18];
                    out[LOC_OFF + (size_t)p * 36 + (co - 18)] = v;
                    g_loc[(size_t)p * 36 + (co - 18)] = v;
                }
            }
        }
    }
}

// ---------------- decode boxes + scores + sort keys ----------------
__global__ void decode_k(const float* __restrict__ anchor)
{
    int n = blockIdx.x * 256 + threadIdx.x;
    if (n >= NBOX) return;
    float a0 = anchor[(size_t)n * 4 + 0], a1 = anchor[(size_t)n * 4 + 1];
    float a2 = anchor[(size_t)n * 4 + 2], a3 = anchor[(size_t)n * 4 + 3];
    float aw = a2 - a0, ah = a3 - a1;
    float acx = (a0 + a2) * 0.5f, acy = (a1 + a3) * 0.5f;
    float l0 = g_loc[(size_t)n * 4 + 0];
    float l1 = g_loc[(size_t)n * 4 + 1];
    float l2 = g_loc[(size_t)n * 4 + 2];
    float l3 = g_loc[(size_t)n * 4 + 3];
    float cx = l0 * aw + acx, cy = l1 * ah + acy;
    float bw = expf(l2) * aw, bh = expf(l3) * ah;
    float x1 = fminf(fmaxf(cx - bw * 0.5f, 0.f), 1.f);
    float y1 = fminf(fmaxf(cy - bh * 0.5f, 0.f), 1.f);
    float x2 = fminf(fmaxf(cx + bw * 0.5f, 0.f), 1.f);
    float y2 = fminf(fmaxf(cy + bh * 0.5f, 0.f), 1.f);
    g_roi[(size_t)n * 4 + 0] = x1;
    g_roi[(size_t)n * 4 + 1] = y1;
    g_roi[(size_t)n * 4 + 2] = x2;
    g_roi[(size_t)n * 4 + 3] = y2;

    float c0 = g_cls[(size_t)n * 2 + 0];
    float c1 = g_cls[(size_t)n * 2 + 1];
    float s = 1.f / (1.f + expf(c0 - c1));
    bool valid = ((y2 - y1) >= MIN_SIZE) && ((x2 - x1) >= MIN_SIZE);
    float sc = valid ? s : -1.0f;

    unsigned b = __float_as_uint(sc);
    unsigned ord = (b & 0x80000000u) ? ~b : (b | 0x80000000u);
    g_key[n] = ~ord;
}

// ---------------- 4-pass MSD radix select ----------------
__global__ void hist_k(int pass, unsigned shift, unsigned pmask)
{
    __shared__ unsigned h[256];
    int t = threadIdx.x;
    for (int i = t; i < 256; i += 256) h[i] = 0;
    __syncthreads();
    unsigned prefix = g_state[0];
    for (int n = blockIdx.x * 256 + t; n < NBOX; n += gridDim.x * 256) {
        unsigned K = g_key[n];
        if ((K & pmask) == prefix) atomicAdd(&h[(K >> shift) & 255u], 1u);
    }
    __syncthreads();
    unsigned* hist = &g_hist[pass * 256];
    for (int i = t; i < 256; i += 256)
        if (h[i]) atomicAdd(&hist[i], h[i]);
}

__global__ void scan_k(int pass, unsigned shift)
{
    if (threadIdx.x == 0) {
        const unsigned* hist = &g_hist[pass * 256];
        unsigned k = g_state[1];
        unsigned cum = 0;
        int d = 0;
        for (; d < 256; d++) {
            if (cum + hist[d] >= k) break;
            cum += hist[d];
        }
        if (d > 255) d = 255;
        g_state[0] |= ((unsigned)d) << shift;
        g_state[1] = k - cum;
    }
}

// ---------------- deterministic compaction ------------
__global__ __launch_bounds__(256) void count_k()
{
    __shared__ unsigned wsum[8];
    int n = blockIdx.x * 256 + threadIdx.x;
    unsigned T = g_state[0];
    bool pred = (n < NBOX) && (g_key[n] < T);
    unsigned bal = __ballot_sync(0xFFFFFFFFu, pred);
    if ((threadIdx.x & 31) == 0) wsum[threadIdx.x >> 5] = (unsigned)__popc(bal);
    __syncthreads();
    if (threadIdx.x == 0) {
        unsigned s = 0;
#pragma unroll
        for (int w = 0; w < 8; w++) s += wsum[w];
        g_bcnt[blockIdx.x] = s;
    }
}

#define SCCH 6
__global__ __launch_bounds__(256) void scanb_k()
{
    __shared__ unsigned ssum[256];
    int t = threadIdx.x;
    unsigned loc[SCCH];
    unsigned s = 0;
#pragma unroll
    for (int e = 0; e < SCCH; e++) {
        int idx = t * SCCH + e;
        loc[e] = (idx < NBLK) ? g_bcnt[idx] : 0u;
        s += loc[e];
    }
    ssum[t] = s;
    __syncthreads();
    if (t == 0) {
        unsigned acc = 0;
        for (int i = 0; i < 256; i++) { unsigned tmp = ssum[i]; ssum[i] = acc; acc += tmp; }
        g_cnt = (int)acc;
    }
    __syncthreads();
    unsigned run = ssum[t];
#pragma unroll
    for (int e = 0; e < SCCH; e++) {
        int idx = t * SCCH + e;
        if (idx < NBLK) g_boff[idx] = run;
        run += loc[e];
    }
}

__global__ __launch_bounds__(256) void place_k()
{
    __shared__ unsigned wcnt[8];
    __shared__ unsigned wex[8];
    int t = threadIdx.x;
    int n = blockIdx.x * 256 + t;
    unsigned T = g_state[0];
    unsigned K = (n < NBOX) ? g_key[n] : 0xFFFFFFFFu;
    bool pred = (n < NBOX) && (K < T);
    unsigned bal = __ballot_sync(0xFFFFFFFFu, pred);
    int lane = t & 31, w = t >> 5;
    if (lane == 0) wcnt[w] = (unsigned)__popc(bal);
    __syncthreads();
    if (t == 0) {
        unsigned a = 0;
#pragma unroll
        for (int i = 0; i < 8; i++) { wex[i] = a; a += wcnt[i]; }
    }
    __syncthreads();
    if (pred) {
        unsigned rank = g_boff[blockIdx.x] + wex[w] +
                        (unsigned)__popc(bal & ((1u << lane) - 1u));
        g_cand[rank] = ((unsigned long long)K << 32) | (unsigned)n;
    }
    if ((n < NBOX) && (K == T))
        atomicOr(&g_tiebm[n >> 5], 1u << (n & 31));
}

__global__ void tie_select_k()
{
    const int lane = threadIdx.x;
    const int base = g_cnt;
    const unsigned r = g_state[1];
    const unsigned T = g_state[0];
    unsigned taken = 0;
    for (int w0 = 0; w0 < TIE_WORDS && taken < r; w0 += 32) {
        int wi = w0 + lane;
        unsigned word = (wi < TIE_WORDS) ? g_tiebm[wi] : 0u;
        int cnt = __popc(word);
        int pre = cnt;
#pragma unroll
        for (int o = 1; o < 32; o <<= 1) {
            int v = __shfl_up_sync(0xFFFFFFFFu, pre, o);
            if (lane >= o) pre += v;
        }
        unsigned rank = taken + (unsigned)(pre - cnt);
        while (word && rank < r) {
            int b = __ffs(word) - 1;
            word &= word - 1;
            unsigned n = (unsigned)wi * 32u + (unsigned)b;
            g_cand[base + rank] = ((unsigned long long)T << 32) | n;
            rank++;
        }
        taken += (unsigned)__shfl_sync(0xFFFFFFFFu, pre, 31);
    }
}

// ---------------- single-block bitonic sort + gather ----------
extern __shared__ unsigned long long s_sort[];
__global__ void sort_topk_k()
{
    const int t = threadIdx.x;
    for (int i = t; i < SORTN; i += 1024)
        s_sort[i] = (i < PRE_NMS) ? g_cand[i] : 0xFFFFFFFFFFFFFFFFull;
    __syncthreads();
    for (int k = 2; k <= SORTN; k <<= 1) {
        for (int j = k >> 1; j > 0; j >>= 1) {
            for (int i = t; i < SORTN; i += 1024) {
                int ixj = i ^ j;
                if (ixj > i) {
                    unsigned long long a = s_sort[i], b = s_sort[ixj];
                    bool up = ((i & k) == 0);
                    if ((a > b) == up) { s_sort[i] = b; s_sort[ixj] = a; }
                }
            }
            __syncthreads();
        }
    }
    for (int i = t; i < 6144; i += 1024) {
        bool valid = false;
        if (i < PRE_NMS) {
            unsigned long long v = s_sort[i];
            unsigned K = (unsigned)(v >> 32);
            unsigned n = (unsigned)v;
            float b0 = 0, b1 = 0, b2 = 0, b3 = 0;
            if (n < (unsigned)NBOX) {
                const float4 bb = *reinterpret_cast<const float4*>(&g_roi[(size_t)n * 4]);
                b0 = bb.x; b1 = bb.y; b2 = bb.z; b3 = bb.w;
                valid = (K < 0x80000000u);
            }
            g_nb[(size_t)i * 4 + 0] = b0;
            g_nb[(size_t)i * 4 + 1] = b1;
            g_nb[(size_t)i * 4 + 2] = b2;
            g_nb[(size_t)i * 4 + 3] = b3;
        }
        unsigned bal = __ballot_sync(0xFFFFFFFFu, valid);
        if ((t & 31) == 0) g_keep_init[i >> 5] = bal;
    }
}

// ---------------- NMS suppression bitmask ----------------
__global__ __launch_bounds__(MASK_W) void mask_k()
{
    const int i = blockIdx.x;
    const int w = threadIdx.x;
    const float4* nb4 = reinterpret_cast<const float4*>(g_nb);
    float4 bi = nb4[i];
    float ai = (bi.z - bi.x) * (bi.w - bi.y);
    unsigned bits = 0;
    int jbase = w * 32;
#pragma unroll 4
    for (int b = 0; b < 32; b++) {
        int j = jbase + b;
        if (j > i && j < PRE_NMS) {
            float4 bj = nb4[j];
            float xx1 = fmaxf(bi.x, bj.x), yy1 = fmaxf(bi.y, bj.y);
            float xx2 = fminf(bi.z, bj.z), yy2 = fminf(bi.w, bj.w);
            float inter = fmaxf(xx2 - xx1, 0.f) * fmaxf(yy2 - yy1, 0.f);
            float aj = (bj.z - bj.x) * (bj.w - bj.y);
            float iou = inter / (ai + aj - inter + 1e-12f);
            if (iou > IOU_THR) bits |= (1u << b);
        }
    }
    g_mask[(size_t)i * MASK_W + w] = bits;
}

// ---------------- sequential greedy scan (single warp, early exit) ---------
// keep bits are finalized in scan order (suppression only clears j > i), and
// the output needs only the FIRST POST_NMS kept boxes. Once >= POST_NMS keeps
// are confirmed among fully-processed words, stop and zero the unscanned tail
// (write_rois skips ranks >= POST_NMS, so truncation is output-identical).
__global__ void nms_scan_k()
{
    const int lane = threadIdx.x;
    unsigned kw[6];
#pragma unroll
    for (int q = 0; q < 6; q++) kw[q] = g_keep_init[q * 32 + lane];

    unsigned total = 0;     // kept count in fully-finalized q blocks
    bool done = false;
    for (int q = 0; q < 6 && !done; q++) {
        const int iend = (q == 5) ? (PRE_NMS - 5 * 1024) : 1024;
        for (int ii = 0; ii < iend; ii++) {
            int i = q * 1024 + ii;
            unsigned word = __shfl_sync(0xFFFFFFFFu, kw[q], (i >> 5) & 31);
            if ((word >> (i & 31)) & 1u) {
                const unsigned* row = &g_mask[(size_t)i * MASK_W];
#pragma unroll
                for (int r = 0; r < 6; r++) kw[r] &= ~row[r * 32 + lane];
            }
            if ((ii & 255) == 255) {
                int nproc = (ii + 1) >> 5;   // finalized words within this q
                unsigned c = (lane < nproc) ? (unsigned)__popc(kw[q]) : 0u;
#pragma unroll
                for (int o = 16; o > 0; o >>= 1)
                    c += __shfl_xor_sync(0xFFFFFFFFu, c, o);
                if (total + c >= POST_NMS) {
                    if (lane >= nproc) kw[q] = 0;    // zero unfinalized words
                    for (int r = q + 1; r < 6; r++) kw[r] = 0;
                    done = true;
                    break;
                }
                if (nproc == 32) total += c;         // q block complete
            }
        }
    }
#pragma unroll
    for (int q = 0; q < 6; q++) g_keep_fin[q * 32 + lane] = kw[q];
}

// ---------------- write rois ----------------
__global__ __launch_bounds__(256) void write_rois_k(float* __restrict__ out)
{
    float* rois = out + ROI_OFF;
    __shared__ unsigned woff[MASK_W];
    int t = threadIdx.x;
    for (int i = t; i < POST_NMS * 4; i += 256) rois[i] = 0.f;
    if (t < MASK_W) woff[t] = (unsigned)__popc(g_keep_fin[t]);
    __syncthreads();
    if (t == 0) {
        unsigned acc = 0;
        for (int i = 0; i < MASK_W; i++) { unsigned tmp = woff[i]; woff[i] = acc; acc += tmp; }
    }
    __syncthreads();
    if (t < MASK_W) {
        unsigned word = g_keep_fin[t];
        unsigned rank = woff[t];
        while (word) {
            int b = __ffs(word) - 1;
            word &= word - 1;
            if (rank < POST_NMS) {
                int i = t * 32 + b;
                rois[rank * 4 + 0] = g_nb[(size_t)i * 4 + 0];
                rois[rank * 4 + 1] = g_nb[(size_t)i * 4 + 1];
                rois[rank * 4 + 2] = g_nb[(size_t)i * 4 + 2];
                rois[rank * 4 + 3] = g_nb[(size_t)i * 4 + 3];
            }
            rank++;
        }
    }
}

// ---------------- launcher ----------------
extern "C" void kernel_launch(void* const* d_in, const int* in_sizes, int n_in,
                              void* d_out, int out_size)
{
    const float* features = (const float*)d_in[0];
    const float* anchor   = (const float*)d_in[1];
    const float* w1       = (const float*)d_in[2];
    const float* b1       = (const float*)d_in[3];
    const float* wc       = (const float*)d_in[4];
    const float* bc       = (const float*)d_in[5];
    const float* wl       = (const float*)d_in[6];
    const float* bl       = (const float*)d_in[7];
    float* out = (float*)d_out;

    cudaFuncSetAttribute(sort_topk_k,
                         cudaFuncAttributeMaxDynamicSharedMemorySize,
                         SORTN * sizeof(unsigned long long));
    cudaFuncSetAttribute(conv_mma_k,
                         cudaFuncAttributeMaxDynamicSharedMemorySize,
                         CONV_SMEM);

    init_k<<<48, 256>>>();
    initb_k<<<48, 256>>>();
    const int XHALF_BLKS = (int)(((size_t)CIN * NPIX / 2 + 255) / 256);
    xsplit_k<<<XHALF_BLKS, 256>>>(features, 0);
    xsplit_k<<<XHALF_BLKS, 256>>>(features, 1);
    wsplit_k<<<(int)(((size_t)CIN * KTOT + 255) / 256), 256>>>(w1);

    dim3 gmma(NPXT, CIN / MTILE);   // 313 x 4
    conv_mma_k<<<gmma, 256, CONV_SMEM>>>(b1);

    conv1x1_k<<<(NPIX + PXT - 1) / PXT, 256>>>(wc, bc, wl, bl, out);

    decode_k<<<(NBOX + 255) / 256, 256>>>(anchor);

    hist_k<<<512, 256>>>(0, 24u, 0x00000000u);
    scan_k<<<1, 32>>>(0, 24u);
    hist_k<<<512, 256>>>(1, 16u, 0xFF000000u);
    scan_k<<<1, 32>>>(1, 16u);
    hist_k<<<512, 256>>>(2,  8u, 0xFFFF0000u);
    scan_k<<<1, 32>>>(2,  8u);
    hist_k<<<512, 256>>>(3,  0u, 0xFFFFFF00u);
    scan_k<<<1, 32>>>(3,  0u);

    count_k<<<NBLK, 256>>>();
    scanb_k<<<1, 256>>>();
    place_k<<<NBLK, 256>>>();
    tie_select_k<<<1, 32>>>();

    sort_topk_k<<<1, 1024, SORTN * sizeof(unsigned long long)>>>();

    mask_k<<<PRE_NMS, MASK_W>>>();

    nms_scan_k<<<1, 32>>>();

    write_rois_k<<<1, 256>>>(out);
}

// round 12
// speedup vs baseline: 2.5328x; 1.3110x over previous
#include <cuda_runtime.h>
#include <cuda_bf16.h>
#include <cuda_fp16.h>
#include <math.h>
#include <cstdint>

// ---------------- problem constants ----------------
#define HH 200
#define WW 200
#define NPIX (HH*WW)            // 40000
#define CIN 512
#define AA 9
#define NBOX (NPIX*AA)          // 360000
#define PRE_NMS 6000
#define POST_NMS 300
#define MIN_SIZE (16.0f/1000.0f)
#define IOU_THR 0.7f

#define CLS_OFF 0
#define LOC_OFF (NBOX*2)        // 720000
#define ROI_OFF (NBOX*2 + NBOX*4)  // 2160000

#define MASK_W 192
#define SORTN 8192
#define TIE_WORDS ((NBOX + 31) / 32)   // 11250
#define NBLK 1407               // ceil(NBOX/256)

// ---- Winograd F(2x2,3x3) GEMM geometry ----
#define NT1D 100                // tiles per axis
#define NTILES (NT1D*NT1D)      // 10000
#define UVW (CIN*CIN)           // 262144 (per-uv weight plane)
#define UVX ((size_t)CIN*NTILES) // 5120000 (per-uv data plane)
#define KC 32
#define GCH (CIN/KC)            // 16 K-chunks per GEMM
#define DRAIN 2
#define MTILE 128
#define NTILE 128
#define NTB ((NTILES + NTILE - 1)/NTILE)  // 79
#define PITCH 40                // fp16 elems per smem row (80 B)
#define SPLIT_B (128*PITCH*2)   // 10240 bytes per split tile
#define BS_OFF  (2*SPLIT_B)
#define CONV_SMEM (4*SPLIT_B)   // 40960 bytes

// fp16 2-split scaling (exact pow2; epilogue rescales by 2^-24)
#define XSCALE 1024.0f          // 2^10
#define WSCALE 16384.0f         // 2^14
#define OSCALE (1.0f/16777216.0f)

// ---------------- scratch (device globals) ------------
__device__ float g_x[(size_t)CIN * NPIX];
__device__ __align__(16) __half g_wu[2][(size_t)16 * UVW];   // U splits [uv][co][ci]
__device__ __align__(16) __half g_xv[2][(size_t)16 * UVX];   // V splits [uv][ci][tile]
__device__ float g_m[(size_t)16 * UVX];                      // M fp32 [uv][co][tile]
__device__ float g_cls[(size_t)NBOX * 2];
__device__ float g_loc[(size_t)NBOX * 4];
__device__ __align__(16) float g_roi[(size_t)NBOX * 4];
__device__ unsigned g_key[NBOX];
__device__ unsigned g_hist[4 * 256];
__device__ unsigned g_state[2];
__device__ int g_cnt;
__device__ unsigned g_bcnt[NBLK + 1];
__device__ unsigned g_boff[NBLK + 1];
__device__ unsigned long long g_cand[SORTN];
__device__ unsigned g_tiebm[TIE_WORDS];
__device__ __align__(16) float g_nb[6144 * 4];
__device__ unsigned g_keep_init[MASK_W];
__device__ unsigned g_keep_fin[MASK_W];
__device__ unsigned g_mask[(size_t)PRE_NMS * MASK_W];

// ---------------- PTX helpers ----------------
__device__ __forceinline__ uint32_t smem_u32(const void* p) {
    uint32_t a;
    asm("{ .reg .u64 t; cvta.to.shared.u64 t, %1; cvt.u32.u64 %0, t; }" : "=r"(a) : "l"(p));
    return a;
}
__device__ __forceinline__ void ldsm_x4(unsigned* r, uint32_t addr) {
    asm volatile("ldmatrix.sync.aligned.m8n8.x4.shared.b16 {%0,%1,%2,%3}, [%4];"
        : "=r"(r[0]), "=r"(r[1]), "=r"(r[2]), "=r"(r[3]) : "r"(addr));
}
__device__ __forceinline__ void ldsm_x2(unsigned* r, uint32_t addr) {
    asm volatile("ldmatrix.sync.aligned.m8n8.x2.shared.b16 {%0,%1}, [%2];"
        : "=r"(r[0]), "=r"(r[1]) : "r"(addr));
}
__device__ __forceinline__ void mma16816h(float* d, const unsigned* a, const unsigned* b) {
    asm volatile(
        "mma.sync.aligned.m16n8k16.row.col.f32.f16.f16.f32 "
        "{%0,%1,%2,%3}, {%4,%5,%6,%7}, {%8,%9}, {%0,%1,%2,%3};"
        : "+f"(d[0]), "+f"(d[1]), "+f"(d[2]), "+f"(d[3])
        : "r"(a[0]), "r"(a[1]), "r"(a[2]), "r"(a[3]), "r"(b[0]), "r"(b[1]));
}

// ---------------- init ----------------
__global__ void init_k() {
    int t = blockIdx.x * 256 + threadIdx.x;
    const int STRIDE = 48 * 256;
    for (int i = t; i < 4 * 256; i += STRIDE) g_hist[i] = 0;
    for (int i = t; i < TIE_WORDS; i += STRIDE) g_tiebm[i] = 0;
    for (int i = t; i < SORTN; i += STRIDE) g_cand[i] = 0xFFFFFFFFFFFFFFFFull;
}
__global__ void initb_k() {
    int t = blockIdx.x * 256 + threadIdx.x;
    const int STRIDE = 48 * 256;
    for (int i = t; i < NBLK + 1; i += STRIDE) { g_bcnt[i] = 0; g_boff[i] = 0; }
    for (int i = t; i < MASK_W; i += STRIDE) { g_keep_init[i] = 0; g_keep_fin[i] = 0; }
    if (t == 0) { g_cnt = 0; g_state[0] = 0u; g_state[1] = PRE_NMS; }
}

// ---------------- fp32 -> 2x fp16 split (value pre-scaled) -----------
__device__ __forceinline__ void split2h(float vs, __half& h0, __half& h1) {
    h0 = __float2half_rn(vs);
    h1 = __float2half_rn(vs - __half2float(h0));
}

// ---------------- weight transform: U = G g G^T, scaled + split -----------
__global__ __launch_bounds__(256) void wtrans_k(const float* __restrict__ w1)
{
    int n = blockIdx.x * 256 + threadIdx.x;
    if (n >= CIN * CIN) return;
    const float* wp = w1 + (size_t)n * 9;   // [co][ci][3][3]
    float g[9];
#pragma unroll
    for (int i = 0; i < 9; i++) g[i] = wp[i];
    float T[4][3];
#pragma unroll
    for (int c = 0; c < 3; c++) {
        T[0][c] = g[c];
        T[1][c] = 0.5f * (g[c] + g[3 + c] + g[6 + c]);
        T[2][c] = 0.5f * (g[c] - g[3 + c] + g[6 + c]);
        T[3][c] = g[6 + c];
    }
#pragma unroll
    for (int r = 0; r < 4; r++) {
        float u[4];
        u[0] = T[r][0];
        u[1] = 0.5f * (T[r][0] + T[r][1] + T[r][2]);
        u[2] = 0.5f * (T[r][0] - T[r][1] + T[r][2]);
        u[3] = T[r][2];
#pragma unroll
        for (int c = 0; c < 4; c++) {
            __half h0, h1;
            split2h(u[c] * WSCALE, h0, h1);
            size_t idx = (size_t)(r * 4 + c) * UVW + n;
            g_wu[0][idx] = h0;
            g_wu[1][idx] = h1;
        }
    }
}

// ---------------- input transform: V = B^T d B, scaled + split -----------
__global__ __launch_bounds__(256) void xtrans_k(const float* __restrict__ f)
{
    int tile = blockIdx.x * 256 + threadIdx.x;
    if (tile >= NTILES) return;
    int ci = blockIdx.y;
    int ty = tile / NT1D, tx = tile - ty * NT1D;
    int y0 = 2 * ty - 1, x0 = 2 * tx - 1;
    const float* fc = f + (size_t)ci * NPIX;
    float d[4][4];
#pragma unroll
    for (int r = 0; r < 4; r++) {
        int y = y0 + r;
#pragma unroll
        for (int c = 0; c < 4; c++) {
            int x = x0 + c;
            d[r][c] = ((unsigned)y < (unsigned)HH && (unsigned)x < (unsigned)WW)
                      ? fc[y * WW + x] : 0.f;
        }
    }
    float P[4][4];
#pragma unroll
    for (int c = 0; c < 4; c++) {
        P[0][c] = d[0][c] - d[2][c];
        P[1][c] = d[1][c] + d[2][c];
        P[2][c] = d[2][c] - d[1][c];
        P[3][c] = d[1][c] - d[3][c];
    }
#pragma unroll
    for (int r = 0; r < 4; r++) {
        float v[4];
        v[0] = P[r][0] - P[r][2];
        v[1] = P[r][1] + P[r][2];
        v[2] = P[r][2] - P[r][1];
        v[3] = P[r][1] - P[r][3];
#pragma unroll
        for (int c = 0; c < 4; c++) {
            __half h0, h1;
            split2h(v[c] * XSCALE, h0, h1);
            size_t idx = (size_t)(r * 4 + c) * UVX + (size_t)ci * NTILES + tile;
            g_xv[0][idx] = h0;
            g_xv[1][idx] = h1;
        }
    }
}

// ---------------- Winograd GEMM: M(uv) = U(uv) x V(uv), fp16x2 3-product ---
// CTA: 128co x 128tiles, 8 warps (warp tile 64x32), K=512 in 16 chunks.
__global__ __launch_bounds__(256) void gemm_k()
{
    extern __shared__ __align__(16) char smem[];
    const uint32_t sb = smem_u32(smem);
    const int t = threadIdx.x;
    const int w = t >> 5, lane = t & 31;
    const int t0 = blockIdx.x * NTILE;
    const int co0 = blockIdx.y * MTILE;
    const int uv = blockIdx.z;
    const int mw = (w & 1) * 64;
    const int nw = (w >> 1) * 32;

    float acc[4][4][4];
    float accm[4][4][4];
#pragma unroll
    for (int mt = 0; mt < 4; mt++)
#pragma unroll
        for (int nt = 0; nt < 4; nt++)
#pragma unroll
            for (int e = 0; e < 4; e++) { acc[mt][nt][e] = 0.f; accm[mt][nt][e] = 0.f; }

    const int arow = t >> 1, ahalf = t & 1;   // A staging: 2 thr/row, 16 fp16 each
    const uint32_t a_lb = (uint32_t)(((lane & 7) + ((lane >> 3) & 1) * 8) * (PITCH * 2)
                                     + (lane >> 4) * 16);
    const uint32_t b_lb = (uint32_t)((lane & 7) * (PITCH * 2) + ((lane >> 3) & 1) * 16);

    uint4 aR[2][2];
    unsigned bR[2][8];

    auto prefetch = [&](int c) {
        const int k0 = c * KC;
#pragma unroll
        for (int s = 0; s < 2; s++) {
            const uint4* src = (const uint4*)&g_wu[s][(size_t)uv * UVW
                                + (size_t)(co0 + arow) * CIN + k0 + ahalf * 16];
            aR[s][0] = src[0];
            aR[s][1] = src[1];
        }
#pragma unroll
        for (int e = 0; e < 8; e++) {
            int L = e * 512 + t * 2;
            int ci = L >> 7, tp = L & 127;
            int gt = t0 + tp;
#pragma unroll
            for (int s = 0; s < 2; s++) {
                unsigned v = 0;
                if (gt < NTILES)
                    v = *(const unsigned*)&g_xv[s][(size_t)uv * UVX
                            + (size_t)(k0 + ci) * NTILES + gt];
                bR[s][e] = v;
            }
        }
    };

    auto store_stage = [&]() {
#pragma unroll
        for (int s = 0; s < 2; s++) {
            uint4* dst = (uint4*)(smem + s * SPLIT_B + arow * (PITCH * 2) + ahalf * 32);
            dst[0] = aR[s][0];
            dst[1] = aR[s][1];
        }
#pragma unroll
        for (int e = 0; e < 8; e++) {
            int L = e * 512 + t * 2;
            int ci = L >> 7, tp = L & 127;
#pragma unroll
            for (int s = 0; s < 2; s++) {
                unsigned v = bR[s][e];
                char* bb = smem + BS_OFF + s * SPLIT_B;
                *(unsigned short*)(bb + tp * (PITCH * 2) + ci * 2) =
                    (unsigned short)(v & 0xFFFFu);
                *(unsigned short*)(bb + (tp + 1) * (PITCH * 2) + ci * 2) =
                    (unsigned short)(v >> 16);
            }
        }
    };

    prefetch(0);

    for (int c = 0; c < GCH; c++) {
        __syncthreads();
        store_stage();
        __syncthreads();
        if (c + 1 < GCH) prefetch(c + 1);

#pragma unroll
        for (int ks = 0; ks < 2; ks++) {
            const uint32_t koff = (uint32_t)(ks * 32);
            unsigned af0[4][4], af1[4][4];
#pragma unroll
            for (int mt = 0; mt < 4; mt++) {
                uint32_t ab = sb + (uint32_t)((mw + mt * 16) * (PITCH * 2)) + a_lb + koff;
                ldsm_x4(af0[mt], ab);
                ldsm_x4(af1[mt], ab + SPLIT_B);
            }
            {
                unsigned bf[4][2];
#pragma unroll
                for (int nt = 0; nt < 4; nt++)
                    ldsm_x2(bf[nt], sb + BS_OFF
                            + (uint32_t)((nw + nt * 8) * (PITCH * 2)) + b_lb + koff);
#pragma unroll
                for (int mt = 0; mt < 4; mt++)
#pragma unroll
                    for (int nt = 0; nt < 4; nt++) {
                        mma16816h(acc[mt][nt], af0[mt], bf[nt]);
                        mma16816h(acc[mt][nt], af1[mt], bf[nt]);
                    }
            }
            {
                unsigned bf[4][2];
#pragma unroll
                for (int nt = 0; nt < 4; nt++)
                    ldsm_x2(bf[nt], sb + BS_OFF + SPLIT_B
                            + (uint32_t)((nw + nt * 8) * (PITCH * 2)) + b_lb + koff);
#pragma unroll
                for (int mt = 0; mt < 4; mt++)
#pragma unroll
                    for (int nt = 0; nt < 4; nt++)
                        mma16816h(acc[mt][nt], af0[mt], bf[nt]);
            }
        }

        if ((c % DRAIN) == (DRAIN - 1)) {
#pragma unroll
            for (int mt = 0; mt < 4; mt++)
#pragma unroll
                for (int nt = 0; nt < 4; nt++)
#pragma unroll
                    for (int e = 0; e < 4; e++) {
                        accm[mt][nt][e] += acc[mt][nt][e];
                        acc[mt][nt][e] = 0.f;
                    }
        }
    }

    // epilogue: raw scaled fp32 -> g_m[uv][co][tile]
    float* mplane = g_m + (size_t)uv * UVX;
#pragma unroll
    for (int mt = 0; mt < 4; mt++) {
        int r0 = co0 + mw + mt * 16 + (lane >> 2);
#pragma unroll
        for (int nt = 0; nt < 4; nt++) {
            int col = t0 + nw + nt * 8 + (lane & 3) * 2;
            if (col < NTILES) {
                mplane[(size_t)r0 * NTILES + col] = accm[mt][nt][0];
                mplane[(size_t)(r0 + 8) * NTILES + col] = accm[mt][nt][2];
            }
            if (col + 1 < NTILES) {
                mplane[(size_t)r0 * NTILES + col + 1] = accm[mt][nt][1];
                mplane[(size_t)(r0 + 8) * NTILES + col + 1] = accm[mt][nt][3];
            }
        }
    }
}

// ---------------- output transform: Y = A^T M A, rescale + bias + relu -----
__global__ __launch_bounds__(256) void otrans_k(const float* __restrict__ b1)
{
    int tile = blockIdx.x * 256 + threadIdx.x;
    if (tile >= NTILES) return;
    int co = blockIdx.y;
    float m[16];
#pragma unroll
    for (int uv = 0; uv < 16; uv++)
        m[uv] = g_m[(size_t)uv * UVX + (size_t)co * NTILES + tile];
    float Z[2][4];
#pragma unroll
    for (int v = 0; v < 4; v++) {
        Z[0][v] = m[v] + m[4 + v] + m[8 + v];
        Z[1][v] = m[4 + v] - m[8 + v] - m[12 + v];
    }
    float bias = b1[co];
    int ty = tile / NT1D, tx = tile - ty * NT1D;
    float* gx = g_x + (size_t)co * NPIX;
#pragma unroll
    for (int i = 0; i < 2; i++) {
        float y0 = (Z[i][0] + Z[i][1] + Z[i][2]) * OSCALE + bias;
        float y1 = (Z[i][1] - Z[i][2] - Z[i][3]) * OSCALE + bias;
        int row = 2 * ty + i;
        gx[row * WW + 2 * tx]     = y0 > 0.f ? y0 : 0.f;
        gx[row * WW + 2 * tx + 1] = y1 > 0.f ? y1 : 0.f;
    }
}

// ---------------- 1x1 heads (cls 18 + loc 36) ----------------
#define PXT 128
#define OC 64
#define CKB 16
__global__ __launch_bounds__(256) void conv1x1_k(
    const float* __restrict__ wc, const float* __restrict__ bc,
    const float* __restrict__ wl, const float* __restrict__ bl,
    float* __restrict__ out)
{
    __shared__ float s_x[CKB][PXT];
    __shared__ float s_w[OC][CKB];
    const int p0 = blockIdx.x * PXT;
    const int t = threadIdx.x;
    const int cg = t >> 4;
    const int pg = t & 15;

    float acc[4][8];
#pragma unroll
    for (int k = 0; k < 4; k++)
#pragma unroll
        for (int j = 0; j < 8; j++) acc[k][j] = 0.f;

    for (int cb = 0; cb < CIN; cb += CKB) {
        __syncthreads();
        for (int i = t; i < CKB * PXT; i += 256) {
            int ci = i >> 7, pp = i & 127;
            int p = p0 + pp;
            s_x[ci][pp] = (p < NPIX) ? g_x[(size_t)(cb + ci) * NPIX + p] : 0.f;
        }
        for (int i = t; i < OC * CKB; i += 256) {
            int co = i >> 4, ci = i & 15;
            float v = 0.f;
            if (co < 18) v = wc[(size_t)co * CIN + cb + ci];
            else if (co < 54) v = wl[(size_t)(co - 18) * CIN + cb + ci];
            s_w[co][ci] = v;
        }
        __syncthreads();
#pragma unroll 4
        for (int ci = 0; ci < CKB; ci++) {
            float xv[8];
#pragma unroll
            for (int j = 0; j < 8; j++) xv[j] = s_x[ci][pg * 8 + j];
#pragma unroll
            for (int k = 0; k < 4; k++) {
                float wv = s_w[cg * 4 + k][ci];
#pragma unroll
                for (int j = 0; j < 8; j++)
                    acc[k][j] = fmaf(wv, xv[j], acc[k][j]);
            }
        }
    }

#pragma unroll
    for (int k = 0; k < 4; k++) {
        int co = cg * 4 + k;
#pragma unroll
        for (int j = 0; j < 8; j++) {
            int p = p0 + pg * 8 + j;
            if (p < NPIX) {
                if (co < 18) {
                    float v = acc[k][j] + bc[co];
                    out[CLS_OFF + (size_t)p * 18 + co] = v;
                    g_cls[(size_t)p * 18 + co] = v;
                } else if (co < 54) {
                    float v = acc[k][j] + bl[co - 18];
                    out[LOC_OFF + (size_t)p * 36 + (co - 18)] = v;
                    g_loc[(size_t)p * 36 + (co - 18)] = v;
                }
            }
        }
    }
}

// ---------------- decode boxes + scores + sort keys ----------------
__global__ void decode_k(const float* __restrict__ anchor)
{
    int n = blockIdx.x * 256 + threadIdx.x;
    if (n >= NBOX) return;
    float a0 = anchor[(size_t)n * 4 + 0], a1 = anchor[(size_t)n * 4 + 1];
    float a2 = anchor[(size_t)n * 4 + 2], a3 = anchor[(size_t)n * 4 + 3];
    float aw = a2 - a0, ah = a3 - a1;
    float acx = (a0 + a2) * 0.5f, acy = (a1 + a3) * 0.5f;
    float l0 = g_loc[(size_t)n * 4 + 0];
    float l1 = g_loc[(size_t)n * 4 + 1];
    float l2 = g_loc[(size_t)n * 4 + 2];
    float l3 = g_loc[(size_t)n * 4 + 3];
    float cx = l0 * aw + acx, cy = l1 * ah + acy;
    float bw = expf(l2) * aw, bh = expf(l3) * ah;
    float x1 = fminf(fmaxf(cx - bw * 0.5f, 0.f), 1.f);
    float y1 = fminf(fmaxf(cy - bh * 0.5f, 0.f), 1.f);
    float x2 = fminf(fmaxf(cx + bw * 0.5f, 0.f), 1.f);
    float y2 = fminf(fmaxf(cy + bh * 0.5f, 0.f), 1.f);
    g_roi[(size_t)n * 4 + 0] = x1;
    g_roi[(size_t)n * 4 + 1] = y1;
    g_roi[(size_t)n * 4 + 2] = x2;
    g_roi[(size_t)n * 4 + 3] = y2;

    float c0 = g_cls[(size_t)n * 2 + 0];
    float c1 = g_cls[(size_t)n * 2 + 1];
    float s = 1.f / (1.f + expf(c0 - c1));
    bool valid = ((y2 - y1) >= MIN_SIZE) && ((x2 - x1) >= MIN_SIZE);
    float sc = valid ? s : -1.0f;

    unsigned b = __float_as_uint(sc);
    unsigned ord = (b & 0x80000000u) ? ~b : (b | 0x80000000u);
    g_key[n] = ~ord;
}

// ---------------- 4-pass MSD radix select ----------------
__global__ void hist_k(int pass, unsigned shift, unsigned pmask)
{
    __shared__ unsigned h[256];
    int t = threadIdx.x;
    for (int i = t; i < 256; i += 256) h[i] = 0;
    __syncthreads();
    unsigned prefix = g_state[0];
    for (int n = blockIdx.x * 256 + t; n < NBOX; n += gridDim.x * 256) {
        unsigned K = g_key[n];
        if ((K & pmask) == prefix) atomicAdd(&h[(K >> shift) & 255u], 1u);
    }
    __syncthreads();
    unsigned* hist = &g_hist[pass * 256];
    for (int i = t; i < 256; i += 256)
        if (h[i]) atomicAdd(&hist[i], h[i]);
}

__global__ void scan_k(int pass, unsigned shift)
{
    if (threadIdx.x == 0) {
        const unsigned* hist = &g_hist[pass * 256];
        unsigned k = g_state[1];
        unsigned cum = 0;
        int d = 0;
        for (; d < 256; d++) {
            if (cum + hist[d] >= k) break;
            cum += hist[d];
        }
        if (d > 255) d = 255;
        g_state[0] |= ((unsigned)d) << shift;
        g_state[1] = k - cum;
    }
}

// ---------------- deterministic compaction ------------
__global__ __launch_bounds__(256) void count_k()
{
    __shared__ unsigned wsum[8];
    int n = blockIdx.x * 256 + threadIdx.x;
    unsigned T = g_state[0];
    bool pred = (n < NBOX) && (g_key[n] < T);
    unsigned bal = __ballot_sync(0xFFFFFFFFu, pred);
    if ((threadIdx.x & 31) == 0) wsum[threadIdx.x >> 5] = (unsigned)__popc(bal);
    __syncthreads();
    if (threadIdx.x == 0) {
        unsigned s = 0;
#pragma unroll
        for (int w = 0; w < 8; w++) s += wsum[w];
        g_bcnt[blockIdx.x] = s;
    }
}

#define SCCH 6
__global__ __launch_bounds__(256) void scanb_k()
{
    __shared__ unsigned ssum[256];
    int t = threadIdx.x;
    unsigned loc[SCCH];
    unsigned s = 0;
#pragma unroll
    for (int e = 0; e < SCCH; e++) {
        int idx = t * SCCH + e;
        loc[e] = (idx < NBLK) ? g_bcnt[idx] : 0u;
        s += loc[e];
    }
    ssum[t] = s;
    __syncthreads();
    if (t == 0) {
        unsigned acc = 0;
        for (int i = 0; i < 256; i++) { unsigned tmp = ssum[i]; ssum[i] = acc; acc += tmp; }
        g_cnt = (int)acc;
    }
    __syncthreads();
    unsigned run = ssum[t];
#pragma unroll
    for (int e = 0; e < SCCH; e++) {
        int idx = t * SCCH + e;
        if (idx < NBLK) g_boff[idx] = run;
        run += loc[e];
    }
}

__global__ __launch_bounds__(256) void place_k()
{
    __shared__ unsigned wcnt[8];
    __shared__ unsigned wex[8];
    int t = threadIdx.x;
    int n = blockIdx.x * 256 + t;
    unsigned T = g_state[0];
    unsigned K = (n < NBOX) ? g_key[n] : 0xFFFFFFFFu;
    bool pred = (n < NBOX) && (K < T);
    unsigned bal = __ballot_sync(0xFFFFFFFFu, pred);
    int lane = t & 31, w = t >> 5;
    if (lane == 0) wcnt[w] = (unsigned)__popc(bal);
    __syncthreads();
    if (t == 0) {
        unsigned a = 0;
#pragma unroll
        for (int i = 0; i < 8; i++) { wex[i] = a; a += wcnt[i]; }
    }
    __syncthreads();
    if (pred) {
        unsigned rank = g_boff[blockIdx.x] + wex[w] +
                        (unsigned)__popc(bal & ((1u << lane) - 1u));
        g_cand[rank] = ((unsigned long long)K << 32) | (unsigned)n;
    }
    if ((n < NBOX) && (K == T))
        atomicOr(&g_tiebm[n >> 5], 1u << (n & 31));
}

__global__ void tie_select_k()
{
    const int lane = threadIdx.x;
    const int base = g_cnt;
    const unsigned r = g_state[1];
    const unsigned T = g_state[0];
    unsigned taken = 0;
    for (int w0 = 0; w0 < TIE_WORDS && taken < r; w0 += 32) {
        int wi = w0 + lane;
        unsigned word = (wi < TIE_WORDS) ? g_tiebm[wi] : 0u;
        int cnt = __popc(word);
        int pre = cnt;
#pragma unroll
        for (int o = 1; o < 32; o <<= 1) {
            int v = __shfl_up_sync(0xFFFFFFFFu, pre, o);
            if (lane >= o) pre += v;
        }
        unsigned rank = taken + (unsigned)(pre - cnt);
        while (word && rank < r) {
            int b = __ffs(word) - 1;
            word &= word - 1;
            unsigned n = (unsigned)wi * 32u + (unsigned)b;
            g_cand[base + rank] = ((unsigned long long)T << 32) | n;
            rank++;
        }
        taken += (unsigned)__shfl_sync(0xFFFFFFFFu, pre, 31);
    }
}

// ---------------- single-block bitonic sort + gather ----------
extern __shared__ unsigned long long s_sort[];
__global__ void sort_topk_k()
{
    const int t = threadIdx.x;
    for (int i = t; i < SORTN; i += 1024)
        s_sort[i] = (i < PRE_NMS) ? g_cand[i] : 0xFFFFFFFFFFFFFFFFull;
    __syncthreads();
    for (int k = 2; k <= SORTN; k <<= 1) {
        for (int j = k >> 1; j > 0; j >>= 1) {
            for (int i = t; i < SORTN; i += 1024) {
                int ixj = i ^ j;
                if (ixj > i) {
                    unsigned long long a = s_sort[i], b = s_sort[ixj];
                    bool up = ((i & k) == 0);
                    if ((a > b) == up) { s_sort[i] = b; s_sort[ixj] = a; }
                }
            }
            __syncthreads();
        }
    }
    for (int i = t; i < 6144; i += 1024) {
        bool valid = false;
        if (i < PRE_NMS) {
            unsigned long long v = s_sort[i];
            unsigned K = (unsigned)(v >> 32);
            unsigned n = (unsigned)v;
            float b0 = 0, b1 = 0, b2 = 0, b3 = 0;
            if (n < (unsigned)NBOX) {
                const float4 bb = *reinterpret_cast<const float4*>(&g_roi[(size_t)n * 4]);
                b0 = bb.x; b1 = bb.y; b2 = bb.z; b3 = bb.w;
                valid = (K < 0x80000000u);
            }
            g_nb[(size_t)i * 4 + 0] = b0;
            g_nb[(size_t)i * 4 + 1] = b1;
            g_nb[(size_t)i * 4 + 2] = b2;
            g_nb[(size_t)i * 4 + 3] = b3;
        }
        unsigned bal = __ballot_sync(0xFFFFFFFFu, valid);
        if ((t & 31) == 0) g_keep_init[i >> 5] = bal;
    }
}

// ---------------- NMS suppression bitmask ----------------
__global__ __launch_bounds__(MASK_W) void mask_k()
{
    const int i = blockIdx.x;
    const int w = threadIdx.x;
    const float4* nb4 = reinterpret_cast<const float4*>(g_nb);
    float4 bi = nb4[i];
    float ai = (bi.z - bi.x) * (bi.w - bi.y);
    unsigned bits = 0;
    int jbase = w * 32;
#pragma unroll 4
    for (int b = 0; b < 32; b++) {
        int j = jbase + b;
        if (j > i && j < PRE_NMS) {
            float4 bj = nb4[j];
            float xx1 = fmaxf(bi.x, bj.x), yy1 = fmaxf(bi.y, bj.y);
            float xx2 = fminf(bi.z, bj.z), yy2 = fminf(bi.w, bj.w);
            float inter = fmaxf(xx2 - xx1, 0.f) * fmaxf(yy2 - yy1, 0.f);
            float aj = (bj.z - bj.x) * (bj.w - bj.y);
            float iou = inter / (ai + aj - inter + 1e-12f);
            if (iou > IOU_THR) bits |= (1u << b);
        }
    }
    g_mask[(size_t)i * MASK_W + w] = bits;
}

// ---------------- sequential greedy scan (single warp, early exit) ---------
__global__ void nms_scan_k()
{
    const int lane = threadIdx.x;
    unsigned kw[6];
#pragma unroll
    for (int q = 0; q < 6; q++) kw[q] = g_keep_init[q * 32 + lane];

    unsigned total = 0;
    bool done = false;
    for (int q = 0; q < 6 && !done; q++) {
        const int iend = (q == 5) ? (PRE_NMS - 5 * 1024) : 1024;
        for (int ii = 0; ii < iend; ii++) {
            int i = q * 1024 + ii;
            unsigned word = __shfl_sync(0xFFFFFFFFu, kw[q], (i >> 5) & 31);
            if ((word >> (i & 31)) & 1u) {
                const unsigned* row = &g_mask[(size_t)i * MASK_W];
#pragma unroll
                for (int r = 0; r < 6; r++) kw[r] &= ~row[r * 32 + lane];
            }
            if ((ii & 255) == 255) {
                int nproc = (ii + 1) >> 5;
                unsigned c = (lane < nproc) ? (unsigned)__popc(kw[q]) : 0u;
#pragma unroll
                for (int o = 16; o > 0; o >>= 1)
                    c += __shfl_xor_sync(0xFFFFFFFFu, c, o);
                if (total + c >= POST_NMS) {
                    if (lane >= nproc) kw[q] = 0;
                    for (int r = q + 1; r < 6; r++) kw[r] = 0;
                    done = true;
                    break;
                }
                if (nproc == 32) total += c;
            }
        }
    }
#pragma unroll
    for (int q = 0; q < 6; q++) g_keep_fin[q * 32 + lane] = kw[q];
}

// ---------------- write rois ----------------
__global__ __launch_bounds__(256) void write_rois_k(float* __restrict__ out)
{
    float* rois = out + ROI_OFF;
    __shared__ unsigned woff[MASK_W];
    int t = threadIdx.x;
    for (int i = t; i < POST_NMS * 4; i += 256) rois[i] = 0.f;
    if (t < MASK_W) woff[t] = (unsigned)__popc(g_keep_fin[t]);
    __syncthreads();
    if (t == 0) {
        unsigned acc = 0;
        for (int i = 0; i < MASK_W; i++) { unsigned tmp = woff[i]; woff[i] = acc; acc += tmp; }
    }
    __syncthreads();
    if (t < MASK_W) {
        unsigned word = g_keep_fin[t];
        unsigned rank = woff[t];
        while (word) {
            int b = __ffs(word) - 1;
            word &= word - 1;
            if (rank < POST_NMS) {
                int i = t * 32 + b;
                rois[rank * 4 + 0] = g_nb[(size_t)i * 4 + 0];
                rois[rank * 4 + 1] = g_nb[(size_t)i * 4 + 1];
                rois[rank * 4 + 2] = g_nb[(size_t)i * 4 + 2];
                rois[rank * 4 + 3] = g_nb[(size_t)i * 4 + 3];
            }
            rank++;
        }
    }
}

// ---------------- launcher ----------------
extern "C" void kernel_launch(void* const* d_in, const int* in_sizes, int n_in,
                              void* d_out, int out_size)
{
    const float* features = (const float*)d_in[0];
    const float* anchor   = (const float*)d_in[1];
    const float* w1       = (const float*)d_in[2];
    const float* b1       = (const float*)d_in[3];
    const float* wc       = (const float*)d_in[4];
    const float* bc       = (const float*)d_in[5];
    const float* wl       = (const float*)d_in[6];
    const float* bl       = (const float*)d_in[7];
    float* out = (float*)d_out;

    cudaFuncSetAttribute(sort_topk_k,
                         cudaFuncAttributeMaxDynamicSharedMemorySize,
                         SORTN * sizeof(unsigned long long));
    cudaFuncSetAttribute(gemm_k,
                         cudaFuncAttributeMaxDynamicSharedMemorySize,
                         CONV_SMEM);

    init_k<<<48, 256>>>();
    initb_k<<<48, 256>>>();

    wtrans_k<<<(CIN * CIN + 255) / 256, 256>>>(w1);
    xtrans_k<<<dim3((NTILES + 255) / 256, CIN), 256>>>(features);

    gemm_k<<<dim3(NTB, CIN / MTILE, 16), 256, CONV_SMEM>>>();

    otrans_k<<<dim3((NTILES + 255) / 256, CIN), 256>>>(b1);

    conv1x1_k<<<(NPIX + PXT - 1) / PXT, 256>>>(wc, bc, wl, bl, out);

    decode_k<<<(NBOX + 255) / 256, 256>>>(anchor);

    hist_k<<<512, 256>>>(0, 24u, 0x00000000u);
    scan_k<<<1, 32>>>(0, 24u);
    hist_k<<<512, 256>>>(1, 16u, 0xFF000000u);
    scan_k<<<1, 32>>>(1, 16u);
    hist_k<<<512, 256>>>(2,  8u, 0xFFFF0000u);
    scan_k<<<1, 32>>>(2,  8u);
    hist_k<<<512, 256>>>(3,  0u, 0xFFFFFF00u);
    scan_k<<<1, 32>>>(3,  0u);

    count_k<<<NBLK, 256>>>();
    scanb_k<<<1, 256>>>();
    place_k<<<NBLK, 256>>>();
    tie_select_k<<<1, 32>>>();

    sort_topk_k<<<1, 1024, SORTN * sizeof(unsigned long long)>>>();

    mask_k<<<PRE_NMS, MASK_W>>>();

    nms_scan_k<<<1, 32>>>();

    write_rois_k<<<1, 256>>>(out);
}

// round 13
// speedup vs baseline: 3.9193x; 1.5474x over previous
#include <cuda_runtime.h>
#include <cuda_bf16.h>
#include <cuda_fp16.h>
#include <math.h>
#include <cstdint>

// ---------------- problem constants ----------------
#define HH 200
#define WW 200
#define NPIX (HH*WW)            // 40000
#define CIN 512
#define AA 9
#define NBOX (NPIX*AA)          // 360000
#define PRE_NMS 6000
#define POST_NMS 300
#define MIN_SIZE (16.0f/1000.0f)
#define IOU_THR 0.7f

#define CLS_OFF 0
#define LOC_OFF (NBOX*2)        // 720000
#define ROI_OFF (NBOX*2 + NBOX*4)  // 2160000

#define MASK_W 192
#define SORTN 8192
#define TIE_WORDS ((NBOX + 31) / 32)   // 11250
#define NBLK 1407               // ceil(NBOX/256)

// ---- Winograd F(2x2,3x3) GEMM geometry ----
#define NT1D 100                // tiles per axis
#define NTILES (NT1D*NT1D)      // 10000
#define UVW (CIN*CIN)           // 262144 (per-uv weight plane)
#define UVX ((size_t)CIN*NTILES) // 5120000 (per-uv data plane)
#define KC 32
#define GCH (CIN/KC)            // 16 K-chunks per GEMM
#define DRAIN 2
#define MTILE 128
#define NTILE 128
#define NTB ((NTILES + NTILE - 1)/NTILE)  // 79
#define PITCH 40                // fp16 elems per smem row (80 B)
#define SPLIT_B (128*PITCH*2)   // 10240 bytes per split tile
#define BS_OFF  (2*SPLIT_B)
#define BUF_B   (4*SPLIT_B)     // one buffer: 2 A splits + 2 B splits
#define CONV_SMEM (2*BUF_B)     // 81920 bytes, double-buffered

// fp16 2-split scaling (exact pow2; epilogue rescales by 2^-24)
#define XSCALE 1024.0f          // 2^10
#define WSCALE 16384.0f         // 2^14
#define OSCALE (1.0f/16777216.0f)

// ---------------- scratch (device globals) ------------
__device__ float g_x[(size_t)CIN * NPIX];
__device__ __align__(16) __half g_wu[2][(size_t)16 * UVW];   // U splits [uv][co][ci]
__device__ __align__(16) __half g_xv[2][(size_t)16 * UVX];   // V splits [uv][ci][tile]
__device__ float g_m[(size_t)16 * UVX];                      // M fp32 [uv][co][tile]
__device__ float g_cls[(size_t)NBOX * 2];
__device__ float g_loc[(size_t)NBOX * 4];
__device__ __align__(16) float g_roi[(size_t)NBOX * 4];
__device__ unsigned g_key[NBOX];
__device__ unsigned g_hist[4 * 256];
__device__ unsigned g_state[2];
__device__ int g_cnt;
__device__ unsigned g_bcnt[NBLK + 1];
__device__ unsigned g_boff[NBLK + 1];
__device__ unsigned long long g_cand[SORTN];
__device__ unsigned g_tiebm[TIE_WORDS];
__device__ __align__(16) float g_nb[6144 * 4];
__device__ unsigned g_keep_init[MASK_W];
__device__ unsigned g_keep_fin[MASK_W];
__device__ unsigned g_mask[(size_t)PRE_NMS * MASK_W];

// ---------------- PTX helpers ----------------
__device__ __forceinline__ uint32_t smem_u32(const void* p) {
    uint32_t a;
    asm("{ .reg .u64 t; cvta.to.shared.u64 t, %1; cvt.u32.u64 %0, t; }" : "=r"(a) : "l"(p));
    return a;
}
__device__ __forceinline__ void ldsm_x4(unsigned* r, uint32_t addr) {
    asm volatile("ldmatrix.sync.aligned.m8n8.x4.shared.b16 {%0,%1,%2,%3}, [%4];"
        : "=r"(r[0]), "=r"(r[1]), "=r"(r[2]), "=r"(r[3]) : "r"(addr));
}
__device__ __forceinline__ void ldsm_x2(unsigned* r, uint32_t addr) {
    asm volatile("ldmatrix.sync.aligned.m8n8.x2.shared.b16 {%0,%1}, [%2];"
        : "=r"(r[0]), "=r"(r[1]) : "r"(addr));
}
__device__ __forceinline__ void mma16816h(float* d, const unsigned* a, const unsigned* b) {
    asm volatile(
        "mma.sync.aligned.m16n8k16.row.col.f32.f16.f16.f32 "
        "{%0,%1,%2,%3}, {%4,%5,%6,%7}, {%8,%9}, {%0,%1,%2,%3};"
        : "+f"(d[0]), "+f"(d[1]), "+f"(d[2]), "+f"(d[3])
        : "r"(a[0]), "r"(a[1]), "r"(a[2]), "r"(a[3]), "r"(b[0]), "r"(b[1]));
}

// ---------------- init ----------------
__global__ void init_k() {
    int t = blockIdx.x * 256 + threadIdx.x;
    const int STRIDE = 48 * 256;
    for (int i = t; i < 4 * 256; i += STRIDE) g_hist[i] = 0;
    for (int i = t; i < TIE_WORDS; i += STRIDE) g_tiebm[i] = 0;
    for (int i = t; i < SORTN; i += STRIDE) g_cand[i] = 0xFFFFFFFFFFFFFFFFull;
}
__global__ void initb_k() {
    int t = blockIdx.x * 256 + threadIdx.x;
    const int STRIDE = 48 * 256;
    for (int i = t; i < NBLK + 1; i += STRIDE) { g_bcnt[i] = 0; g_boff[i] = 0; }
    for (int i = t; i < MASK_W; i += STRIDE) { g_keep_init[i] = 0; g_keep_fin[i] = 0; }
    if (t == 0) { g_cnt = 0; g_state[0] = 0u; g_state[1] = PRE_NMS; }
}

// ---------------- fp32 -> 2x fp16 split (value pre-scaled) -----------
__device__ __forceinline__ void split2h(float vs, __half& h0, __half& h1) {
    h0 = __float2half_rn(vs);
    h1 = __float2half_rn(vs - __half2float(h0));
}

// ---------------- weight transform: U = G g G^T, scaled + split -----------
__global__ __launch_bounds__(256) void wtrans_k(const float* __restrict__ w1)
{
    int n = blockIdx.x * 256 + threadIdx.x;
    if (n >= CIN * CIN) return;
    const float* wp = w1 + (size_t)n * 9;   // [co][ci][3][3]
    float g[9];
#pragma unroll
    for (int i = 0; i < 9; i++) g[i] = wp[i];
    float T[4][3];
#pragma unroll
    for (int c = 0; c < 3; c++) {
        T[0][c] = g[c];
        T[1][c] = 0.5f * (g[c] + g[3 + c] + g[6 + c]);
        T[2][c] = 0.5f * (g[c] - g[3 + c] + g[6 + c]);
        T[3][c] = g[6 + c];
    }
#pragma unroll
    for (int r = 0; r < 4; r++) {
        float u[4];
        u[0] = T[r][0];
        u[1] = 0.5f * (T[r][0] + T[r][1] + T[r][2]);
        u[2] = 0.5f * (T[r][0] - T[r][1] + T[r][2]);
        u[3] = T[r][2];
#pragma unroll
        for (int c = 0; c < 4; c++) {
            __half h0, h1;
            split2h(u[c] * WSCALE, h0, h1);
            size_t idx = (size_t)(r * 4 + c) * UVW + n;
            g_wu[0][idx] = h0;
            g_wu[1][idx] = h1;
        }
    }
}

// ---------------- input transform: V = B^T d B, scaled + split -----------
__global__ __launch_bounds__(256) void xtrans_k(const float* __restrict__ f)
{
    int tile = blockIdx.x * 256 + threadIdx.x;
    if (tile >= NTILES) return;
    int ci = blockIdx.y;
    int ty = tile / NT1D, tx = tile - ty * NT1D;
    int y0 = 2 * ty - 1, x0 = 2 * tx - 1;
    const float* fc = f + (size_t)ci * NPIX;
    float d[4][4];
#pragma unroll
    for (int r = 0; r < 4; r++) {
        int y = y0 + r;
#pragma unroll
        for (int c = 0; c < 4; c++) {
            int x = x0 + c;
            d[r][c] = ((unsigned)y < (unsigned)HH && (unsigned)x < (unsigned)WW)
                      ? fc[y * WW + x] : 0.f;
        }
    }
    float P[4][4];
#pragma unroll
    for (int c = 0; c < 4; c++) {
        P[0][c] = d[0][c] - d[2][c];
        P[1][c] = d[1][c] + d[2][c];
        P[2][c] = d[2][c] - d[1][c];
        P[3][c] = d[1][c] - d[3][c];
    }
#pragma unroll
    for (int r = 0; r < 4; r++) {
        float v[4];
        v[0] = P[r][0] - P[r][2];
        v[1] = P[r][1] + P[r][2];
        v[2] = P[r][2] - P[r][1];
        v[3] = P[r][1] - P[r][3];
#pragma unroll
        for (int c = 0; c < 4; c++) {
            __half h0, h1;
            split2h(v[c] * XSCALE, h0, h1);
            size_t idx = (size_t)(r * 4 + c) * UVX + (size_t)ci * NTILES + tile;
            g_xv[0][idx] = h0;
            g_xv[1][idx] = h1;
        }
    }
}

// ---------------- Winograd GEMM: M(uv) = U(uv) x V(uv), fp16x2 3-product ---
// CTA: 128co x 128tiles, 8 warps (warp tile 64x32), K=512 in 16 chunks.
// Double-buffered smem: one barrier/chunk; LDGs for c+1 issue before compute
// of c, STS for c+1 land after compute (scoreboard-overlapped).
__global__ __launch_bounds__(256) void gemm_k()
{
    extern __shared__ __align__(16) char smem[];
    const uint32_t sb = smem_u32(smem);
    const int t = threadIdx.x;
    const int w = t >> 5, lane = t & 31;
    const int t0 = blockIdx.x * NTILE;
    const int co0 = blockIdx.y * MTILE;
    const int uv = blockIdx.z;
    const int mw = (w & 1) * 64;
    const int nw = (w >> 1) * 32;

    float acc[4][4][4];
    float accm[4][4][4];
#pragma unroll
    for (int mt = 0; mt < 4; mt++)
#pragma unroll
        for (int nt = 0; nt < 4; nt++)
#pragma unroll
            for (int e = 0; e < 4; e++) { acc[mt][nt][e] = 0.f; accm[mt][nt][e] = 0.f; }

    const int arow = t >> 1, ahalf = t & 1;   // A staging: 2 thr/row, 16 fp16 each
    const uint32_t a_lb = (uint32_t)(((lane & 7) + ((lane >> 3) & 1) * 8) * (PITCH * 2)
                                     + (lane >> 4) * 16);
    const uint32_t b_lb = (uint32_t)((lane & 7) * (PITCH * 2) + ((lane >> 3) & 1) * 16);

    uint4 aR[2][2];
    unsigned bR[2][8];

    auto prefetch = [&](int c) {
        const int k0 = c * KC;
#pragma unroll
        for (int s = 0; s < 2; s++) {
            const uint4* src = (const uint4*)&g_wu[s][(size_t)uv * UVW
                                + (size_t)(co0 + arow) * CIN + k0 + ahalf * 16];
            aR[s][0] = src[0];
            aR[s][1] = src[1];
        }
#pragma unroll
        for (int e = 0; e < 8; e++) {
            int L = e * 512 + t * 2;
            int ci = L >> 7, tp = L & 127;
            int gt = t0 + tp;
#pragma unroll
            for (int s = 0; s < 2; s++) {
                unsigned v = 0;
                if (gt < NTILES)
                    v = *(const unsigned*)&g_xv[s][(size_t)uv * UVX
                            + (size_t)(k0 + ci) * NTILES + gt];
                bR[s][e] = v;
            }
        }
    };

    auto store_stage = [&](char* base) {
#pragma unroll
        for (int s = 0; s < 2; s++) {
            uint4* dst = (uint4*)(base + s * SPLIT_B + arow * (PITCH * 2) + ahalf * 32);
            dst[0] = aR[s][0];
            dst[1] = aR[s][1];
        }
#pragma unroll
        for (int e = 0; e < 8; e++) {
            int L = e * 512 + t * 2;
            int ci = L >> 7, tp = L & 127;
#pragma unroll
            for (int s = 0; s < 2; s++) {
                unsigned v = bR[s][e];
                char* bb = base + BS_OFF + s * SPLIT_B;
                *(unsigned short*)(bb + tp * (PITCH * 2) + ci * 2) =
                    (unsigned short)(v & 0xFFFFu);
                *(unsigned short*)(bb + (tp + 1) * (PITCH * 2) + ci * 2) =
                    (unsigned short)(v >> 16);
            }
        }
    };

    auto compute = [&](uint32_t bufb) {
#pragma unroll
        for (int ks = 0; ks < 2; ks++) {
            const uint32_t koff = (uint32_t)(ks * 32);
            unsigned af0[4][4], af1[4][4];
#pragma unroll
            for (int mt = 0; mt < 4; mt++) {
                uint32_t ab = bufb + (uint32_t)((mw + mt * 16) * (PITCH * 2)) + a_lb + koff;
                ldsm_x4(af0[mt], ab);
                ldsm_x4(af1[mt], ab + SPLIT_B);
            }
            {
                unsigned bf[4][2];
#pragma unroll
                for (int nt = 0; nt < 4; nt++)
                    ldsm_x2(bf[nt], bufb + BS_OFF
                            + (uint32_t)((nw + nt * 8) * (PITCH * 2)) + b_lb + koff);
#pragma unroll
                for (int mt = 0; mt < 4; mt++)
#pragma unroll
                    for (int nt = 0; nt < 4; nt++) {
                        mma16816h(acc[mt][nt], af0[mt], bf[nt]);
                        mma16816h(acc[mt][nt], af1[mt], bf[nt]);
                    }
            }
            {
                unsigned bf[4][2];
#pragma unroll
                for (int nt = 0; nt < 4; nt++)
                    ldsm_x2(bf[nt], bufb + BS_OFF + SPLIT_B
                            + (uint32_t)((nw + nt * 8) * (PITCH * 2)) + b_lb + koff);
#pragma unroll
                for (int mt = 0; mt < 4; mt++)
#pragma unroll
                    for (int nt = 0; nt < 4; nt++)
                        mma16816h(acc[mt][nt], af0[mt], bf[nt]);
            }
        }
    };

    // prologue: fill buffer 0
    prefetch(0);
    store_stage(smem);
    __syncthreads();

    for (int c = 0; c < GCH; c++) {
        const int cur = c & 1;
        if (c + 1 < GCH) prefetch(c + 1);          // LDGs fly under compute
        compute(sb + cur * BUF_B);                  // read buf[cur]
        if (c + 1 < GCH) store_stage(smem + (cur ^ 1) * BUF_B);  // write other buf
        __syncthreads();                            // hand off both buffers

        if ((c % DRAIN) == (DRAIN - 1)) {
#pragma unroll
            for (int mt = 0; mt < 4; mt++)
#pragma unroll
                for (int nt = 0; nt < 4; nt++)
#pragma unroll
                    for (int e = 0; e < 4; e++) {
                        accm[mt][nt][e] += acc[mt][nt][e];
                        acc[mt][nt][e] = 0.f;
                    }
        }
    }

    // epilogue: raw scaled fp32 -> g_m[uv][co][tile] (paired 64-bit stores)
    float* mplane = g_m + (size_t)uv * UVX;
#pragma unroll
    for (int mt = 0; mt < 4; mt++) {
        int r0 = co0 + mw + mt * 16 + (lane >> 2);
#pragma unroll
        for (int nt = 0; nt < 4; nt++) {
            int col = t0 + nw + nt * 8 + (lane & 3) * 2;
            if (col + 1 < NTILES) {
                *(float2*)&mplane[(size_t)r0 * NTILES + col] =
                    make_float2(accm[mt][nt][0], accm[mt][nt][1]);
                *(float2*)&mplane[(size_t)(r0 + 8) * NTILES + col] =
                    make_float2(accm[mt][nt][2], accm[mt][nt][3]);
            } else if (col < NTILES) {
                mplane[(size_t)r0 * NTILES + col] = accm[mt][nt][0];
                mplane[(size_t)(r0 + 8) * NTILES + col] = accm[mt][nt][2];
            }
        }
    }
}

// ---------------- output transform: Y = A^T M A, rescale + bias + relu -----
__global__ __launch_bounds__(256) void otrans_k(const float* __restrict__ b1)
{
    int tile = blockIdx.x * 256 + threadIdx.x;
    if (tile >= NTILES) return;
    int co = blockIdx.y;
    float m[16];
#pragma unroll
    for (int uv = 0; uv < 16; uv++)
        m[uv] = g_m[(size_t)uv * UVX + (size_t)co * NTILES + tile];
    float Z[2][4];
#pragma unroll
    for (int v = 0; v < 4; v++) {
        Z[0][v] = m[v] + m[4 + v] + m[8 + v];
        Z[1][v] = m[4 + v] - m[8 + v] - m[12 + v];
    }
    float bias = b1[co];
    int ty = tile / NT1D, tx = tile - ty * NT1D;
    float* gx = g_x + (size_t)co * NPIX;
#pragma unroll
    for (int i = 0; i < 2; i++) {
        float y0 = (Z[i][0] + Z[i][1] + Z[i][2]) * OSCALE + bias;
        float y1 = (Z[i][1] - Z[i][2] - Z[i][3]) * OSCALE + bias;
        int row = 2 * ty + i;
        gx[row * WW + 2 * tx]     = y0 > 0.f ? y0 : 0.f;
        gx[row * WW + 2 * tx + 1] = y1 > 0.f ? y1 : 0.f;
    }
}

// ---------------- 1x1 heads (cls 18 + loc 36) ----------------
#define PXT 128
#define OC 64
#define CKB 16
__global__ __launch_bounds__(256) void conv1x1_k(
    const float* __restrict__ wc, const float* __restrict__ bc,
    const float* __restrict__ wl, const float* __restrict__ bl,
    float* __restrict__ out)
{
    __shared__ float s_x[CKB][PXT];
    __shared__ float s_w[OC][CKB];
    const int p0 = blockIdx.x * PXT;
    const int t = threadIdx.x;
    const int cg = t >> 4;
    const int pg = t & 15;

    float acc[4][8];
#pragma unroll
    for (int k = 0; k < 4; k++)
#pragma unroll
        for (int j = 0; j < 8; j++) acc[k][j] = 0.f;

    for (int cb = 0; cb < CIN; cb += CKB) {
        __syncthreads();
        for (int i = t; i < CKB * PXT; i += 256) {
            int ci = i >> 7, pp = i & 127;
            int p = p0 + pp;
            s_x[ci][pp] = (p < NPIX) ? g_x[(size_t)(cb + ci) * NPIX + p] : 0.f;
        }
        for (int i = t; i < OC * CKB; i += 256) {
            int co = i >> 4, ci = i & 15;
            float v = 0.f;
            if (co < 18) v = wc[(size_t)co * CIN + cb + ci];
            else if (co < 54) v = wl[(size_t)(co - 18) * CIN + cb + ci];
            s_w[co][ci] = v;
        }
        __syncthreads();
#pragma unroll 4
        for (int ci = 0; ci < CKB; ci++) {
            float xv[8];
#pragma unroll
            for (int j = 0; j < 8; j++) xv[j] = s_x[ci][pg * 8 + j];
#pragma unroll
            for (int k = 0; k < 4; k++) {
                float wv = s_w[cg * 4 + k][ci];
#pragma unroll
                for (int j = 0; j < 8; j++)
                    acc[k][j] = fmaf(wv, xv[j], acc[k][j]);
            }
        }
    }

#pragma unroll
    for (int k = 0; k < 4; k++) {
        int co = cg * 4 + k;
#pragma unroll
        for (int j = 0; j < 8; j++) {
            int p = p0 + pg * 8 + j;
            if (p < NPIX) {
                if (co < 18) {
                    float v = acc[k][j] + bc[co];
                    out[CLS_OFF + (size_t)p * 18 + co] = v;
                    g_cls[(size_t)p * 18 + co] = v;
                } else if (co < 54) {
                    float v = acc[k][j] + bl[co - 18];
                    out[LOC_OFF + (size_t)p * 36 + (co - 18)] = v;
                    g_loc[(size_t)p * 36 + (co - 18)] = v;
                }
            }
        }
    }
}

// ---------------- decode boxes + scores + sort keys ----------------
__global__ void decode_k(const float* __restrict__ anchor)
{
    int n = blockIdx.x * 256 + threadIdx.x;
    if (n >= NBOX) return;
    float a0 = anchor[(size_t)n * 4 + 0], a1 = anchor[(size_t)n * 4 + 1];
    float a2 = anchor[(size_t)n * 4 + 2], a3 = anchor[(size_t)n * 4 + 3];
    float aw = a2 - a0, ah = a3 - a1;
    float acx = (a0 + a2) * 0.5f, acy = (a1 + a3) * 0.5f;
    float l0 = g_loc[(size_t)n * 4 + 0];
    float l1 = g_loc[(size_t)n * 4 + 1];
    float l2 = g_loc[(size_t)n * 4 + 2];
    float l3 = g_loc[(size_t)n * 4 + 3];
    float cx = l0 * aw + acx, cy = l1 * ah + acy;
    float bw = expf(l2) * aw, bh = expf(l3) * ah;
    float x1 = fminf(fmaxf(cx - bw * 0.5f, 0.f), 1.f);
    float y1 = fminf(fmaxf(cy - bh * 0.5f, 0.f), 1.f);
    float x2 = fminf(fmaxf(cx + bw * 0.5f, 0.f), 1.f);
    float y2 = fminf(fmaxf(cy + bh * 0.5f, 0.f), 1.f);
    g_roi[(size_t)n * 4 + 0] = x1;
    g_roi[(size_t)n * 4 + 1] = y1;
    g_roi[(size_t)n * 4 + 2] = x2;
    g_roi[(size_t)n * 4 + 3] = y2;

    float c0 = g_cls[(size_t)n * 2 + 0];
    float c1 = g_cls[(size_t)n * 2 + 1];
    float s = 1.f / (1.f + expf(c0 - c1));
    bool valid = ((y2 - y1) >= MIN_SIZE) && ((x2 - x1) >= MIN_SIZE);
    float sc = valid ? s : -1.0f;

    unsigned b = __float_as_uint(sc);
    unsigned ord = (b & 0x80000000u) ? ~b : (b | 0x80000000u);
    g_key[n] = ~ord;
}

// ---------------- 4-pass MSD radix select ----------------
__global__ void hist_k(int pass, unsigned shift, unsigned pmask)
{
    __shared__ unsigned h[256];
    int t = threadIdx.x;
    for (int i = t; i < 256; i += 256) h[i] = 0;
    __syncthreads();
    unsigned prefix = g_state[0];
    for (int n = blockIdx.x * 256 + t; n < NBOX; n += gridDim.x * 256) {
        unsigned K = g_key[n];
        if ((K & pmask) == prefix) atomicAdd(&h[(K >> shift) & 255u], 1u);
    }
    __syncthreads();
    unsigned* hist = &g_hist[pass * 256];
    for (int i = t; i < 256; i += 256)
        if (h[i]) atomicAdd(&hist[i], h[i]);
}

__global__ void scan_k(int pass, unsigned shift)
{
    if (threadIdx.x == 0) {
        const unsigned* hist = &g_hist[pass * 256];
        unsigned k = g_state[1];
        unsigned cum = 0;
        int d = 0;
        for (; d < 256; d++) {
            if (cum + hist[d] >= k) break;
            cum += hist[d];
        }
        if (d > 255) d = 255;
        g_state[0] |= ((unsigned)d) << shift;
        g_state[1] = k - cum;
    }
}

// ---------------- deterministic compaction ------------
__global__ __launch_bounds__(256) void count_k()
{
    __shared__ unsigned wsum[8];
    int n = blockIdx.x * 256 + threadIdx.x;
    unsigned T = g_state[0];
    bool pred = (n < NBOX) && (g_key[n] < T);
    unsigned bal = __ballot_sync(0xFFFFFFFFu, pred);
    if ((threadIdx.x & 31) == 0) wsum[threadIdx.x >> 5] = (unsigned)__popc(bal);
    __syncthreads();
    if (threadIdx.x == 0) {
        unsigned s = 0;
#pragma unroll
        for (int w = 0; w < 8; w++) s += wsum[w];
        g_bcnt[blockIdx.x] = s;
    }
}

#define SCCH 6
__global__ __launch_bounds__(256) void scanb_k()
{
    __shared__ unsigned ssum[256];
    int t = threadIdx.x;
    unsigned loc[SCCH];
    unsigned s = 0;
#pragma unroll
    for (int e = 0; e < SCCH; e++) {
        int idx = t * SCCH + e;
        loc[e] = (idx < NBLK) ? g_bcnt[idx] : 0u;
        s += loc[e];
    }
    ssum[t] = s;
    __syncthreads();
    if (t == 0) {
        unsigned acc = 0;
        for (int i = 0; i < 256; i++) { unsigned tmp = ssum[i]; ssum[i] = acc; acc += tmp; }
        g_cnt = (int)acc;
    }
    __syncthreads();
    unsigned run = ssum[t];
#pragma unroll
    for (int e = 0; e < SCCH; e++) {
        int idx = t * SCCH + e;
        if (idx < NBLK) g_boff[idx] = run;
        run += loc[e];
    }
}

__global__ __launch_bounds__(256) void place_k()
{
    __shared__ unsigned wcnt[8];
    __shared__ unsigned wex[8];
    int t = threadIdx.x;
    int n = blockIdx.x * 256 + t;
    unsigned T = g_state[0];
    unsigned K = (n < NBOX) ? g_key[n] : 0xFFFFFFFFu;
    bool pred = (n < NBOX) && (K < T);
    unsigned bal = __ballot_sync(0xFFFFFFFFu, pred);
    int lane = t & 31, w = t >> 5;
    if (lane == 0) wcnt[w] = (unsigned)__popc(bal);
    __syncthreads();
    if (t == 0) {
        unsigned a = 0;
#pragma unroll
        for (int i = 0; i < 8; i++) { wex[i] = a; a += wcnt[i]; }
    }
    __syncthreads();
    if (pred) {
        unsigned rank = g_boff[blockIdx.x] + wex[w] +
                        (unsigned)__popc(bal & ((1u << lane) - 1u));
        g_cand[rank] = ((unsigned long long)K << 32) | (unsigned)n;
    }
    if ((n < NBOX) && (K == T))
        atomicOr(&g_tiebm[n >> 5], 1u << (n & 31));
}

__global__ void tie_select_k()
{
    const int lane = threadIdx.x;
    const int base = g_cnt;
    const unsigned r = g_state[1];
    const unsigned T = g_state[0];
    unsigned taken = 0;
    for (int w0 = 0; w0 < TIE_WORDS && taken < r; w0 += 32) {
        int wi = w0 + lane;
        unsigned word = (wi < TIE_WORDS) ? g_tiebm[wi] : 0u;
        int cnt = __popc(word);
        int pre = cnt;
#pragma unroll
        for (int o = 1; o < 32; o <<= 1) {
            int v = __shfl_up_sync(0xFFFFFFFFu, pre, o);
            if (lane >= o) pre += v;
        }
        unsigned rank = taken + (unsigned)(pre - cnt);
        while (word && rank < r) {
            int b = __ffs(word) - 1;
            word &= word - 1;
            unsigned n = (unsigned)wi * 32u + (unsigned)b;
            g_cand[base + rank] = ((unsigned long long)T << 32) | n;
            rank++;
        }
        taken += (unsigned)__shfl_sync(0xFFFFFFFFu, pre, 31);
    }
}

// ---------------- single-block bitonic sort + gather ----------
extern __shared__ unsigned long long s_sort[];
__global__ void sort_topk_k()
{
    const int t = threadIdx.x;
    for (int i = t; i < SORTN; i += 1024)
        s_sort[i] = (i < PRE_NMS) ? g_cand[i] : 0xFFFFFFFFFFFFFFFFull;
    __syncthreads();
    for (int k = 2; k <= SORTN; k <<= 1) {
        for (int j = k >> 1; j > 0; j >>= 1) {
            for (int i = t; i < SORTN; i += 1024) {
                int ixj = i ^ j;
                if (ixj > i) {
                    unsigned long long a = s_sort[i], b = s_sort[ixj];
                    bool up = ((i & k) == 0);
                    if ((a > b) == up) { s_sort[i] = b; s_sort[ixj] = a; }
                }
            }
            __syncthreads();
        }
    }
    for (int i = t; i < 6144; i += 1024) {
        bool valid = false;
        if (i < PRE_NMS) {
            unsigned long long v = s_sort[i];
            unsigned K = (unsigned)(v >> 32);
            unsigned n = (unsigned)v;
            float b0 = 0, b1 = 0, b2 = 0, b3 = 0;
            if (n < (unsigned)NBOX) {
                const float4 bb = *reinterpret_cast<const float4*>(&g_roi[(size_t)n * 4]);
                b0 = bb.x; b1 = bb.y; b2 = bb.z; b3 = bb.w;
                valid = (K < 0x80000000u);
            }
            g_nb[(size_t)i * 4 + 0] = b0;
            g_nb[(size_t)i * 4 + 1] = b1;
            g_nb[(size_t)i * 4 + 2] = b2;
            g_nb[(size_t)i * 4 + 3] = b3;
        }
        unsigned bal = __ballot_sync(0xFFFFFFFFu, valid);
        if ((t & 31) == 0) g_keep_init[i >> 5] = bal;
    }
}

// ---------------- NMS suppression bitmask ----------------
__global__ __launch_bounds__(MASK_W) void mask_k()
{
    const int i = blockIdx.x;
    const int w = threadIdx.x;
    const float4* nb4 = reinterpret_cast<const float4*>(g_nb);
    float4 bi = nb4[i];
    float ai = (bi.z - bi.x) * (bi.w - bi.y);
    unsigned bits = 0;
    int jbase = w * 32;
#pragma unroll 4
    for (int b = 0; b < 32; b++) {
        int j = jbase + b;
        if (j > i && j < PRE_NMS) {
            float4 bj = nb4[j];
            float xx1 = fmaxf(bi.x, bj.x), yy1 = fmaxf(bi.y, bj.y);
            float xx2 = fminf(bi.z, bj.z), yy2 = fminf(bi.w, bj.w);
            float inter = fmaxf(xx2 - xx1, 0.f) * fmaxf(yy2 - yy1, 0.f);
            float aj = (bj.z - bj.x) * (bj.w - bj.y);
            float iou = inter / (ai + aj - inter + 1e-12f);
            if (iou > IOU_THR) bits |= (1u << b);
        }
    }
    g_mask[(size_t)i * MASK_W + w] = bits;
}

// ---------------- sequential greedy scan (single warp, early exit) ---------
__global__ void nms_scan_k()
{
    const int lane = threadIdx.x;
    unsigned kw[6];
#pragma unroll
    for (int q = 0; q < 6; q++) kw[q] = g_keep_init[q * 32 + lane];

    unsigned total = 0;
    bool done = false;
    for (int q = 0; q < 6 && !done; q++) {
        const int iend = (q == 5) ? (PRE_NMS - 5 * 1024) : 1024;
        for (int ii = 0; ii < iend; ii++) {
            int i = q * 1024 + ii;
            unsigned word = __shfl_sync(0xFFFFFFFFu, kw[q], (i >> 5) & 31);
            if ((word >> (i & 31)) & 1u) {
                const unsigned* row = &g_mask[(size_t)i * MASK_W];
#pragma unroll
                for (int r = 0; r < 6; r++) kw[r] &= ~row[r * 32 + lane];
            }
            if ((ii & 255) == 255) {
                int nproc = (ii + 1) >> 5;
                unsigned c = (lane < nproc) ? (unsigned)__popc(kw[q]) : 0u;
#pragma unroll
                for (int o = 16; o > 0; o >>= 1)
                    c += __shfl_xor_sync(0xFFFFFFFFu, c, o);
                if (total + c >= POST_NMS) {
                    if (lane >= nproc) kw[q] = 0;
                    for (int r = q + 1; r < 6; r++) kw[r] = 0;
                    done = true;
                    break;
                }
                if (nproc == 32) total += c;
            }
        }
    }
#pragma unroll
    for (int q = 0; q < 6; q++) g_keep_fin[q * 32 + lane] = kw[q];
}

// ---------------- write rois ----------------
__global__ __launch_bounds__(256) void write_rois_k(float* __restrict__ out)
{
    float* rois = out + ROI_OFF;
    __shared__ unsigned woff[MASK_W];
    int t = threadIdx.x;
    for (int i = t; i < POST_NMS * 4; i += 256) rois[i] = 0.f;
    if (t < MASK_W) woff[t] = (unsigned)__popc(g_keep_fin[t]);
    __syncthreads();
    if (t == 0) {
        unsigned acc = 0;
        for (int i = 0; i < MASK_W; i++) { unsigned tmp = woff[i]; woff[i] = acc; acc += tmp; }
    }
    __syncthreads();
    if (t < MASK_W) {
        unsigned word = g_keep_fin[t];
        unsigned rank = woff[t];
        while (word) {
            int b = __ffs(word) - 1;
            word &= word - 1;
            if (rank < POST_NMS) {
                int i = t * 32 + b;
                rois[rank * 4 + 0] = g_nb[(size_t)i * 4 + 0];
                rois[rank * 4 + 1] = g_nb[(size_t)i * 4 + 1];
                rois[rank * 4 + 2] = g_nb[(size_t)i * 4 + 2];
                rois[rank * 4 + 3] = g_nb[(size_t)i * 4 + 3];
            }
            rank++;
        }
    }
}

// ---------------- launcher ----------------
extern "C" void kernel_launch(void* const* d_in, const int* in_sizes, int n_in,
                              void* d_out, int out_size)
{
    const float* features = (const float*)d_in[0];
    const float* anchor   = (const float*)d_in[1];
    const float* w1       = (const float*)d_in[2];
    const float* b1       = (const float*)d_in[3];
    const float* wc       = (const float*)d_in[4];
    const float* bc       = (const float*)d_in[5];
    const float* wl       = (const float*)d_in[6];
    const float* bl       = (const float*)d_in[7];
    float* out = (float*)d_out;

    cudaFuncSetAttribute(sort_topk_k,
                         cudaFuncAttributeMaxDynamicSharedMemorySize,
                         SORTN * sizeof(unsigned long long));
    cudaFuncSetAttribute(gemm_k,
                         cudaFuncAttributeMaxDynamicSharedMemorySize,
                         CONV_SMEM);

    init_k<<<48, 256>>>();
    initb_k<<<48, 256>>>();

    wtrans_k<<<(CIN * CIN + 255) / 256, 256>>>(w1);
    xtrans_k<<<dim3((NTILES + 255) / 256, CIN), 256>>>(features);

    gemm_k<<<dim3(NTB, CIN / MTILE, 16), 256, CONV_SMEM>>>();

    otrans_k<<<dim3((NTILES + 255) / 256, CIN), 256>>>(b1);

    conv1x1_k<<<(NPIX + PXT - 1) / PXT, 256>>>(wc, bc, wl, bl, out);

    decode_k<<<(NBOX + 255) / 256, 256>>>(anchor);

    hist_k<<<512, 256>>>(0, 24u, 0x00000000u);
    scan_k<<<1, 32>>>(0, 24u);
    hist_k<<<512, 256>>>(1, 16u, 0xFF000000u);
    scan_k<<<1, 32>>>(1, 16u);
    hist_k<<<512, 256>>>(2,  8u, 0xFFFF0000u);
    scan_k<<<1, 32>>>(2,  8u);
    hist_k<<<512, 256>>>(3,  0u, 0xFFFFFF00u);
    scan_k<<<1, 32>>>(3,  0u);

    count_k<<<NBLK, 256>>>();
    scanb_k<<<1, 256>>>();
    place_k<<<NBLK, 256>>>();
    tie_select_k<<<1, 32>>>();

    sort_topk_k<<<1, 1024, SORTN * sizeof(unsigned long long)>>>();

    mask_k<<<PRE_NMS, MASK_W>>>();

    nms_scan_k<<<1, 32>>>();

    write_rois_k<<<1, 256>>>(out);
}

// round 14
// speedup vs baseline: 4.7272x; 1.2062x over previous
#include <cuda_runtime.h>
#include <cuda_bf16.h>
#include <cuda_fp16.h>
#include <math.h>
#include <cstdint>

// ---------------- problem constants ----------------
#define HH 200
#define WW 200
#define NPIX (HH*WW)            // 40000
#define CIN 512
#define AA 9
#define NBOX (NPIX*AA)          // 360000
#define PRE_NMS 6000
#define POST_NMS 300
#define MIN_SIZE (16.0f/1000.0f)
#define IOU_THR 0.7f

#define CLS_OFF 0
#define LOC_OFF (NBOX*2)        // 720000
#define ROI_OFF (NBOX*2 + NBOX*4)  // 2160000

#define MASK_W 192
#define SORTN 8192
#define TIE_WORDS ((NBOX + 31) / 32)   // 11250
#define NBLK 1407               // ceil(NBOX/256)

// ---- Winograd F(2x2,3x3) GEMM geometry ----
#define NT1D 100                // tiles per axis
#define NTILES (NT1D*NT1D)      // 10000
#define UVW (CIN*CIN)           // 262144 (per-uv weight plane)
#define UVX ((size_t)CIN*NTILES) // 5120000 (per-uv data plane)
#define KC 32
#define GCH (CIN/KC)            // 16 K-chunks per GEMM
#define DRAIN 2
#define MTILE 128
#define NTILE 128
#define NTB ((NTILES + NTILE - 1)/NTILE)  // 79
#define PITCH 40                // fp16 elems per smem row (80 B)
#define SPLIT_B (128*PITCH*2)   // 10240 bytes per split tile
#define BS_OFF  (2*SPLIT_B)
#define BUF_B   (4*SPLIT_B)     // one buffer: 2 A splits + 2 B splits
#define CONV_SMEM (2*BUF_B)     // 81920 bytes, double-buffered

// fp16 2-split scaling (exact pow2; epilogue rescales by 2^-24)
#define XSCALE 1024.0f          // 2^10
#define WSCALE 16384.0f         // 2^14
#define OSCALE (1.0f/16777216.0f)

// ---------------- scratch (device globals) ------------
__device__ float g_x[(size_t)CIN * NPIX];
__device__ __align__(16) __half g_wu[2][(size_t)16 * UVW];   // U splits [uv][co][ci]
__device__ __align__(16) __half g_xv[2][(size_t)16 * UVX];   // V splits [uv][tile][ci]
__device__ float g_m[(size_t)16 * UVX];                      // M fp32 [uv][co][tile]
__device__ float g_cls[(size_t)NBOX * 2];
__device__ float g_loc[(size_t)NBOX * 4];
__device__ __align__(16) float g_roi[(size_t)NBOX * 4];
__device__ unsigned g_key[NBOX];
__device__ unsigned g_hist[4 * 256];
__device__ unsigned g_state[2];
__device__ int g_cnt;
__device__ unsigned g_bcnt[NBLK + 1];
__device__ unsigned g_boff[NBLK + 1];
__device__ unsigned long long g_cand[SORTN];
__device__ unsigned g_tiebm[TIE_WORDS];
__device__ __align__(16) float g_nb[6144 * 4];
__device__ unsigned g_keep_init[MASK_W];
__device__ unsigned g_keep_fin[MASK_W];
__device__ unsigned g_mask[(size_t)PRE_NMS * MASK_W];

// ---------------- PTX helpers ----------------
__device__ __forceinline__ uint32_t smem_u32(const void* p) {
    uint32_t a;
    asm("{ .reg .u64 t; cvta.to.shared.u64 t, %1; cvt.u32.u64 %0, t; }" : "=r"(a) : "l"(p));
    return a;
}
__device__ __forceinline__ void ldsm_x4(unsigned* r, uint32_t addr) {
    asm volatile("ldmatrix.sync.aligned.m8n8.x4.shared.b16 {%0,%1,%2,%3}, [%4];"
        : "=r"(r[0]), "=r"(r[1]), "=r"(r[2]), "=r"(r[3]) : "r"(addr));
}
__device__ __forceinline__ void ldsm_x2(unsigned* r, uint32_t addr) {
    asm volatile("ldmatrix.sync.aligned.m8n8.x2.shared.b16 {%0,%1}, [%2];"
        : "=r"(r[0]), "=r"(r[1]) : "r"(addr));
}
__device__ __forceinline__ void mma16816h(float* d, const unsigned* a, const unsigned* b) {
    asm volatile(
        "mma.sync.aligned.m16n8k16.row.col.f32.f16.f16.f32 "
        "{%0,%1,%2,%3}, {%4,%5,%6,%7}, {%8,%9}, {%0,%1,%2,%3};"
        : "+f"(d[0]), "+f"(d[1]), "+f"(d[2]), "+f"(d[3])
        : "r"(a[0]), "r"(a[1]), "r"(a[2]), "r"(a[3]), "r"(b[0]), "r"(b[1]));
}

// ---------------- init ----------------
__global__ void init_k() {
    int t = blockIdx.x * 256 + threadIdx.x;
    const int STRIDE = 48 * 256;
    for (int i = t; i < 4 * 256; i += STRIDE) g_hist[i] = 0;
    for (int i = t; i < TIE_WORDS; i += STRIDE) g_tiebm[i] = 0;
    for (int i = t; i < SORTN; i += STRIDE) g_cand[i] = 0xFFFFFFFFFFFFFFFFull;
}
__global__ void initb_k() {
    int t = blockIdx.x * 256 + threadIdx.x;
    const int STRIDE = 48 * 256;
    for (int i = t; i < NBLK + 1; i += STRIDE) { g_bcnt[i] = 0; g_boff[i] = 0; }
    for (int i = t; i < MASK_W; i += STRIDE) { g_keep_init[i] = 0; g_keep_fin[i] = 0; }
    if (t == 0) { g_cnt = 0; g_state[0] = 0u; g_state[1] = PRE_NMS; }
}

// ---------------- fp32 -> 2x fp16 split (value pre-scaled) -----------
__device__ __forceinline__ void split2h(float vs, __half& h0, __half& h1) {
    h0 = __float2half_rn(vs);
    h1 = __float2half_rn(vs - __half2float(h0));
}

// ---------------- weight transform: U = G g G^T, scaled + split -----------
__global__ __launch_bounds__(256) void wtrans_k(const float* __restrict__ w1)
{
    int n = blockIdx.x * 256 + threadIdx.x;
    if (n >= CIN * CIN) return;
    const float* wp = w1 + (size_t)n * 9;   // [co][ci][3][3]
    float g[9];
#pragma unroll
    for (int i = 0; i < 9; i++) g[i] = wp[i];
    float T[4][3];
#pragma unroll
    for (int c = 0; c < 3; c++) {
        T[0][c] = g[c];
        T[1][c] = 0.5f * (g[c] + g[3 + c] + g[6 + c]);
        T[2][c] = 0.5f * (g[c] - g[3 + c] + g[6 + c]);
        T[3][c] = g[6 + c];
    }
#pragma unroll
    for (int r = 0; r < 4; r++) {
        float u[4];
        u[0] = T[r][0];
        u[1] = 0.5f * (T[r][0] + T[r][1] + T[r][2]);
        u[2] = 0.5f * (T[r][0] - T[r][1] + T[r][2]);
        u[3] = T[r][2];
#pragma unroll
        for (int c = 0; c < 4; c++) {
            __half h0, h1;
            split2h(u[c] * WSCALE, h0, h1);
            size_t idx = (size_t)(r * 4 + c) * UVW + n;
            g_wu[0][idx] = h0;
            g_wu[1][idx] = h1;
        }
    }
}

// ---------------- input transform: V = B^T d B, scaled + split -------------
// Output layout [uv][tile][ci] (GEMM-friendly). Block = 16 tiles x 16 ci with
// a padded smem transpose so global writes stay coalesced (32B runs).
__global__ __launch_bounds__(256) void xtrans_k(const float* __restrict__ f)
{
    __shared__ __half s_v[32][16 * 17];   // [s*16+uv][tl*17 + cl]
    const int t = threadIdx.x;
    const int tl = t & 15;                // tile local
    const int cl = t >> 4;                // ci local
    const int tile0 = blockIdx.x * 16;
    const int ci0 = blockIdx.y * 16;
    const int tile = tile0 + tl;          // NTILES = 625*16 exact
    const int ci = ci0 + cl;

    int ty = tile / NT1D, tx = tile - ty * NT1D;
    int y0 = 2 * ty - 1, x0 = 2 * tx - 1;
    const float* fc = f + (size_t)ci * NPIX;
    float d[4][4];
#pragma unroll
    for (int r = 0; r < 4; r++) {
        int y = y0 + r;
#pragma unroll
        for (int c = 0; c < 4; c++) {
            int x = x0 + c;
            d[r][c] = ((unsigned)y < (unsigned)HH && (unsigned)x < (unsigned)WW)
                      ? fc[y * WW + x] : 0.f;
        }
    }
    float P[4][4];
#pragma unroll
    for (int c = 0; c < 4; c++) {
        P[0][c] = d[0][c] - d[2][c];
        P[1][c] = d[1][c] + d[2][c];
        P[2][c] = d[2][c] - d[1][c];
        P[3][c] = d[1][c] - d[3][c];
    }
#pragma unroll
    for (int r = 0; r < 4; r++) {
        float v[4];
        v[0] = P[r][0] - P[r][2];
        v[1] = P[r][1] + P[r][2];
        v[2] = P[r][2] - P[r][1];
        v[3] = P[r][1] - P[r][3];
#pragma unroll
        for (int c = 0; c < 4; c++) {
            __half h0, h1;
            split2h(v[c] * XSCALE, h0, h1);
            int uv = r * 4 + c;
            s_v[uv][tl * 17 + cl] = h0;
            s_v[16 + uv][tl * 17 + cl] = h1;
        }
    }
    __syncthreads();
    // writeout: thread t -> (tile row t>>4, ci col t&15) of each plane
    const int tl2 = t >> 4, cl2 = t & 15;
#pragma unroll
    for (int p = 0; p < 32; p++) {
        int s = p >> 4, uv = p & 15;
        g_xv[s][(size_t)uv * UVX + (size_t)(tile0 + tl2) * CIN + ci0 + cl2] =
            s_v[p][tl2 * 17 + cl2];
    }
}

// ---------------- Winograd GEMM: M(uv) = U(uv) x V(uv), fp16x2 3-product ---
// CTA: 128co x 128tiles, 8 warps (warp tile 64x32), K=512 in 16 chunks.
// Double-buffered; A and B staging both wide (LDG.128 -> STS.128).
__global__ __launch_bounds__(256) void gemm_k()
{
    extern __shared__ __align__(16) char smem[];
    const uint32_t sb = smem_u32(smem);
    const int t = threadIdx.x;
    const int w = t >> 5, lane = t & 31;
    const int t0 = blockIdx.x * NTILE;
    const int co0 = blockIdx.y * MTILE;
    const int uv = blockIdx.z;
    const int mw = (w & 1) * 64;
    const int nw = (w >> 1) * 32;

    float acc[4][4][4];
    float accm[4][4][4];
#pragma unroll
    for (int mt = 0; mt < 4; mt++)
#pragma unroll
        for (int nt = 0; nt < 4; nt++)
#pragma unroll
            for (int e = 0; e < 4; e++) { acc[mt][nt][e] = 0.f; accm[mt][nt][e] = 0.f; }

    const int arow = t >> 1, ahalf = t & 1;   // staging: 2 thr/row, 16 fp16 each
    const int bgt = t0 + arow;                // B global tile for this thread
    const bool bok = bgt < NTILES;
    const uint32_t a_lb = (uint32_t)(((lane & 7) + ((lane >> 3) & 1) * 8) * (PITCH * 2)
                                     + (lane >> 4) * 16);
    const uint32_t b_lb = (uint32_t)((lane & 7) * (PITCH * 2) + ((lane >> 3) & 1) * 16);

    uint4 aR[2][2];
    uint4 bR[2][2];

    auto prefetch = [&](int c) {
        const int k0 = c * KC;
#pragma unroll
        for (int s = 0; s < 2; s++) {
            const uint4* srcA = (const uint4*)&g_wu[s][(size_t)uv * UVW
                                + (size_t)(co0 + arow) * CIN + k0 + ahalf * 16];
            aR[s][0] = srcA[0];
            aR[s][1] = srcA[1];
            if (bok) {
                const uint4* srcB = (const uint4*)&g_xv[s][(size_t)uv * UVX
                                    + (size_t)bgt * CIN + k0 + ahalf * 16];
                bR[s][0] = srcB[0];
                bR[s][1] = srcB[1];
            } else {
                bR[s][0] = make_uint4(0, 0, 0, 0);
                bR[s][1] = make_uint4(0, 0, 0, 0);
            }
        }
    };

    auto store_stage = [&](char* base) {
#pragma unroll
        for (int s = 0; s < 2; s++) {
            uint4* dstA = (uint4*)(base + s * SPLIT_B + arow * (PITCH * 2) + ahalf * 32);
            dstA[0] = aR[s][0];
            dstA[1] = aR[s][1];
            uint4* dstB = (uint4*)(base + BS_OFF + s * SPLIT_B
                                   + arow * (PITCH * 2) + ahalf * 32);
            dstB[0] = bR[s][0];
            dstB[1] = bR[s][1];
        }
    };

    auto compute = [&](uint32_t bufb) {
#pragma unroll
        for (int ks = 0; ks < 2; ks++) {
            const uint32_t koff = (uint32_t)(ks * 32);
            unsigned af0[4][4], af1[4][4];
#pragma unroll
            for (int mt = 0; mt < 4; mt++) {
                uint32_t ab = bufb + (uint32_t)((mw + mt * 16) * (PITCH * 2)) + a_lb + koff;
                ldsm_x4(af0[mt], ab);
                ldsm_x4(af1[mt], ab + SPLIT_B);
            }
            {
                unsigned bf[4][2];
#pragma unroll
                for (int nt = 0; nt < 4; nt++)
                    ldsm_x2(bf[nt], bufb + BS_OFF
                            + (uint32_t)((nw + nt * 8) * (PITCH * 2)) + b_lb + koff);
#pragma unroll
                for (int mt = 0; mt < 4; mt++)
#pragma unroll
                    for (int nt = 0; nt < 4; nt++) {
                        mma16816h(acc[mt][nt], af0[mt], bf[nt]);
                        mma16816h(acc[mt][nt], af1[mt], bf[nt]);
                    }
            }
            {
                unsigned bf[4][2];
#pragma unroll
                for (int nt = 0; nt < 4; nt++)
                    ldsm_x2(bf[nt], bufb + BS_OFF + SPLIT_B
                            + (uint32_t)((nw + nt * 8) * (PITCH * 2)) + b_lb + koff);
#pragma unroll
                for (int mt = 0; mt < 4; mt++)
#pragma unroll
                    for (int nt = 0; nt < 4; nt++)
                        mma16816h(acc[mt][nt], af0[mt], bf[nt]);
            }
        }
    };

    // prologue: fill buffer 0
    prefetch(0);
    store_stage(smem);
    __syncthreads();

    for (int c = 0; c < GCH; c++) {
        const int cur = c & 1;
        if (c + 1 < GCH) prefetch(c + 1);          // LDGs fly under compute
        compute(sb + cur * BUF_B);                  // read buf[cur]
        if (c + 1 < GCH) store_stage(smem + (cur ^ 1) * BUF_B);  // write other buf
        __syncthreads();                            // hand off both buffers

        if ((c % DRAIN) == (DRAIN - 1)) {
#pragma unroll
            for (int mt = 0; mt < 4; mt++)
#pragma unroll
                for (int nt = 0; nt < 4; nt++)
#pragma unroll
                    for (int e = 0; e < 4; e++) {
                        accm[mt][nt][e] += acc[mt][nt][e];
                        acc[mt][nt][e] = 0.f;
                    }
        }
    }

    // epilogue: raw scaled fp32 -> g_m[uv][co][tile] (paired 64-bit stores)
    float* mplane = g_m + (size_t)uv * UVX;
#pragma unroll
    for (int mt = 0; mt < 4; mt++) {
        int r0 = co0 + mw + mt * 16 + (lane >> 2);
#pragma unroll
        for (int nt = 0; nt < 4; nt++) {
            int col = t0 + nw + nt * 8 + (lane & 3) * 2;
            if (col + 1 < NTILES) {
                *(float2*)&mplane[(size_t)r0 * NTILES + col] =
                    make_float2(accm[mt][nt][0], accm[mt][nt][1]);
                *(float2*)&mplane[(size_t)(r0 + 8) * NTILES + col] =
                    make_float2(accm[mt][nt][2], accm[mt][nt][3]);
            } else if (col < NTILES) {
                mplane[(size_t)r0 * NTILES + col] = accm[mt][nt][0];
                mplane[(size_t)(r0 + 8) * NTILES + col] = accm[mt][nt][2];
            }
        }
    }
}

// ---------------- output transform: Y = A^T M A, rescale + bias + relu -----
__global__ __launch_bounds__(256) void otrans_k(const float* __restrict__ b1)
{
    int tile = blockIdx.x * 256 + threadIdx.x;
    if (tile >= NTILES) return;
    int co = blockIdx.y;
    float m[16];
#pragma unroll
    for (int uv = 0; uv < 16; uv++)
        m[uv] = g_m[(size_t)uv * UVX + (size_t)co * NTILES + tile];
    float Z[2][4];
#pragma unroll
    for (int v = 0; v < 4; v++) {
        Z[0][v] = m[v] + m[4 + v] + m[8 + v];
        Z[1][v] = m[4 + v] - m[8 + v] - m[12 + v];
    }
    float bias = b1[co];
    int ty = tile / NT1D, tx = tile - ty * NT1D;
    float* gx = g_x + (size_t)co * NPIX;
#pragma unroll
    for (int i = 0; i < 2; i++) {
        float y0 = (Z[i][0] + Z[i][1] + Z[i][2]) * OSCALE + bias;
        float y1 = (Z[i][1] - Z[i][2] - Z[i][3]) * OSCALE + bias;
        int row = 2 * ty + i;
        gx[row * WW + 2 * tx]     = y0 > 0.f ? y0 : 0.f;
        gx[row * WW + 2 * tx + 1] = y1 > 0.f ? y1 : 0.f;
    }
}

// ---------------- 1x1 heads (cls 18 + loc 36) ----------------
#define PXT 128
#define OC 64
#define CKB 16
__global__ __launch_bounds__(256) void conv1x1_k(
    const float* __restrict__ wc, const float* __restrict__ bc,
    const float* __restrict__ wl, const float* __restrict__ bl,
    float* __restrict__ out)
{
    __shared__ float s_x[CKB][PXT];
    __shared__ float s_w[OC][CKB];
    const int p0 = blockIdx.x * PXT;
    const int t = threadIdx.x;
    const int cg = t >> 4;
    const int pg = t & 15;

    float acc[4][8];
#pragma unroll
    for (int k = 0; k < 4; k++)
#pragma unroll
        for (int j = 0; j < 8; j++) acc[k][j] = 0.f;

    for (int cb = 0; cb < CIN; cb += CKB) {
        __syncthreads();
        for (int i = t; i < CKB * PXT; i += 256) {
            int ci = i >> 7, pp = i & 127;
            int p = p0 + pp;
            s_x[ci][pp] = (p < NPIX) ? g_x[(size_t)(cb + ci) * NPIX + p] : 0.f;
        }
        for (int i = t; i < OC * CKB; i += 256) {
            int co = i >> 4, ci = i & 15;
            float v = 0.f;
            if (co < 18) v = wc[(size_t)co * CIN + cb + ci];
            else if (co < 54) v = wl[(size_t)(co - 18) * CIN + cb + ci];
            s_w[co][ci] = v;
        }
        __syncthreads();
#pragma unroll 4
        for (int ci = 0; ci < CKB; ci++) {
            float xv[8];
#pragma unroll
            for (int j = 0; j < 8; j++) xv[j] = s_x[ci][pg * 8 + j];
#pragma unroll
            for (int k = 0; k < 4; k++) {
                float wv = s_w[cg * 4 + k][ci];
#pragma unroll
                for (int j = 0; j < 8; j++)
                    acc[k][j] = fmaf(wv, xv[j], acc[k][j]);
            }
        }
    }

#pragma unroll
    for (int k = 0; k < 4; k++) {
        int co = cg * 4 + k;
#pragma unroll
        for (int j = 0; j < 8; j++) {
            int p = p0 + pg * 8 + j;
            if (p < NPIX) {
                if (co < 18) {
                    float v = acc[k][j] + bc[co];
                    out[CLS_OFF + (size_t)p * 18 + co] = v;
                    g_cls[(size_t)p * 18 + co] = v;
                } else if (co < 54) {
                    float v = acc[k][j] + bl[co - 18];
                    out[LOC_OFF + (size_t)p * 36 + (co - 18)] = v;
                    g_loc[(size_t)p * 36 + (co - 18)] = v;
                }
            }
        }
    }
}

// ---------------- decode boxes + scores + sort keys ----------------
__global__ void decode_k(const float* __restrict__ anchor)
{
    int n = blockIdx.x * 256 + threadIdx.x;
    if (n >= NBOX) return;
    float a0 = anchor[(size_t)n * 4 + 0], a1 = anchor[(size_t)n * 4 + 1];
    float a2 = anchor[(size_t)n * 4 + 2], a3 = anchor[(size_t)n * 4 + 3];
    float aw = a2 - a0, ah = a3 - a1;
    float acx = (a0 + a2) * 0.5f, acy = (a1 + a3) * 0.5f;
    float l0 = g_loc[(size_t)n * 4 + 0];
    float l1 = g_loc[(size_t)n * 4 + 1];
    float l2 = g_loc[(size_t)n * 4 + 2];
    float l3 = g_loc[(size_t)n * 4 + 3];
    float cx = l0 * aw + acx, cy = l1 * ah + acy;
    float bw = expf(l2) * aw, bh = expf(l3) * ah;
    float x1 = fminf(fmaxf(cx - bw * 0.5f, 0.f), 1.f);
    float y1 = fminf(fmaxf(cy - bh * 0.5f, 0.f), 1.f);
    float x2 = fminf(fmaxf(cx + bw * 0.5f, 0.f), 1.f);
    float y2 = fminf(fmaxf(cy + bh * 0.5f, 0.f), 1.f);
    g_roi[(size_t)n * 4 + 0] = x1;
    g_roi[(size_t)n * 4 + 1] = y1;
    g_roi[(size_t)n * 4 + 2] = x2;
    g_roi[(size_t)n * 4 + 3] = y2;

    float c0 = g_cls[(size_t)n * 2 + 0];
    float c1 = g_cls[(size_t)n * 2 + 1];
    float s = 1.f / (1.f + expf(c0 - c1));
    bool valid = ((y2 - y1) >= MIN_SIZE) && ((x2 - x1) >= MIN_SIZE);
    float sc = valid ? s : -1.0f;

    unsigned b = __float_as_uint(sc);
    unsigned ord = (b & 0x80000000u) ? ~b : (b | 0x80000000u);
    g_key[n] = ~ord;
}

// ---------------- 4-pass MSD radix select ----------------
__global__ void hist_k(int pass, unsigned shift, unsigned pmask)
{
    __shared__ unsigned h[256];
    int t = threadIdx.x;
    for (int i = t; i < 256; i += 256) h[i] = 0;
    __syncthreads();
    unsigned prefix = g_state[0];
    for (int n = blockIdx.x * 256 + t; n < NBOX; n += gridDim.x * 256) {
        unsigned K = g_key[n];
        if ((K & pmask) == prefix) atomicAdd(&h[(K >> shift) & 255u], 1u);
    }
    __syncthreads();
    unsigned* hist = &g_hist[pass * 256];
    for (int i = t; i < 256; i += 256)
        if (h[i]) atomicAdd(&hist[i], h[i]);
}

__global__ void scan_k(int pass, unsigned shift)
{
    if (threadIdx.x == 0) {
        const unsigned* hist = &g_hist[pass * 256];
        unsigned k = g_state[1];
        unsigned cum = 0;
        int d = 0;
        for (; d < 256; d++) {
            if (cum + hist[d] >= k) break;
            cum += hist[d];
        }
        if (d > 255) d = 255;
        g_state[0] |= ((unsigned)d) << shift;
        g_state[1] = k - cum;
    }
}

// ---------------- deterministic compaction ------------
__global__ __launch_bounds__(256) void count_k()
{
    __shared__ unsigned wsum[8];
    int n = blockIdx.x * 256 + threadIdx.x;
    unsigned T = g_state[0];
    bool pred = (n < NBOX) && (g_key[n] < T);
    unsigned bal = __ballot_sync(0xFFFFFFFFu, pred);
    if ((threadIdx.x & 31) == 0) wsum[threadIdx.x >> 5] = (unsigned)__popc(bal);
    __syncthreads();
    if (threadIdx.x == 0) {
        unsigned s = 0;
#pragma unroll
        for (int w = 0; w < 8; w++) s += wsum[w];
        g_bcnt[blockIdx.x] = s;
    }
}

#define SCCH 6
__global__ __launch_bounds__(256) void scanb_k()
{
    __shared__ unsigned ssum[256];
    int t = threadIdx.x;
    unsigned loc[SCCH];
    unsigned s = 0;
#pragma unroll
    for (int e = 0; e < SCCH; e++) {
        int idx = t * SCCH + e;
        loc[e] = (idx < NBLK) ? g_bcnt[idx] : 0u;
        s += loc[e];
    }
    ssum[t] = s;
    __syncthreads();
    if (t == 0) {
        unsigned acc = 0;
        for (int i = 0; i < 256; i++) { unsigned tmp = ssum[i]; ssum[i] = acc; acc += tmp; }
        g_cnt = (int)acc;
    }
    __syncthreads();
    unsigned run = ssum[t];
#pragma unroll
    for (int e = 0; e < SCCH; e++) {
        int idx = t * SCCH + e;
        if (idx < NBLK) g_boff[idx] = run;
        run += loc[e];
    }
}

__global__ __launch_bounds__(256) void place_k()
{
    __shared__ unsigned wcnt[8];
    __shared__ unsigned wex[8];
    int t = threadIdx.x;
    int n = blockIdx.x * 256 + t;
    unsigned T = g_state[0];
    unsigned K = (n < NBOX) ? g_key[n] : 0xFFFFFFFFu;
    bool pred = (n < NBOX) && (K < T);
    unsigned bal = __ballot_sync(0xFFFFFFFFu, pred);
    int lane = t & 31, w = t >> 5;
    if (lane == 0) wcnt[w] = (unsigned)__popc(bal);
    __syncthreads();
    if (t == 0) {
        unsigned a = 0;
#pragma unroll
        for (int i = 0; i < 8; i++) { wex[i] = a; a += wcnt[i]; }
    }
    __syncthreads();
    if (pred) {
        unsigned rank = g_boff[blockIdx.x] + wex[w] +
                        (unsigned)__popc(bal & ((1u << lane) - 1u));
        g_cand[rank] = ((unsigned long long)K << 32) | (unsigned)n;
    }
    if ((n < NBOX) && (K == T))
        atomicOr(&g_tiebm[n >> 5], 1u << (n & 31));
}

__global__ void tie_select_k()
{
    const int lane = threadIdx.x;
    const int base = g_cnt;
    const unsigned r = g_state[1];
    const unsigned T = g_state[0];
    unsigned taken = 0;
    for (int w0 = 0; w0 < TIE_WORDS && taken < r; w0 += 32) {
        int wi = w0 + lane;
        unsigned word = (wi < TIE_WORDS) ? g_tiebm[wi] : 0u;
        int cnt = __popc(word);
        int pre = cnt;
#pragma unroll
        for (int o = 1; o < 32; o <<= 1) {
            int v = __shfl_up_sync(0xFFFFFFFFu, pre, o);
            if (lane >= o) pre += v;
        }
        unsigned rank = taken + (unsigned)(pre - cnt);
        while (word && rank < r) {
            int b = __ffs(word) - 1;
            word &= word - 1;
            unsigned n = (unsigned)wi * 32u + (unsigned)b;
            g_cand[base + rank] = ((unsigned long long)T << 32) | n;
            rank++;
        }
        taken += (unsigned)__shfl_sync(0xFFFFFFFFu, pre, 31);
    }
}

// ---------------- single-block bitonic sort + gather ----------
extern __shared__ unsigned long long s_sort[];
__global__ void sort_topk_k()
{
    const int t = threadIdx.x;
    for (int i = t; i < SORTN; i += 1024)
        s_sort[i] = (i < PRE_NMS) ? g_cand[i] : 0xFFFFFFFFFFFFFFFFull;
    __syncthreads();
    for (int k = 2; k <= SORTN; k <<= 1) {
        for (int j = k >> 1; j > 0; j >>= 1) {
            for (int i = t; i < SORTN; i += 1024) {
                int ixj = i ^ j;
                if (ixj > i) {
                    unsigned long long a = s_sort[i], b = s_sort[ixj];
                    bool up = ((i & k) == 0);
                    if ((a > b) == up) { s_sort[i] = b; s_sort[ixj] = a; }
                }
            }
            __syncthreads();
        }
    }
    for (int i = t; i < 6144; i += 1024) {
        bool valid = false;
        if (i < PRE_NMS) {
            unsigned long long v = s_sort[i];
            unsigned K = (unsigned)(v >> 32);
            unsigned n = (unsigned)v;
            float b0 = 0, b1 = 0, b2 = 0, b3 = 0;
            if (n < (unsigned)NBOX) {
                const float4 bb = *reinterpret_cast<const float4*>(&g_roi[(size_t)n * 4]);
                b0 = bb.x; b1 = bb.y; b2 = bb.z; b3 = bb.w;
                valid = (K < 0x80000000u);
            }
            g_nb[(size_t)i * 4 + 0] = b0;
            g_nb[(size_t)i * 4 + 1] = b1;
            g_nb[(size_t)i * 4 + 2] = b2;
            g_nb[(size_t)i * 4 + 3] = b3;
        }
        unsigned bal = __ballot_sync(0xFFFFFFFFu, valid);
        if ((t & 31) == 0) g_keep_init[i >> 5] = bal;
    }
}

// ---------------- NMS suppression bitmask ----------------
__global__ __launch_bounds__(MASK_W) void mask_k()
{
    const int i = blockIdx.x;
    const int w = threadIdx.x;
    const float4* nb4 = reinterpret_cast<const float4*>(g_nb);
    float4 bi = nb4[i];
    float ai = (bi.z - bi.x) * (bi.w - bi.y);
    unsigned bits = 0;
    int jbase = w * 32;
#pragma unroll 4
    for (int b = 0; b < 32; b++) {
        int j = jbase + b;
        if (j > i && j < PRE_NMS) {
            float4 bj = nb4[j];
            float xx1 = fmaxf(bi.x, bj.x), yy1 = fmaxf(bi.y, bj.y);
            float xx2 = fminf(bi.z, bj.z), yy2 = fminf(bi.w, bj.w);
            float inter = fmaxf(xx2 - xx1, 0.f) * fmaxf(yy2 - yy1, 0.f);
            float aj = (bj.z - bj.x) * (bj.w - bj.y);
            float iou = inter / (ai + aj - inter + 1e-12f);
            if (iou > IOU_THR) bits |= (1u << b);
        }
    }
    g_mask[(size_t)i * MASK_W + w] = bits;
}

// ---------------- sequential greedy scan (single warp, early exit) ---------
__global__ void nms_scan_k()
{
    const int lane = threadIdx.x;
    unsigned kw[6];
#pragma unroll
    for (int q = 0; q < 6; q++) kw[q] = g_keep_init[q * 32 + lane];

    unsigned total = 0;
    bool done = false;
    for (int q = 0; q < 6 && !done; q++) {
        const int iend = (q == 5) ? (PRE_NMS - 5 * 1024) : 1024;
        for (int ii = 0; ii < iend; ii++) {
            int i = q * 1024 + ii;
            unsigned word = __shfl_sync(0xFFFFFFFFu, kw[q], (i >> 5) & 31);
            if ((word >> (i & 31)) & 1u) {
                const unsigned* row = &g_mask[(size_t)i * MASK_W];
#pragma unroll
                for (int r = 0; r < 6; r++) kw[r] &= ~row[r * 32 + lane];
            }
            if ((ii & 255) == 255) {
                int nproc = (ii + 1) >> 5;
                unsigned c = (lane < nproc) ? (unsigned)__popc(kw[q]) : 0u;
#pragma unroll
                for (int o = 16; o > 0; o >>= 1)
                    c += __shfl_xor_sync(0xFFFFFFFFu, c, o);
                if (total + c >= POST_NMS) {
                    if (lane >= nproc) kw[q] = 0;
                    for (int r = q + 1; r < 6; r++) kw[r] = 0;
                    done = true;
                    break;
                }
                if (nproc == 32) total += c;
            }
        }
    }
#pragma unroll
    for (int q = 0; q < 6; q++) g_keep_fin[q * 32 + lane] = kw[q];
}

// ---------------- write rois ----------------
__global__ __launch_bounds__(256) void write_rois_k(float* __restrict__ out)
{
    float* rois = out + ROI_OFF;
    __shared__ unsigned woff[MASK_W];
    int t = threadIdx.x;
    for (int i = t; i < POST_NMS * 4; i += 256) rois[i] = 0.f;
    if (t < MASK_W) woff[t] = (unsigned)__popc(g_keep_fin[t]);
    __syncthreads();
    if (t == 0) {
        unsigned acc = 0;
        for (int i = 0; i < MASK_W; i++) { unsigned tmp = woff[i]; woff[i] = acc; acc += tmp; }
    }
    __syncthreads();
    if (t < MASK_W) {
        unsigned word = g_keep_fin[t];
        unsigned rank = woff[t];
        while (word) {
            int b = __ffs(word) - 1;
            word &= word - 1;
            if (rank < POST_NMS) {
                int i = t * 32 + b;
                rois[rank * 4 + 0] = g_nb[(size_t)i * 4 + 0];
                rois[rank * 4 + 1] = g_nb[(size_t)i * 4 + 1];
                rois[rank * 4 + 2] = g_nb[(size_t)i * 4 + 2];
                rois[rank * 4 + 3] = g_nb[(size_t)i * 4 + 3];
            }
            rank++;
        }
    }
}

// ---------------- launcher ----------------
extern "C" void kernel_launch(void* const* d_in, const int* in_sizes, int n_in,
                              void* d_out, int out_size)
{
    const float* features = (const float*)d_in[0];
    const float* anchor   = (const float*)d_in[1];
    const float* w1       = (const float*)d_in[2];
    const float* b1       = (const float*)d_in[3];
    const float* wc       = (const float*)d_in[4];
    const float* bc       = (const float*)d_in[5];
    const float* wl       = (const float*)d_in[6];
    const float* bl       = (const float*)d_in[7];
    float* out = (float*)d_out;

    cudaFuncSetAttribute(sort_topk_k,
                         cudaFuncAttributeMaxDynamicSharedMemorySize,
                         SORTN * sizeof(unsigned long long));
    cudaFuncSetAttribute(gemm_k,
                         cudaFuncAttributeMaxDynamicSharedMemorySize,
                         CONV_SMEM);

    init_k<<<48, 256>>>();
    initb_k<<<48, 256>>>();

    wtrans_k<<<(CIN * CIN + 255) / 256, 256>>>(w1);
    xtrans_k<<<dim3(NTILES / 16, CIN / 16), 256>>>(features);   // 625 x 32

    gemm_k<<<dim3(NTB, CIN / MTILE, 16), 256, CONV_SMEM>>>();

    otrans_k<<<dim3((NTILES + 255) / 256, CIN), 256>>>(b1);

    conv1x1_k<<<(NPIX + PXT - 1) / PXT, 256>>>(wc, bc, wl, bl, out);

    decode_k<<<(NBOX + 255) / 256, 256>>>(anchor);

    hist_k<<<512, 256>>>(0, 24u, 0x00000000u);
    scan_k<<<1, 32>>>(0, 24u);
    hist_k<<<512, 256>>>(1, 16u, 0xFF000000u);
    scan_k<<<1, 32>>>(1, 16u);
    hist_k<<<512, 256>>>(2,  8u, 0xFFFF0000u);
    scan_k<<<1, 32>>>(2,  8u);
    hist_k<<<512, 256>>>(3,  0u, 0xFFFFFF00u);
    scan_k<<<1, 32>>>(3,  0u);

    count_k<<<NBLK, 256>>>();
    scanb_k<<<1, 256>>>();
    place_k<<<NBLK, 256>>>();
    tie_select_k<<<1, 32>>>();

    sort_topk_k<<<1, 1024, SORTN * sizeof(unsigned long long)>>>();

    mask_k<<<PRE_NMS, MASK_W>>>();

    nms_scan_k<<<1, 32>>>();

    write_rois_k<<<1, 256>>>(out);
}

// round 15
// speedup vs baseline: 4.7716x; 1.0094x over previous
#include <cuda_runtime.h>
#include <cuda_bf16.h>
#include <cuda_fp16.h>
#include <math.h>
#include <cstdint>

// ---------------- problem constants ----------------
#define HH 200
#define WW 200
#define NPIX (HH*WW)            // 40000
#define CIN 512
#define AA 9
#define NBOX (NPIX*AA)          // 360000
#define PRE_NMS 6000
#define POST_NMS 300
#define MIN_SIZE (16.0f/1000.0f)
#define IOU_THR 0.7f

#define CLS_OFF 0
#define LOC_OFF (NBOX*2)        // 720000
#define ROI_OFF (NBOX*2 + NBOX*4)  // 2160000

#define MASK_W 192
#define SORTN 8192
#define TIE_WORDS ((NBOX + 31) / 32)   // 11250
#define NBLK 1407               // ceil(NBOX/256)

// ---- Winograd F(2x2,3x3) GEMM geometry ----
#define NT1D 100                // tiles per axis
#define NTILES (NT1D*NT1D)      // 10000
#define UVW (CIN*CIN)           // 262144 (per-uv weight plane)
#define UVX ((size_t)CIN*NTILES) // 5120000 (per-uv data plane)
#define KC 32
#define GCH (CIN/KC)            // 16 K-chunks per GEMM
#define DRAIN 2
#define MTILE 128
#define NTILE 128
#define NTB ((NTILES + NTILE - 1)/NTILE)  // 79
#define PITCH 40                // fp16 elems per smem row (80 B)
#define SPLIT_B (128*PITCH*2)   // 10240 bytes per split tile
#define BS_OFF  (2*SPLIT_B)
#define BUF_B   (4*SPLIT_B)     // one buffer: 2 A splits + 2 B splits
#define CONV_SMEM (2*BUF_B)     // 81920 bytes, double-buffered

// fp16 2-split scaling (exact pow2; epilogue rescales by 2^-24)
#define XSCALE 1024.0f          // 2^10
#define WSCALE 16384.0f         // 2^14
#define OSCALE (1.0f/16777216.0f)

// ---------------- scratch (device globals) ------------
__device__ float g_x[(size_t)CIN * NPIX];
__device__ __align__(16) __half g_wu[2][(size_t)16 * UVW];   // U splits [uv][co][ci]
__device__ __align__(16) __half g_xv[2][(size_t)16 * UVX];   // V splits [uv][tile][ci]
__device__ float g_m[(size_t)16 * UVX];                      // M fp32 [uv][co][tile]
__device__ float g_cls[(size_t)NBOX * 2];
__device__ float g_loc[(size_t)NBOX * 4];
__device__ __align__(16) float g_roi[(size_t)NBOX * 4];
__device__ unsigned g_key[NBOX];
__device__ unsigned g_hist[4 * 256];
__device__ unsigned g_state[2];
__device__ int g_cnt;
__device__ unsigned g_bcnt[NBLK + 1];
__device__ unsigned g_boff[NBLK + 1];
__device__ unsigned long long g_cand[SORTN];
__device__ unsigned g_tiebm[TIE_WORDS];
__device__ __align__(16) float g_nb[6144 * 4];
__device__ unsigned g_keep_init[MASK_W];
__device__ unsigned g_keep_fin[MASK_W];
__device__ unsigned g_mask[(size_t)PRE_NMS * MASK_W];

// ---------------- PTX helpers ----------------
__device__ __forceinline__ uint32_t smem_u32(const void* p) {
    uint32_t a;
    asm("{ .reg .u64 t; cvta.to.shared.u64 t, %1; cvt.u32.u64 %0, t; }" : "=r"(a) : "l"(p));
    return a;
}
__device__ __forceinline__ void ldsm_x4(unsigned* r, uint32_t addr) {
    asm volatile("ldmatrix.sync.aligned.m8n8.x4.shared.b16 {%0,%1,%2,%3}, [%4];"
        : "=r"(r[0]), "=r"(r[1]), "=r"(r[2]), "=r"(r[3]) : "r"(addr));
}
__device__ __forceinline__ void ldsm_x2(unsigned* r, uint32_t addr) {
    asm volatile("ldmatrix.sync.aligned.m8n8.x2.shared.b16 {%0,%1}, [%2];"
        : "=r"(r[0]), "=r"(r[1]) : "r"(addr));
}
__device__ __forceinline__ void mma16816h(float* d, const unsigned* a, const unsigned* b) {
    asm volatile(
        "mma.sync.aligned.m16n8k16.row.col.f32.f16.f16.f32 "
        "{%0,%1,%2,%3}, {%4,%5,%6,%7}, {%8,%9}, {%0,%1,%2,%3};"
        : "+f"(d[0]), "+f"(d[1]), "+f"(d[2]), "+f"(d[3])
        : "r"(a[0]), "r"(a[1]), "r"(a[2]), "r"(a[3]), "r"(b[0]), "r"(b[1]));
}

// ---------------- init ----------------
__global__ void init_k() {
    int t = blockIdx.x * 256 + threadIdx.x;
    const int STRIDE = 48 * 256;
    for (int i = t; i < 4 * 256; i += STRIDE) g_hist[i] = 0;
    for (int i = t; i < TIE_WORDS; i += STRIDE) g_tiebm[i] = 0;
    for (int i = t; i < SORTN; i += STRIDE) g_cand[i] = 0xFFFFFFFFFFFFFFFFull;
}
__global__ void initb_k() {
    int t = blockIdx.x * 256 + threadIdx.x;
    const int STRIDE = 48 * 256;
    for (int i = t; i < NBLK + 1; i += STRIDE) { g_bcnt[i] = 0; g_boff[i] = 0; }
    for (int i = t; i < MASK_W; i += STRIDE) { g_keep_init[i] = 0; g_keep_fin[i] = 0; }
    if (t == 0) { g_cnt = 0; g_state[0] = 0u; g_state[1] = PRE_NMS; }
}

// ---------------- fp32 -> 2x fp16 split (value pre-scaled) -----------
__device__ __forceinline__ void split2h(float vs, __half& h0, __half& h1) {
    h0 = __float2half_rn(vs);
    h1 = __float2half_rn(vs - __half2float(h0));
}

// ---------------- weight transform: U = G g G^T, scaled + split -----------
__global__ __launch_bounds__(256) void wtrans_k(const float* __restrict__ w1)
{
    int n = blockIdx.x * 256 + threadIdx.x;
    if (n >= CIN * CIN) return;
    const float* wp = w1 + (size_t)n * 9;   // [co][ci][3][3]
    float g[9];
#pragma unroll
    for (int i = 0; i < 9; i++) g[i] = wp[i];
    float T[4][3];
#pragma unroll
    for (int c = 0; c < 3; c++) {
        T[0][c] = g[c];
        T[1][c] = 0.5f * (g[c] + g[3 + c] + g[6 + c]);
        T[2][c] = 0.5f * (g[c] - g[3 + c] + g[6 + c]);
        T[3][c] = g[6 + c];
    }
#pragma unroll
    for (int r = 0; r < 4; r++) {
        float u[4];
        u[0] = T[r][0];
        u[1] = 0.5f * (T[r][0] + T[r][1] + T[r][2]);
        u[2] = 0.5f * (T[r][0] - T[r][1] + T[r][2]);
        u[3] = T[r][2];
#pragma unroll
        for (int c = 0; c < 4; c++) {
            __half h0, h1;
            split2h(u[c] * WSCALE, h0, h1);
            size_t idx = (size_t)(r * 4 + c) * UVW + n;
            g_wu[0][idx] = h0;
            g_wu[1][idx] = h1;
        }
    }
}

// ---------------- input transform: V = B^T d B, scaled + split -------------
// Output layout [uv][tile][ci]. Block = 16 tiles x 16 ci; padded smem
// transpose (stride 20 halves, 8B-aligned rows) drained with uint2 ops.
#define XPAD 20
__global__ __launch_bounds__(256) void xtrans_k(const float* __restrict__ f)
{
    __shared__ __align__(8) __half s_v[32][16 * XPAD];
    const int t = threadIdx.x;
    const int tl = t & 15;                // tile local
    const int cl = t >> 4;                // ci local
    const int tile0 = blockIdx.x * 16;
    const int ci0 = blockIdx.y * 16;
    const int tile = tile0 + tl;          // NTILES = 625*16 exact
    const int ci = ci0 + cl;

    int ty = tile / NT1D, tx = tile - ty * NT1D;
    int y0 = 2 * ty - 1, x0 = 2 * tx - 1;
    const float* fc = f + (size_t)ci * NPIX;
    float d[4][4];
#pragma unroll
    for (int r = 0; r < 4; r++) {
        int y = y0 + r;
#pragma unroll
        for (int c = 0; c < 4; c++) {
            int x = x0 + c;
            d[r][c] = ((unsigned)y < (unsigned)HH && (unsigned)x < (unsigned)WW)
                      ? fc[y * WW + x] : 0.f;
        }
    }
    float P[4][4];
#pragma unroll
    for (int c = 0; c < 4; c++) {
        P[0][c] = d[0][c] - d[2][c];
        P[1][c] = d[1][c] + d[2][c];
        P[2][c] = d[2][c] - d[1][c];
        P[3][c] = d[1][c] - d[3][c];
    }
#pragma unroll
    for (int r = 0; r < 4; r++) {
        float v[4];
        v[0] = P[r][0] - P[r][2];
        v[1] = P[r][1] + P[r][2];
        v[2] = P[r][2] - P[r][1];
        v[3] = P[r][1] - P[r][3];
#pragma unroll
        for (int c = 0; c < 4; c++) {
            __half h0, h1;
            split2h(v[c] * XSCALE, h0, h1);
            int uv = r * 4 + c;
            s_v[uv][tl * XPAD + cl] = h0;
            s_v[16 + uv][tl * XPAD + cl] = h1;
        }
    }
    __syncthreads();
    // writeout: 2048 uint2 units = 32 planes x 16 tiles x 4 ci-groups
#pragma unroll
    for (int i = 0; i < 8; i++) {
        int unit = i * 256 + t;
        int p = unit >> 6;
        int rem = unit & 63;
        int tl2 = rem >> 2, g = rem & 3;
        int s = p >> 4, uv = p & 15;
        uint2 v = *(const uint2*)&s_v[p][tl2 * XPAD + g * 4];
        *(uint2*)&g_xv[s][(size_t)uv * UVX + (size_t)(tile0 + tl2) * CIN + ci0 + g * 4] = v;
    }
}

// ---------------- Winograd GEMM: M(uv) = U(uv) x V(uv), fp16x2 3-product ---
__global__ __launch_bounds__(256) void gemm_k()
{
    extern __shared__ __align__(16) char smem[];
    const uint32_t sb = smem_u32(smem);
    const int t = threadIdx.x;
    const int w = t >> 5, lane = t & 31;
    const int t0 = blockIdx.x * NTILE;
    const int co0 = blockIdx.y * MTILE;
    const int uv = blockIdx.z;
    const int mw = (w & 1) * 64;
    const int nw = (w >> 1) * 32;

    float acc[4][4][4];
    float accm[4][4][4];
#pragma unroll
    for (int mt = 0; mt < 4; mt++)
#pragma unroll
        for (int nt = 0; nt < 4; nt++)
#pragma unroll
            for (int e = 0; e < 4; e++) { acc[mt][nt][e] = 0.f; accm[mt][nt][e] = 0.f; }

    const int arow = t >> 1, ahalf = t & 1;   // staging: 2 thr/row, 16 fp16 each
    const int bgt = t0 + arow;                // B global tile for this thread
    const bool bok = bgt < NTILES;
    const uint32_t a_lb = (uint32_t)(((lane & 7) + ((lane >> 3) & 1) * 8) * (PITCH * 2)
                                     + (lane >> 4) * 16);
    const uint32_t b_lb = (uint32_t)((lane & 7) * (PITCH * 2) + ((lane >> 3) & 1) * 16);

    uint4 aR[2][2];
    uint4 bR[2][2];

    auto prefetch = [&](int c) {
        const int k0 = c * KC;
#pragma unroll
        for (int s = 0; s < 2; s++) {
            const uint4* srcA = (const uint4*)&g_wu[s][(size_t)uv * UVW
                                + (size_t)(co0 + arow) * CIN + k0 + ahalf * 16];
            aR[s][0] = srcA[0];
            aR[s][1] = srcA[1];
            if (bok) {
                const uint4* srcB = (const uint4*)&g_xv[s][(size_t)uv * UVX
                                    + (size_t)bgt * CIN + k0 + ahalf * 16];
                bR[s][0] = srcB[0];
                bR[s][1] = srcB[1];
            } else {
                bR[s][0] = make_uint4(0, 0, 0, 0);
                bR[s][1] = make_uint4(0, 0, 0, 0);
            }
        }
    };

    auto store_stage = [&](char* base) {
#pragma unroll
        for (int s = 0; s < 2; s++) {
            uint4* dstA = (uint4*)(base + s * SPLIT_B + arow * (PITCH * 2) + ahalf * 32);
            dstA[0] = aR[s][0];
            dstA[1] = aR[s][1];
            uint4* dstB = (uint4*)(base + BS_OFF + s * SPLIT_B
                                   + arow * (PITCH * 2) + ahalf * 32);
            dstB[0] = bR[s][0];
            dstB[1] = bR[s][1];
        }
    };

    auto compute = [&](uint32_t bufb) {
#pragma unroll
        for (int ks = 0; ks < 2; ks++) {
            const uint32_t koff = (uint32_t)(ks * 32);
            unsigned af0[4][4], af1[4][4];
#pragma unroll
            for (int mt = 0; mt < 4; mt++) {
                uint32_t ab = bufb + (uint32_t)((mw + mt * 16) * (PITCH * 2)) + a_lb + koff;
                ldsm_x4(af0[mt], ab);
                ldsm_x4(af1[mt], ab + SPLIT_B);
            }
            {
                unsigned bf[4][2];
#pragma unroll
                for (int nt = 0; nt < 4; nt++)
                    ldsm_x2(bf[nt], bufb + BS_OFF
                            + (uint32_t)((nw + nt * 8) * (PITCH * 2)) + b_lb + koff);
#pragma unroll
                for (int mt = 0; mt < 4; mt++)
#pragma unroll
                    for (int nt = 0; nt < 4; nt++) {
                        mma16816h(acc[mt][nt], af0[mt], bf[nt]);
                        mma16816h(acc[mt][nt], af1[mt], bf[nt]);
                    }
            }
            {
                unsigned bf[4][2];
#pragma unroll
                for (int nt = 0; nt < 4; nt++)
                    ldsm_x2(bf[nt], bufb + BS_OFF + SPLIT_B
                            + (uint32_t)((nw + nt * 8) * (PITCH * 2)) + b_lb + koff);
#pragma unroll
                for (int mt = 0; mt < 4; mt++)
#pragma unroll
                    for (int nt = 0; nt < 4; nt++)
                        mma16816h(acc[mt][nt], af0[mt], bf[nt]);
            }
        }
    };

    // prologue: fill buffer 0
    prefetch(0);
    store_stage(smem);
    __syncthreads();

    for (int c = 0; c < GCH; c++) {
        const int cur = c & 1;
        if (c + 1 < GCH) prefetch(c + 1);
        compute(sb + cur * BUF_B);
        if (c + 1 < GCH) store_stage(smem + (cur ^ 1) * BUF_B);
        __syncthreads();

        if ((c % DRAIN) == (DRAIN - 1)) {
#pragma unroll
            for (int mt = 0; mt < 4; mt++)
#pragma unroll
                for (int nt = 0; nt < 4; nt++)
#pragma unroll
                    for (int e = 0; e < 4; e++) {
                        accm[mt][nt][e] += acc[mt][nt][e];
                        acc[mt][nt][e] = 0.f;
                    }
        }
    }

    // epilogue: raw scaled fp32 -> g_m[uv][co][tile] (paired 64-bit stores)
    float* mplane = g_m + (size_t)uv * UVX;
#pragma unroll
    for (int mt = 0; mt < 4; mt++) {
        int r0 = co0 + mw + mt * 16 + (lane >> 2);
#pragma unroll
        for (int nt = 0; nt < 4; nt++) {
            int col = t0 + nw + nt * 8 + (lane & 3) * 2;
            if (col + 1 < NTILES) {
                *(float2*)&mplane[(size_t)r0 * NTILES + col] =
                    make_float2(accm[mt][nt][0], accm[mt][nt][1]);
                *(float2*)&mplane[(size_t)(r0 + 8) * NTILES + col] =
                    make_float2(accm[mt][nt][2], accm[mt][nt][3]);
            } else if (col < NTILES) {
                mplane[(size_t)r0 * NTILES + col] = accm[mt][nt][0];
                mplane[(size_t)(r0 + 8) * NTILES + col] = accm[mt][nt][2];
            }
        }
    }
}

// ---------------- output transform: Y = A^T M A, rescale + bias + relu -----
__global__ __launch_bounds__(256) void otrans_k(const float* __restrict__ b1)
{
    int tile = blockIdx.x * 256 + threadIdx.x;
    if (tile >= NTILES) return;
    int co = blockIdx.y;
    float m[16];
#pragma unroll
    for (int uv = 0; uv < 16; uv++)
        m[uv] = g_m[(size_t)uv * UVX + (size_t)co * NTILES + tile];
    float Z[2][4];
#pragma unroll
    for (int v = 0; v < 4; v++) {
        Z[0][v] = m[v] + m[4 + v] + m[8 + v];
        Z[1][v] = m[4 + v] - m[8 + v] - m[12 + v];
    }
    float bias = b1[co];
    int ty = tile / NT1D, tx = tile - ty * NT1D;
    float* gx = g_x + (size_t)co * NPIX;
#pragma unroll
    for (int i = 0; i < 2; i++) {
        float y0 = (Z[i][0] + Z[i][1] + Z[i][2]) * OSCALE + bias;
        float y1 = (Z[i][1] - Z[i][2] - Z[i][3]) * OSCALE + bias;
        int row = 2 * ty + i;
        gx[row * WW + 2 * tx]     = y0 > 0.f ? y0 : 0.f;
        gx[row * WW + 2 * tx + 1] = y1 > 0.f ? y1 : 0.f;
    }
}

// ---------------- 1x1 heads (cls 18 + loc 36) ----------------
#define PXT 128
#define OC 64
#define CKB 16
__global__ __launch_bounds__(256) void conv1x1_k(
    const float* __restrict__ wc, const float* __restrict__ bc,
    const float* __restrict__ wl, const float* __restrict__ bl,
    float* __restrict__ out)
{
    __shared__ float s_x[CKB][PXT];
    __shared__ float s_w[OC][CKB];
    const int p0 = blockIdx.x * PXT;
    const int t = threadIdx.x;
    const int cg = t >> 4;
    const int pg = t & 15;

    float acc[4][8];
#pragma unroll
    for (int k = 0; k < 4; k++)
#pragma unroll
        for (int j = 0; j < 8; j++) acc[k][j] = 0.f;

    for (int cb = 0; cb < CIN; cb += CKB) {
        __syncthreads();
        for (int i = t; i < CKB * PXT; i += 256) {
            int ci = i >> 7, pp = i & 127;
            int p = p0 + pp;
            s_x[ci][pp] = (p < NPIX) ? g_x[(size_t)(cb + ci) * NPIX + p] : 0.f;
        }
        for (int i = t; i < OC * CKB; i += 256) {
            int co = i >> 4, ci = i & 15;
            float v = 0.f;
            if (co < 18) v = wc[(size_t)co * CIN + cb + ci];
            else if (co < 54) v = wl[(size_t)(co - 18) * CIN + cb + ci];
            s_w[co][ci] = v;
        }
        __syncthreads();
#pragma unroll 4
        for (int ci = 0; ci < CKB; ci++) {
            float xv[8];
#pragma unroll
            for (int j = 0; j < 8; j++) xv[j] = s_x[ci][pg * 8 + j];
#pragma unroll
            for (int k = 0; k < 4; k++) {
                float wv = s_w[cg * 4 + k][ci];
#pragma unroll
                for (int j = 0; j < 8; j++)
                    acc[k][j] = fmaf(wv, xv[j], acc[k][j]);
            }
        }
    }

#pragma unroll
    for (int k = 0; k < 4; k++) {
        int co = cg * 4 + k;
#pragma unroll
        for (int j = 0; j < 8; j++) {
            int p = p0 + pg * 8 + j;
            if (p < NPIX) {
                if (co < 18) {
                    float v = acc[k][j] + bc[co];
                    out[CLS_OFF + (size_t)p * 18 + co] = v;
                    g_cls[(size_t)p * 18 + co] = v;
                } else if (co < 54) {
                    float v = acc[k][j] + bl[co - 18];
                    out[LOC_OFF + (size_t)p * 36 + (co - 18)] = v;
                    g_loc[(size_t)p * 36 + (co - 18)] = v;
                }
            }
        }
    }
}

// ---------------- decode boxes + scores + keys + fused hist pass 0 ---------
__global__ __launch_bounds__(256) void decode_k(const float* __restrict__ anchor)
{
    __shared__ unsigned h[256];
    int t = threadIdx.x;
    h[t] = 0;
    __syncthreads();

    int n = blockIdx.x * 256 + t;
    if (n < NBOX) {
        float a0 = anchor[(size_t)n * 4 + 0], a1 = anchor[(size_t)n * 4 + 1];
        float a2 = anchor[(size_t)n * 4 + 2], a3 = anchor[(size_t)n * 4 + 3];
        float aw = a2 - a0, ah = a3 - a1;
        float acx = (a0 + a2) * 0.5f, acy = (a1 + a3) * 0.5f;
        float l0 = g_loc[(size_t)n * 4 + 0];
        float l1 = g_loc[(size_t)n * 4 + 1];
        float l2 = g_loc[(size_t)n * 4 + 2];
        float l3 = g_loc[(size_t)n * 4 + 3];
        float cx = l0 * aw + acx, cy = l1 * ah + acy;
        float bw = expf(l2) * aw, bh = expf(l3) * ah;
        float x1 = fminf(fmaxf(cx - bw * 0.5f, 0.f), 1.f);
        float y1 = fminf(fmaxf(cy - bh * 0.5f, 0.f), 1.f);
        float x2 = fminf(fmaxf(cx + bw * 0.5f, 0.f), 1.f);
        float y2 = fminf(fmaxf(cy + bh * 0.5f, 0.f), 1.f);
        g_roi[(size_t)n * 4 + 0] = x1;
        g_roi[(size_t)n * 4 + 1] = y1;
        g_roi[(size_t)n * 4 + 2] = x2;
        g_roi[(size_t)n * 4 + 3] = y2;

        float c0 = g_cls[(size_t)n * 2 + 0];
        float c1 = g_cls[(size_t)n * 2 + 1];
        float s = 1.f / (1.f + expf(c0 - c1));
        bool valid = ((y2 - y1) >= MIN_SIZE) && ((x2 - x1) >= MIN_SIZE);
        float sc = valid ? s : -1.0f;

        unsigned b = __float_as_uint(sc);
        unsigned ord = (b & 0x80000000u) ? ~b : (b | 0x80000000u);
        unsigned K = ~ord;
        g_key[n] = K;
        atomicAdd(&h[K >> 24], 1u);   // fused radix pass 0
    }
    __syncthreads();
    if (h[t]) atomicAdd(&g_hist[t], h[t]);
}

// ---------------- radix passes 1..3 ----------------
__global__ void hist_k(int pass, unsigned shift, unsigned pmask)
{
    __shared__ unsigned h[256];
    int t = threadIdx.x;
    for (int i = t; i < 256; i += 256) h[i] = 0;
    __syncthreads();
    unsigned prefix = g_state[0];
    for (int n = blockIdx.x * 256 + t; n < NBOX; n += gridDim.x * 256) {
        unsigned K = g_key[n];
        if ((K & pmask) == prefix) atomicAdd(&h[(K >> shift) & 255u], 1u);
    }
    __syncthreads();
    unsigned* hist = &g_hist[pass * 256];
    for (int i = t; i < 256; i += 256)
        if (h[i]) atomicAdd(&hist[i], h[i]);
}

__global__ void scan_k(int pass, unsigned shift)
{
    if (threadIdx.x == 0) {
        const unsigned* hist = &g_hist[pass * 256];
        unsigned k = g_state[1];
        unsigned cum = 0;
        int d = 0;
        for (; d < 256; d++) {
            if (cum + hist[d] >= k) break;
            cum += hist[d];
        }
        if (d > 255) d = 255;
        g_state[0] |= ((unsigned)d) << shift;
        g_state[1] = k - cum;
    }
}

// ---------------- deterministic compaction ------------
__global__ __launch_bounds__(256) void count_k()
{
    __shared__ unsigned wsum[8];
    int n = blockIdx.x * 256 + threadIdx.x;
    unsigned T = g_state[0];
    bool pred = (n < NBOX) && (g_key[n] < T);
    unsigned bal = __ballot_sync(0xFFFFFFFFu, pred);
    if ((threadIdx.x & 31) == 0) wsum[threadIdx.x >> 5] = (unsigned)__popc(bal);
    __syncthreads();
    if (threadIdx.x == 0) {
        unsigned s = 0;
#pragma unroll
        for (int w = 0; w < 8; w++) s += wsum[w];
        g_bcnt[blockIdx.x] = s;
    }
}

#define SCCH 6
__global__ __launch_bounds__(256) void scanb_k()
{
    __shared__ unsigned ssum[256];
    int t = threadIdx.x;
    unsigned loc[SCCH];
    unsigned s = 0;
#pragma unroll
    for (int e = 0; e < SCCH; e++) {
        int idx = t * SCCH + e;
        loc[e] = (idx < NBLK) ? g_bcnt[idx] : 0u;
        s += loc[e];
    }
    ssum[t] = s;
    __syncthreads();
    if (t == 0) {
        unsigned acc = 0;
        for (int i = 0; i < 256; i++) { unsigned tmp = ssum[i]; ssum[i] = acc; acc += tmp; }
        g_cnt = (int)acc;
    }
    __syncthreads();
    unsigned run = ssum[t];
#pragma unroll
    for (int e = 0; e < SCCH; e++) {
        int idx = t * SCCH + e;
        if (idx < NBLK) g_boff[idx] = run;
        run += loc[e];
    }
}

__global__ __launch_bounds__(256) void place_k()
{
    __shared__ unsigned wcnt[8];
    __shared__ unsigned wex[8];
    int t = threadIdx.x;
    int n = blockIdx.x * 256 + t;
    unsigned T = g_state[0];
    unsigned K = (n < NBOX) ? g_key[n] : 0xFFFFFFFFu;
    bool pred = (n < NBOX) && (K < T);
    unsigned bal = __ballot_sync(0xFFFFFFFFu, pred);
    int lane = t & 31, w = t >> 5;
    if (lane == 0) wcnt[w] = (unsigned)__popc(bal);
    __syncthreads();
    if (t == 0) {
        unsigned a = 0;
#pragma unroll
        for (int i = 0; i < 8; i++) { wex[i] = a; a += wcnt[i]; }
    }
    __syncthreads();
    if (pred) {
        unsigned rank = g_boff[blockIdx.x] + wex[w] +
                        (unsigned)__popc(bal & ((1u << lane) - 1u));
        g_cand[rank] = ((unsigned long long)K << 32) | (unsigned)n;
    }
    if ((n < NBOX) && (K == T))
        atomicOr(&g_tiebm[n >> 5], 1u << (n & 31));
}

__global__ void tie_select_k()
{
    const int lane = threadIdx.x;
    const int base = g_cnt;
    const unsigned r = g_state[1];
    const unsigned T = g_state[0];
    unsigned taken = 0;
    for (int w0 = 0; w0 < TIE_WORDS && taken < r; w0 += 32) {
        int wi = w0 + lane;
        unsigned word = (wi < TIE_WORDS) ? g_tiebm[wi] : 0u;
        int cnt = __popc(word);
        int pre = cnt;
#pragma unroll
        for (int o = 1; o < 32; o <<= 1) {
            int v = __shfl_up_sync(0xFFFFFFFFu, pre, o);
            if (lane >= o) pre += v;
        }
        unsigned rank = taken + (unsigned)(pre - cnt);
        while (word && rank < r) {
            int b = __ffs(word) - 1;
            word &= word - 1;
            unsigned n = (unsigned)wi * 32u + (unsigned)b;
            g_cand[base + rank] = ((unsigned long long)T << 32) | n;
            rank++;
        }
        taken += (unsigned)__shfl_sync(0xFFFFFFFFu, pre, 31);
    }
}

// ---------------- single-block bitonic sort + gather ----------
extern __shared__ unsigned long long s_sort[];
__global__ void sort_topk_k()
{
    const int t = threadIdx.x;
    for (int i = t; i < SORTN; i += 1024)
        s_sort[i] = (i < PRE_NMS) ? g_cand[i] : 0xFFFFFFFFFFFFFFFFull;
    __syncthreads();
    for (int k = 2; k <= SORTN; k <<= 1) {
        for (int j = k >> 1; j > 0; j >>= 1) {
            for (int i = t; i < SORTN; i += 1024) {
                int ixj = i ^ j;
                if (ixj > i) {
                    unsigned long long a = s_sort[i], b = s_sort[ixj];
                    bool up = ((i & k) == 0);
                    if ((a > b) == up) { s_sort[i] = b; s_sort[ixj] = a; }
                }
            }
            __syncthreads();
        }
    }
    for (int i = t; i < 6144; i += 1024) {
        bool valid = false;
        if (i < PRE_NMS) {
            unsigned long long v = s_sort[i];
            unsigned K = (unsigned)(v >> 32);
            unsigned n = (unsigned)v;
            float b0 = 0, b1 = 0, b2 = 0, b3 = 0;
            if (n < (unsigned)NBOX) {
                const float4 bb = *reinterpret_cast<const float4*>(&g_roi[(size_t)n * 4]);
                b0 = bb.x; b1 = bb.y; b2 = bb.z; b3 = bb.w;
                valid = (K < 0x80000000u);
            }
            g_nb[(size_t)i * 4 + 0] = b0;
            g_nb[(size_t)i * 4 + 1] = b1;
            g_nb[(size_t)i * 4 + 2] = b2;
            g_nb[(size_t)i * 4 + 3] = b3;
        }
        unsigned bal = __ballot_sync(0xFFFFFFFFu, valid);
        if ((t & 31) == 0) g_keep_init[i >> 5] = bal;
    }
}

// ---------------- NMS suppression bitmask ----------------
__global__ __launch_bounds__(MASK_W) void mask_k()
{
    const int i = blockIdx.x;
    const int w = threadIdx.x;
    const float4* nb4 = reinterpret_cast<const float4*>(g_nb);
    float4 bi = nb4[i];
    float ai = (bi.z - bi.x) * (bi.w - bi.y);
    unsigned bits = 0;
    int jbase = w * 32;
#pragma unroll 4
    for (int b = 0; b < 32; b++) {
        int j = jbase + b;
        if (j > i && j < PRE_NMS) {
            float4 bj = nb4[j];
            float xx1 = fmaxf(bi.x, bj.x), yy1 = fmaxf(bi.y, bj.y);
            float xx2 = fminf(bi.z, bj.z), yy2 = fminf(bi.w, bj.w);
            float inter = fmaxf(xx2 - xx1, 0.f) * fmaxf(yy2 - yy1, 0.f);
            float aj = (bj.z - bj.x) * (bj.w - bj.y);
            float iou = inter / (ai + aj - inter + 1e-12f);
            if (iou > IOU_THR) bits |= (1u << b);
        }
    }
    g_mask[(size_t)i * MASK_W + w] = bits;
}

// ---------------- sequential greedy scan (single warp, early exit) ---------
__global__ void nms_scan_k()
{
    const int lane = threadIdx.x;
    unsigned kw[6];
#pragma unroll
    for (int q = 0; q < 6; q++) kw[q] = g_keep_init[q * 32 + lane];

    unsigned total = 0;
    bool done = false;
    for (int q = 0; q < 6 && !done; q++) {
        const int iend = (q == 5) ? (PRE_NMS - 5 * 1024) : 1024;
        for (int ii = 0; ii < iend; ii++) {
            int i = q * 1024 + ii;
            unsigned word = __shfl_sync(0xFFFFFFFFu, kw[q], (i >> 5) & 31);
            if ((word >> (i & 31)) & 1u) {
                const unsigned* row = &g_mask[(size_t)i * MASK_W];
#pragma unroll
                for (int r = 0; r < 6; r++) kw[r] &= ~row[r * 32 + lane];
            }
            if ((ii & 255) == 255) {
                int nproc = (ii + 1) >> 5;
                unsigned c = (lane < nproc) ? (unsigned)__popc(kw[q]) : 0u;
#pragma unroll
                for (int o = 16; o > 0; o >>= 1)
                    c += __shfl_xor_sync(0xFFFFFFFFu, c, o);
                if (total + c >= POST_NMS) {
                    if (lane >= nproc) kw[q] = 0;
                    for (int r = q + 1; r < 6; r++) kw[r] = 0;
                    done = true;
                    break;
                }
                if (nproc == 32) total += c;
            }
        }
    }
#pragma unroll
    for (int q = 0; q < 6; q++) g_keep_fin[q * 32 + lane] = kw[q];
}

// ---------------- write rois ----------------
__global__ __launch_bounds__(256) void write_rois_k(float* __restrict__ out)
{
    float* rois = out + ROI_OFF;
    __shared__ unsigned woff[MASK_W];
    int t = threadIdx.x;
    for (int i = t; i < POST_NMS * 4; i += 256) rois[i] = 0.f;
    if (t < MASK_W) woff[t] = (unsigned)__popc(g_keep_fin[t]);
    __syncthreads();
    if (t == 0) {
        unsigned acc = 0;
        for (int i = 0; i < MASK_W; i++) { unsigned tmp = woff[i]; woff[i] = acc; acc += tmp; }
    }
    __syncthreads();
    if (t < MASK_W) {
        unsigned word = g_keep_fin[t];
        unsigned rank = woff[t];
        while (word) {
            int b = __ffs(word) - 1;
            word &= word - 1;
            if (rank < POST_NMS) {
                int i = t * 32 + b;
                rois[rank * 4 + 0] = g_nb[(size_t)i * 4 + 0];
                rois[rank * 4 + 1] = g_nb[(size_t)i * 4 + 1];
                rois[rank * 4 + 2] = g_nb[(size_t)i * 4 + 2];
                rois[rank * 4 + 3] = g_nb[(size_t)i * 4 + 3];
            }
            rank++;
        }
    }
}

// ---------------- launcher ----------------
extern "C" void kernel_launch(void* const* d_in, const int* in_sizes, int n_in,
                              void* d_out, int out_size)
{
    const float* features = (const float*)d_in[0];
    const float* anchor   = (const float*)d_in[1];
    const float* w1       = (const float*)d_in[2];
    const float* b1       = (const float*)d_in[3];
    const float* wc       = (const float*)d_in[4];
    const float* bc       = (const float*)d_in[5];
    const float* wl       = (const float*)d_in[6];
    const float* bl       = (const float*)d_in[7];
    float* out = (float*)d_out;

    cudaFuncSetAttribute(sort_topk_k,
                         cudaFuncAttributeMaxDynamicSharedMemorySize,
                         SORTN * sizeof(unsigned long long));
    cudaFuncSetAttribute(gemm_k,
                         cudaFuncAttributeMaxDynamicSharedMemorySize,
                         CONV_SMEM);

    init_k<<<48, 256>>>();
    initb_k<<<48, 256>>>();

    wtrans_k<<<(CIN * CIN + 255) / 256, 256>>>(w1);
    xtrans_k<<<dim3(NTILES / 16, CIN / 16), 256>>>(features);   // 625 x 32

    gemm_k<<<dim3(NTB, CIN / MTILE, 16), 256, CONV_SMEM>>>();

    otrans_k<<<dim3((NTILES + 255) / 256, CIN), 256>>>(b1);

    conv1x1_k<<<(NPIX + PXT - 1) / PXT, 256>>>(wc, bc, wl, bl, out);

    decode_k<<<NBLK, 256>>>(anchor);   // fused radix pass 0

    scan_k<<<1, 32>>>(0, 24u);
    hist_k<<<512, 256>>>(1, 16u, 0xFF000000u);
    scan_k<<<1, 32>>>(1, 16u);
    hist_k<<<512, 256>>>(2,  8u, 0xFFFF0000u);
    scan_k<<<1, 32>>>(2,  8u);
    hist_k<<<512, 256>>>(3,  0u, 0xFFFFFF00u);
    scan_k<<<1, 32>>>(3,  0u);

    count_k<<<NBLK, 256>>>();
    scanb_k<<<1, 256>>>();
    place_k<<<NBLK, 256>>>();
    tie_select_k<<<1, 32>>>();

    sort_topk_k<<<1, 1024, SORTN * sizeof(unsigned long long)>>>();

    mask_k<<<PRE_NMS, MASK_W>>>();

    nms_scan_k<<<1, 32>>>();

    write_rois_k<<<1, 256>>>(out);
}